// round 1
// baseline (speedup 1.0000x reference)
#include <cuda_runtime.h>
#include <math.h>

#define Bn   4096
#define Mn   4
#define Hn   1024
#define Rn   10
#define MIDn 512
#define D3n  3072

// ---------------- scratch (__device__ globals: alloc-free) ----------------
__device__ float d_featgo[3 * Bn * D3n];        // 37.75M
__device__ float d_hidgo[3 * Bn * MIDn];        // 6.29M
__device__ float d_ggo[3 * Bn];
__device__ float d_a2o[Bn * Hn];
__device__ float d_onew[Bn * 3 * Hn];
__device__ float d_omean[Bn * Hn];
__device__ float d_featga[Bn * D3n];
__device__ float d_hidga[Bn * MIDn];
__device__ float d_gavec[Bn];
__device__ float d_o2a[Bn * Hn];
__device__ float d_mixed[Bn * Mn * Hn];
__device__ float d_zbuf[167772160];             // B*M*R*H = 671MB
__device__ float d_fused[Bn * Hn];
__device__ float d_h1[Bn * Hn];
__device__ float d_h2[Bn * Hn];
__device__ unsigned char d_mask[Bn * Mn];

// ---------------- helpers ----------------
__device__ __forceinline__ float gelu_f(float x) {
    return 0.5f * x * (1.0f + erff(x * 0.70710678118654752f));
}

__device__ __forceinline__ float2 blkSum2(float a, float b) {
    __shared__ float sa[32], sb[32];
    __shared__ float ra, rb;
    int lane = threadIdx.x & 31, w = threadIdx.x >> 5;
#pragma unroll
    for (int o = 16; o > 0; o >>= 1) {
        a += __shfl_xor_sync(0xffffffffu, a, o);
        b += __shfl_xor_sync(0xffffffffu, b, o);
    }
    if (lane == 0) { sa[w] = a; sb[w] = b; }
    __syncthreads();
    if (threadIdx.x == 0) {
        float x = 0.f, y = 0.f;
        int nw = blockDim.x >> 5;
        for (int i = 0; i < nw; i++) { x += sa[i]; y += sb[i]; }
        ra = x; rb = y;
    }
    __syncthreads();
    return make_float2(ra, rb);
}

// ---------------- mask dtype sniffer ----------------
// token_mask is a jax bool; serialized dtype may be u8 / i32 / f32. Detect by
// checking which interpretation yields only {0,1} values, normalize to u8.
__global__ void k_mask_norm(const void* p) {
    __shared__ int ok32, okf;
    if (threadIdx.x == 0) { ok32 = 1; okf = 1; }
    __syncthreads();
    const unsigned char* pb = (const unsigned char*)p;
    const int* pi = (const int*)p;
    const float* pf = (const float*)p;
    for (int i = threadIdx.x; i < 4096; i += blockDim.x) {  // 4096*4B stays inside even a u8 buffer
        int v = pi[i];
        if (v != 0 && v != 1) ok32 = 0;
        float f = pf[i];
        if (f != 0.0f && f != 1.0f) okf = 0;
    }
    __syncthreads();
    for (int i = threadIdx.x; i < Bn * Mn; i += blockDim.x) {
        unsigned char m;
        if (ok32)      m = (pi[i] != 0);
        else if (okf)  m = (pf[i] != 0.0f);
        else           m = (pb[i] != 0);
        d_mask[i] = m;
    }
}

// ---------------- tiled fp32 GEMM core: 128x128x8, 8x8 microtile ----------------
// BT=true : B operand is W[n][k] row-major (ldb = K)  -> C = A @ W^T
// BT=false: B operand is B[k][n] row-major (ldb = N)  -> C = A @ B
template <bool BT>
__device__ __forceinline__ void gemm_tile(
    const float* __restrict__ A, int lda,
    const float* __restrict__ Bp, int ldb,
    float* __restrict__ C, int ldc,
    const float* __restrict__ bias, int K, int act)
{
    __shared__ float As[8][128];
    __shared__ float Bs[8][128];
    const int tid = threadIdx.x;
    const int tx = tid & 15, ty = tid >> 4;
    const int m0 = blockIdx.y * 128, n0 = blockIdx.x * 128;

    float acc[8][8];
#pragma unroll
    for (int i = 0; i < 8; i++)
#pragma unroll
        for (int j = 0; j < 8; j++) acc[i][j] = 0.0f;

    const int ar = tid >> 1, akc = (tid & 1) * 4;   // A / BT-B loader mapping
    const int bkk = tid >> 5, bnc = (tid & 31) * 4; // NN-B loader mapping

    for (int k0 = 0; k0 < K; k0 += 8) {
        float4 av = *(const float4*)(A + (size_t)(m0 + ar) * lda + (k0 + akc));
        As[akc + 0][ar] = av.x; As[akc + 1][ar] = av.y;
        As[akc + 2][ar] = av.z; As[akc + 3][ar] = av.w;
        if (BT) {
            float4 bv = *(const float4*)(Bp + (size_t)(n0 + ar) * ldb + (k0 + akc));
            Bs[akc + 0][ar] = bv.x; Bs[akc + 1][ar] = bv.y;
            Bs[akc + 2][ar] = bv.z; Bs[akc + 3][ar] = bv.w;
        } else {
            float4 bv = *(const float4*)(Bp + (size_t)(k0 + bkk) * ldb + (n0 + bnc));
            *(float4*)(&Bs[bkk][bnc]) = bv;
        }
        __syncthreads();
#pragma unroll
        for (int kk = 0; kk < 8; kk++) {
            float a[8], bb[8];
            *(float4*)&a[0]  = *(const float4*)&As[kk][ty * 8];
            *(float4*)&a[4]  = *(const float4*)&As[kk][ty * 8 + 4];
            *(float4*)&bb[0] = *(const float4*)&Bs[kk][tx * 8];
            *(float4*)&bb[4] = *(const float4*)&Bs[kk][tx * 8 + 4];
#pragma unroll
            for (int i = 0; i < 8; i++)
#pragma unroll
                for (int j = 0; j < 8; j++)
                    acc[i][j] = fmaf(a[i], bb[j], acc[i][j]);
        }
        __syncthreads();
    }

#pragma unroll
    for (int i = 0; i < 8; i++) {
        int m = m0 + ty * 8 + i;
        float* crow = C + (size_t)m * ldc + n0 + tx * 8;
#pragma unroll
        for (int j = 0; j < 8; j++) {
            float v = acc[i][j];
            if (bias) v += bias[n0 + tx * 8 + j];
            if (act) v = gelu_f(v);
            acc[i][j] = v;
        }
        *(float4*)crow       = *(float4*)&acc[i][0];
        *(float4*)(crow + 4) = *(float4*)&acc[i][4];
    }
}

// ---------------- GEMM wrappers (scratch referenced directly) ----------------
__global__ void __launch_bounds__(256) k_gemm_hidgo(const float* w1, const float* b1) {
    gemm_tile<true>(d_featgo, D3n, w1, D3n, d_hidgo, MIDn, b1, D3n, 1);
}
__global__ void __launch_bounds__(256) k_gemm_hidga(const float* w1, const float* b1) {
    gemm_tile<true>(d_featga, D3n, w1, D3n, d_hidga, MIDn, b1, D3n, 1);
}
__global__ void __launch_bounds__(256) k_gemm_a2o(const float* tokens, const float* w) {
    gemm_tile<true>(tokens + Hn, Mn * Hn, w, Hn, d_a2o, Hn, (const float*)0, Hn, 0);
}
__global__ void __launch_bounds__(256) k_gemm_o2a(const float* w) {
    gemm_tile<true>(d_omean, Hn, w, Hn, d_o2a, Hn, (const float*)0, Hn, 0);
}
__global__ void __launch_bounds__(256) k_gemm_out(const float* w, const float* bb) {
    gemm_tile<true>(d_h1, Hn, w, Hn, d_h2, Hn, bb, Hn, 1);
}
// z[b,m,r,h] = factors[m,r,0,h] + sum_d mixed[b,m,d]*factors[m,r,1+d,h]
__global__ void __launch_bounds__(256) k_gemm_z(const float* factors) {
    int mr = blockIdx.z;  // m*Rn + r
    gemm_tile<false>(d_mixed + (mr / Rn) * Hn, Mn * Hn,
                     factors + ((size_t)mr * 1025 + 1) * Hn, Hn,
                     d_zbuf + (size_t)mr * Hn, Mn * Rn * Hn,
                     factors + (size_t)mr * 1025 * Hn, Hn, 0);
}

// ---------------- feat builders (concat + LN, stashed in smem) ----------------
__global__ void k_feat_go(const float* tokens, const float* lnw, const float* lnb) {
    int row = blockIdx.x;
    int b = row / 3, j = row - 3 * b;
    int oj = (j == 0) ? 0 : (j + 1);          // OTHERS = {0,2,3}
    const float* tok = tokens + (size_t)b * Mn * Hn;
    float mj = d_mask[b * Mn + oj] ? 1.0f : 0.0f;
    __shared__ float sf[D3n];
    float s = 0.f, q = 0.f;
    for (int k = threadIdx.x; k < Hn; k += blockDim.x) {
        float t = tok[oj * Hn + k] * mj;
        float sv = tok[Hn + k];               // audio, unmasked
        float dv = fabsf(t - sv);
        sf[k] = t; sf[Hn + k] = sv; sf[2 * Hn + k] = dv;
        s += t + sv + dv; q += t * t + sv * sv + dv * dv;
    }
    float2 rr = blkSum2(s, q);
    float mean = rr.x / D3n;
    float var = rr.y / D3n - mean * mean;
    float rstd = rsqrtf(var + 1e-5f);
    float* o = d_featgo + (size_t)row * D3n;
    for (int k = threadIdx.x; k < D3n; k += blockDim.x)
        o[k] = (sf[k] - mean) * rstd * lnw[k] + lnb[k];
}

__global__ void k_feat_ga(const float* tokens, const float* lnw, const float* lnb) {
    int b = blockIdx.x;
    const float* tok = tokens + (size_t)b * Mn * Hn;
    __shared__ float sf[D3n];
    float s = 0.f, q = 0.f;
    for (int k = threadIdx.x; k < Hn; k += blockDim.x) {
        float t = tok[Hn + k];                // audio, unmasked
        float sv = d_omean[(size_t)b * Hn + k];
        float dv = fabsf(t - sv);
        sf[k] = t; sf[Hn + k] = sv; sf[2 * Hn + k] = dv;
        s += t + sv + dv; q += t * t + sv * sv + dv * dv;
    }
    float2 rr = blkSum2(s, q);
    float mean = rr.x / D3n;
    float var = rr.y / D3n - mean * mean;
    float rstd = rsqrtf(var + 1e-5f);
    float* o = d_featga + (size_t)b * D3n;
    for (int k = threadIdx.x; k < D3n; k += blockDim.x)
        o[k] = (sf[k] - mean) * rstd * lnw[k] + lnb[k];
}

// ---------------- gate tail: sigmoid(hidden . w2 + b2) ----------------
__global__ void k_gate_go(const float* w2, const float* b2) {
    int row = blockIdx.x;
    const float* hr = d_hidgo + (size_t)row * MIDn;
    float v = 0.f;
    for (int k = threadIdx.x; k < MIDn; k += blockDim.x) v += hr[k] * w2[k];
    float2 rr = blkSum2(v, 0.f);
    if (threadIdx.x == 0) d_ggo[row] = 1.0f / (1.0f + expf(-(rr.x + b2[0])));
}
__global__ void k_gate_ga(const float* w2, const float* b2) {
    int row = blockIdx.x;
    const float* hr = d_hidga + (size_t)row * MIDn;
    float v = 0.f;
    for (int k = threadIdx.x; k < MIDn; k += blockDim.x) v += hr[k] * w2[k];
    float2 rr = blkSum2(v, 0.f);
    if (threadIdx.x == 0) d_gavec[row] = 1.0f / (1.0f + expf(-(rr.x + b2[0])));
}

// ---------------- others_new: where(pv, LN(others+g*a2o), others)*mask ----------------
__global__ void k_others_new(const float* tokens, const float* lnw, const float* lnb) {
    int row = blockIdx.x;
    int b = row / 3, j = row - 3 * b;
    int oj = (j == 0) ? 0 : (j + 1);
    const float* tok = tokens + (size_t)b * Mn * Hn;
    int moj = d_mask[b * Mn + oj], ma = d_mask[b * Mn + 1];
    float* o = d_onew + (size_t)row * Hn;
    if (moj && ma) {                        // pair_valid (and moj==1 -> others==tokens)
        __shared__ float sx[Hn];
        float g = d_ggo[row];
        float s = 0.f, q = 0.f;
        for (int k = threadIdx.x; k < Hn; k += blockDim.x) {
            float x = tok[oj * Hn + k] + g * d_a2o[(size_t)b * Hn + k];
            sx[k] = x; s += x; q += x * x;
        }
        float2 rr = blkSum2(s, q);
        float mean = rr.x / Hn;
        float var = rr.y / Hn - mean * mean;
        float rstd = rsqrtf(var + 1e-5f);
        for (int k = threadIdx.x; k < Hn; k += blockDim.x)
            o[k] = (sx[k] - mean) * rstd * lnw[k] + lnb[k];
    } else {
        float mf = moj ? 1.0f : 0.0f;
        for (int k = threadIdx.x; k < Hn; k += blockDim.x)
            o[k] = tok[oj * Hn + k] * mf;
    }
}

__global__ void k_omean() {
    int idx = blockIdx.x * 256 + threadIdx.x;
    int b = idx >> 10, h = idx & 1023;
    float m0 = d_mask[b * 4 + 0] ? 1.f : 0.f;
    float m2 = d_mask[b * 4 + 2] ? 1.f : 0.f;
    float m3 = d_mask[b * 4 + 3] ? 1.f : 0.f;
    float denom = fmaxf(1.0f, m0 + m2 + m3);
    size_t base = (size_t)b * 3 * Hn;
    float sum = d_onew[base + h] + d_onew[base + Hn + h] + d_onew[base + 2 * Hn + h];
    d_omean[idx] = sum / denom;
}

// ---------------- mixed assembly (incl. mixed_audio LN branch) ----------------
__global__ void k_mixed(const float* tokens, const float* lnw, const float* lnb) {
    int b = blockIdx.x;
    const float* tok = tokens + (size_t)b * Mn * Hn;
    int m0 = d_mask[b * 4], m1 = d_mask[b * 4 + 1], m2 = d_mask[b * 4 + 2], m3 = d_mask[b * 4 + 3];
    float* mx = d_mixed + (size_t)b * Mn * Hn;
    int aum = m1 && (m0 || m2 || m3);
    if (aum) {
        __shared__ float sx[Hn];
        float g = d_gavec[b];
        float s = 0.f, q = 0.f;
        for (int k = threadIdx.x; k < Hn; k += blockDim.x) {
            float x = tok[Hn + k] + g * d_o2a[(size_t)b * Hn + k];
            sx[k] = x; s += x; q += x * x;
        }
        float2 rr = blkSum2(s, q);
        float mean = rr.x / Hn;
        float var = rr.y / Hn - mean * mean;
        float rstd = rsqrtf(var + 1e-5f);
        for (int k = threadIdx.x; k < Hn; k += blockDim.x)
            mx[Hn + k] = (sx[k] - mean) * rstd * lnw[k] + lnb[k];   // * m1 (==1)
    } else {
        float f = m1 ? 1.0f : 0.0f;
        for (int k = threadIdx.x; k < Hn; k += blockDim.x)
            mx[Hn + k] = tok[Hn + k] * f;
    }
    float f0 = m0 ? 1.f : 0.f, f2 = m2 ? 1.f : 0.f, f3 = m3 ? 1.f : 0.f;
    size_t ob = (size_t)b * 3 * Hn;
    for (int k = threadIdx.x; k < Hn; k += blockDim.x) {
        mx[k]           = d_onew[ob + k] * f0;            // token 0
        mx[2 * Hn + k]  = d_onew[ob + Hn + k] * f2;       // token 2
        mx[3 * Hn + k]  = d_onew[ob + 2 * Hn + k] * f3;   // token 3
    }
}

// ---------------- rank product + weighted sum over r ----------------
__global__ void k_combine(const float* rank_w, const float* lmf_bias) {
    int idx = blockIdx.x * 256 + threadIdx.x;
    int b = idx >> 10, h = idx & 1023;
    const unsigned char* mk = d_mask + b * 4;
    bool m0 = mk[0], m1 = mk[1], m2 = mk[2], m3 = mk[3];
    const float* zb = d_zbuf + (size_t)b * (Mn * Rn * Hn) + h;
    float acc = 0.f;
#pragma unroll
    for (int r = 0; r < Rn; r++) {
        float p = rank_w[r];
        if (m0) p *= zb[(0 * Rn + r) * Hn];
        if (m1) p *= zb[(1 * Rn + r) * Hn];
        if (m2) p *= zb[(2 * Rn + r) * Hn];
        if (m3) p *= zb[(3 * Rn + r) * Hn];
        acc += p;
    }
    d_fused[idx] = acc + lmf_bias[h];
}

// ---------------- row LayerNorms ----------------
__device__ __forceinline__ void rowln(const float* x, float* y, const float* w, const float* bb) {
    float s = 0.f, q = 0.f;
    for (int k = threadIdx.x; k < Hn; k += blockDim.x) { float v = x[k]; s += v; q += v * v; }
    float2 rr = blkSum2(s, q);
    float mean = rr.x / Hn;
    float var = rr.y / Hn - mean * mean;
    float rstd = rsqrtf(var + 1e-5f);
    for (int k = threadIdx.x; k < Hn; k += blockDim.x)
        y[k] = (x[k] - mean) * rstd * w[k] + bb[k];
}
__global__ void k_ln_fused(const float* w, const float* bb) {
    int b = blockIdx.x;
    rowln(d_fused + (size_t)b * Hn, d_h1 + (size_t)b * Hn, w, bb);
}
__global__ void k_ln_out(const float* w, const float* bb, float* out) {
    int b = blockIdx.x;
    rowln(d_h2 + (size_t)b * Hn, out + (size_t)b * Hn, w, bb);
}

// ---------------- launch ----------------
extern "C" void kernel_launch(void* const* d_in, const int* in_sizes, int n_in,
                              void* d_out, int out_size) {
    const float* tokens   = (const float*)d_in[0];
    const void*  maskraw  = d_in[1];
    const float* ln_go_w  = (const float*)d_in[2];
    const float* ln_go_b  = (const float*)d_in[3];
    const float* go_w1    = (const float*)d_in[4];
    const float* go_b1    = (const float*)d_in[5];
    const float* go_w2    = (const float*)d_in[6];
    const float* go_b2    = (const float*)d_in[7];
    const float* ln_ga_w  = (const float*)d_in[8];
    const float* ln_ga_b  = (const float*)d_in[9];
    const float* ga_w1    = (const float*)d_in[10];
    const float* ga_b1    = (const float*)d_in[11];
    const float* ga_w2    = (const float*)d_in[12];
    const float* ga_b2    = (const float*)d_in[13];
    const float* a2o_w    = (const float*)d_in[14];
    const float* o2a_w    = (const float*)d_in[15];
    const float* ln_o_w   = (const float*)d_in[16];
    const float* ln_o_b   = (const float*)d_in[17];
    const float* ln_a_w   = (const float*)d_in[18];
    const float* ln_a_b   = (const float*)d_in[19];
    const float* factors  = (const float*)d_in[20];
    const float* rank_w   = (const float*)d_in[21];
    const float* lmf_bias = (const float*)d_in[22];
    const float* out_ln1w = (const float*)d_in[23];
    const float* out_ln1b = (const float*)d_in[24];
    const float* out_w    = (const float*)d_in[25];
    const float* out_b    = (const float*)d_in[26];
    const float* out_ln2w = (const float*)d_in[27];
    const float* out_ln2b = (const float*)d_in[28];
    float* out = (float*)d_out;

    k_mask_norm<<<1, 256>>>(maskraw);
    k_gemm_a2o<<<dim3(Hn / 128, Bn / 128), 256>>>(tokens, a2o_w);
    k_feat_go<<<3 * Bn, 256>>>(tokens, ln_go_w, ln_go_b);
    k_gemm_hidgo<<<dim3(MIDn / 128, 3 * Bn / 128), 256>>>(go_w1, go_b1);
    k_gate_go<<<3 * Bn, 256>>>(go_w2, go_b2);
    k_others_new<<<3 * Bn, 256>>>(tokens, ln_o_w, ln_o_b);
    k_omean<<<Bn * Hn / 256, 256>>>();
    k_feat_ga<<<Bn, 256>>>(tokens, ln_ga_w, ln_ga_b);
    k_gemm_hidga<<<dim3(MIDn / 128, Bn / 128), 256>>>(ga_w1, ga_b1);
    k_gate_ga<<<Bn, 256>>>(ga_w2, ga_b2);
    k_gemm_o2a<<<dim3(Hn / 128, Bn / 128), 256>>>(o2a_w);
    k_mixed<<<Bn, 256>>>(tokens, ln_a_w, ln_a_b);
    k_gemm_z<<<dim3(Hn / 128, Bn / 128, Mn * Rn), 256>>>(factors);
    k_combine<<<Bn * Hn / 256, 256>>>(rank_w, lmf_bias);
    k_ln_fused<<<Bn, 256>>>(out_ln1w, out_ln1b);
    k_gemm_out<<<dim3(Hn / 128, Bn / 128), 256>>>(out_w, out_b);
    k_ln_out<<<Bn, 256>>>(out_ln2w, out_ln2b, out);
}

// round 3
// speedup vs baseline: 1.8120x; 1.8120x over previous
#include <cuda_runtime.h>
#include <cuda_bf16.h>
#include <math.h>
#include <cstdint>

#define Bn   4096
#define Mn   4
#define Hn   1024
#define Rn   10
#define MIDn 512
#define D3n  3072

// ---------------- scratch (__device__ globals: alloc-free) ----------------
__device__ float d_featgo[3 * Bn * D3n];
__device__ float d_hidgo[3 * Bn * MIDn];
__device__ float d_ggo[3 * Bn];
__device__ float d_a2o[Bn * Hn];
__device__ float d_onew[Bn * 3 * Hn];
__device__ float d_omean[Bn * Hn];
__device__ float d_featga[Bn * D3n];
__device__ float d_hidga[Bn * MIDn];
__device__ float d_gavec[Bn];
__device__ float d_o2a[Bn * Hn];
__device__ float d_mixed[Bn * Mn * Hn];
__device__ float d_zbuf[167772160];             // B*M*R*H fp32
__device__ float d_fused[Bn * Hn];
__device__ float d_h1[Bn * Hn];
__device__ float d_h2[Bn * Hn];
__device__ unsigned char d_mask[Bn * Mn];
// bf16-split operands for the LMF GEMM
__device__ __nv_bfloat16 d_ahi[Mn * Bn * Hn];      // [m][b][h]
__device__ __nv_bfloat16 d_alo[Mn * Bn * Hn];
__device__ __nv_bfloat16 d_fhi[Mn * Rn * Hn * Hn]; // [mr][h][d] (K-contiguous)
__device__ __nv_bfloat16 d_flo[Mn * Rn * Hn * Hn];

// ---------------- generic helpers ----------------
__device__ __forceinline__ float gelu_f(float x) {
    return 0.5f * x * (1.0f + erff(x * 0.70710678118654752f));
}
__device__ __forceinline__ float2 blkSum2(float a, float b) {
    __shared__ float sa[32], sb[32];
    __shared__ float ra, rb;
    int lane = threadIdx.x & 31, w = threadIdx.x >> 5;
#pragma unroll
    for (int o = 16; o > 0; o >>= 1) {
        a += __shfl_xor_sync(0xffffffffu, a, o);
        b += __shfl_xor_sync(0xffffffffu, b, o);
    }
    if (lane == 0) { sa[w] = a; sb[w] = b; }
    __syncthreads();
    if (threadIdx.x == 0) {
        float x = 0.f, y = 0.f;
        int nw = blockDim.x >> 5;
        for (int i = 0; i < nw; i++) { x += sa[i]; y += sb[i]; }
        ra = x; rb = y;
    }
    __syncthreads();
    return make_float2(ra, rb);
}

// ---------------- mma.sync helpers (arch-portable PTX) ----------------
__device__ __forceinline__ uint32_t smem_u32(const void* p) {
    uint32_t a;
    asm("{ .reg .u64 t; cvta.to.shared.u64 t, %1; cvt.u32.u64 %0, t; }" : "=r"(a) : "l"(p));
    return a;
}
__device__ __forceinline__ void ldm_x4(uint32_t& r0, uint32_t& r1, uint32_t& r2, uint32_t& r3,
                                       uint32_t addr) {
    asm volatile("ldmatrix.sync.aligned.m8n8.x4.shared.b16 {%0,%1,%2,%3}, [%4];"
                 : "=r"(r0), "=r"(r1), "=r"(r2), "=r"(r3) : "r"(addr));
}
__device__ __forceinline__ void mma_bf16(float* c, const uint32_t* a, const uint32_t* b) {
    asm volatile("mma.sync.aligned.m16n8k16.row.col.f32.bf16.bf16.f32 "
                 "{%0,%1,%2,%3}, {%4,%5,%6,%7}, {%8,%9}, {%0,%1,%2,%3};"
                 : "+f"(c[0]), "+f"(c[1]), "+f"(c[2]), "+f"(c[3])
                 : "r"(a[0]), "r"(a[1]), "r"(a[2]), "r"(a[3]), "r"(b[0]), "r"(b[1]));
}
__device__ __forceinline__ void cp16(uint32_t dst, const void* src) {
    asm volatile("cp.async.cg.shared.global [%0], [%1], 16;" :: "r"(dst), "l"(src));
}
#define CP_COMMIT() asm volatile("cp.async.commit_group;" ::: "memory")
#define CP_WAIT(n)  asm volatile("cp.async.wait_group %0;" :: "n"(n) : "memory")

// ---------------- mask dtype sniffer ----------------
__global__ void k_mask_norm(const void* p) {
    __shared__ int ok32, okf;
    if (threadIdx.x == 0) { ok32 = 1; okf = 1; }
    __syncthreads();
    const unsigned char* pb = (const unsigned char*)p;
    const int* pi = (const int*)p;
    const float* pf = (const float*)p;
    for (int i = threadIdx.x; i < 4096; i += blockDim.x) {
        int v = pi[i];
        if (v != 0 && v != 1) ok32 = 0;
        float f = pf[i];
        if (f != 0.0f && f != 1.0f) okf = 0;
    }
    __syncthreads();
    for (int i = threadIdx.x; i < Bn * Mn; i += blockDim.x) {
        unsigned char m;
        if (ok32)      m = (pi[i] != 0);
        else if (okf)  m = (pf[i] != 0.0f);
        else           m = (pb[i] != 0);
        d_mask[i] = m;
    }
}

// ---------------- SIMT fp32 GEMM (non-LMF ops) ----------------
template <bool BT>
__device__ __forceinline__ void gemm_tile(
    const float* __restrict__ A, int lda,
    const float* __restrict__ Bp, int ldb,
    float* __restrict__ C, int ldc,
    const float* __restrict__ bias, int K, int act)
{
    __shared__ float As[8][128];
    __shared__ float Bs[8][128];
    const int tid = threadIdx.x;
    const int tx = tid & 15, ty = tid >> 4;
    const int m0 = blockIdx.y * 128, n0 = blockIdx.x * 128;
    float acc[8][8];
#pragma unroll
    for (int i = 0; i < 8; i++)
#pragma unroll
        for (int j = 0; j < 8; j++) acc[i][j] = 0.0f;
    const int ar = tid >> 1, akc = (tid & 1) * 4;
    const int bkk = tid >> 5, bnc = (tid & 31) * 4;
    for (int k0 = 0; k0 < K; k0 += 8) {
        float4 av = *(const float4*)(A + (size_t)(m0 + ar) * lda + (k0 + akc));
        As[akc + 0][ar] = av.x; As[akc + 1][ar] = av.y;
        As[akc + 2][ar] = av.z; As[akc + 3][ar] = av.w;
        if (BT) {
            float4 bv = *(const float4*)(Bp + (size_t)(n0 + ar) * ldb + (k0 + akc));
            Bs[akc + 0][ar] = bv.x; Bs[akc + 1][ar] = bv.y;
            Bs[akc + 2][ar] = bv.z; Bs[akc + 3][ar] = bv.w;
        } else {
            float4 bv = *(const float4*)(Bp + (size_t)(k0 + bkk) * ldb + (n0 + bnc));
            *(float4*)(&Bs[bkk][bnc]) = bv;
        }
        __syncthreads();
#pragma unroll
        for (int kk = 0; kk < 8; kk++) {
            float a[8], bb[8];
            *(float4*)&a[0]  = *(const float4*)&As[kk][ty * 8];
            *(float4*)&a[4]  = *(const float4*)&As[kk][ty * 8 + 4];
            *(float4*)&bb[0] = *(const float4*)&Bs[kk][tx * 8];
            *(float4*)&bb[4] = *(const float4*)&Bs[kk][tx * 8 + 4];
#pragma unroll
            for (int i = 0; i < 8; i++)
#pragma unroll
                for (int j = 0; j < 8; j++)
                    acc[i][j] = fmaf(a[i], bb[j], acc[i][j]);
        }
        __syncthreads();
    }
#pragma unroll
    for (int i = 0; i < 8; i++) {
        int m = m0 + ty * 8 + i;
        float* crow = C + (size_t)m * ldc + n0 + tx * 8;
#pragma unroll
        for (int j = 0; j < 8; j++) {
            float v = acc[i][j];
            if (bias) v += bias[n0 + tx * 8 + j];
            if (act) v = gelu_f(v);
            acc[i][j] = v;
        }
        *(float4*)crow       = *(float4*)&acc[i][0];
        *(float4*)(crow + 4) = *(float4*)&acc[i][4];
    }
}

__global__ void __launch_bounds__(256) k_gemm_hidgo(const float* w1, const float* b1) {
    gemm_tile<true>(d_featgo, D3n, w1, D3n, d_hidgo, MIDn, b1, D3n, 1);
}
__global__ void __launch_bounds__(256) k_gemm_hidga(const float* w1, const float* b1) {
    gemm_tile<true>(d_featga, D3n, w1, D3n, d_hidga, MIDn, b1, D3n, 1);
}
__global__ void __launch_bounds__(256) k_gemm_a2o(const float* tokens, const float* w) {
    gemm_tile<true>(tokens + Hn, Mn * Hn, w, Hn, d_a2o, Hn, (const float*)0, Hn, 0);
}
__global__ void __launch_bounds__(256) k_gemm_o2a(const float* w) {
    gemm_tile<true>(d_omean, Hn, w, Hn, d_o2a, Hn, (const float*)0, Hn, 0);
}
__global__ void __launch_bounds__(256) k_gemm_out(const float* w, const float* bb) {
    gemm_tile<true>(d_h1, Hn, w, Hn, d_h2, Hn, bb, Hn, 1);
}

// ---------------- bf16-split prep ----------------
__global__ void k_prep_mixed() {
    int idx = blockIdx.x * 256 + threadIdx.x;      // over B*M*H
    int h = idx & 1023;
    int bm = idx >> 10;
    int b = bm >> 2, m = bm & 3;
    float x = d_mixed[idx];
    __nv_bfloat16 hi = __float2bfloat16(x);
    float lo = x - __bfloat162float(hi);
    size_t o = ((size_t)m * Bn + b) * Hn + h;
    d_ahi[o] = hi;
    d_alo[o] = __float2bfloat16(lo);
}

// factors[m][r][1+d][h] fp32 -> [mr][h][d] bf16 hi/lo (transpose)
__global__ void __launch_bounds__(256) k_prep_factors(const float* __restrict__ f) {
    __shared__ float t[32][33];
    int mr = blockIdx.z;
    int d0 = blockIdx.x * 32, h0 = blockIdx.y * 32;
    int tx = threadIdx.x, ty = threadIdx.y;
#pragma unroll
    for (int i = ty; i < 32; i += 8)
        t[i][tx] = f[((size_t)mr * 1025 + 1 + d0 + i) * Hn + h0 + tx];
    __syncthreads();
#pragma unroll
    for (int i = ty; i < 32; i += 8) {
        float x = t[tx][i];                        // in[d0+tx][h0+i]
        __nv_bfloat16 hi = __float2bfloat16(x);
        float lo = x - __bfloat162float(hi);
        size_t o = ((size_t)mr * Hn + h0 + i) * Hn + d0 + tx;
        d_fhi[o] = hi;
        d_flo[o] = __float2bfloat16(lo);
    }
}

// ---------------- LMF GEMM via mma.sync bf16 (3-term split) ----------------
// z[b, mr, h] = sum_d mixed[b,m,d] * factors[m,r,1+d,h]
// block 128(b) x 128(h); 8 warps (2 M x 4 N), warp tile 64x32;
// k-chunk 32, cp.async double-buffered.
#define ZKC   32
#define ZPAD  40                   // bf16 elems per smem row (80 B) -> conflict-free ldmatrix
#define ZBUFB (128 * ZPAD * 2)     // 10240 B per operand buffer
#define ZSTAGE (4 * ZBUFB)         // Ahi,Alo,Bhi,Blo
#define ZSM_TOTAL (2 * ZSTAGE)     // 81920 B

__global__ void __launch_bounds__(256) k_gemm_z_mma() {
    extern __shared__ char zsm[];
    const uint32_t sbase = smem_u32(zsm);
    const int tid = threadIdx.x;
    const int wid = tid >> 5, lane = tid & 31;
    const int h0 = blockIdx.x * 128;
    const int b0 = blockIdx.y * 128;
    const int mr = blockIdx.z;
    const int m = mr / Rn;

    const __nv_bfloat16* gbase[4];
    gbase[0] = d_ahi + ((size_t)m * Bn + b0) * Hn;
    gbase[1] = d_alo + ((size_t)m * Bn + b0) * Hn;
    gbase[2] = d_fhi + ((size_t)mr * Hn + h0) * Hn;
    gbase[3] = d_flo + ((size_t)mr * Hn + h0) * Hn;

    const int lrow = tid >> 1;            // 0..127
    const int lseg = (tid & 1) * 2;       // 0 or 2 (two 16B segments each)

    auto load_stage = [&](int st, int k0) {
#pragma unroll
        for (int bsel = 0; bsel < 4; bsel++) {
            const __nv_bfloat16* src = gbase[bsel] + (size_t)lrow * Hn + k0 + lseg * 8;
            uint32_t dst = sbase + st * ZSTAGE + bsel * ZBUFB + lrow * (ZPAD * 2) + lseg * 16;
            cp16(dst, src);
            cp16(dst + 16, src + 8);
        }
    };

    float acc[4][4][4];
#pragma unroll
    for (int i = 0; i < 4; i++)
#pragma unroll
        for (int j = 0; j < 4; j++)
#pragma unroll
            for (int c = 0; c < 4; c++) acc[i][j][c] = 0.0f;

    const int wm0 = (wid >> 2) * 64;      // warp m-offset in tile
    const int wn0 = (wid & 3) * 32;       // warp n-offset in tile

    // ldmatrix lane addressing
    const int a_r = lane & 15;                               // row within 16
    const int a_c8 = (lane >> 4) << 3;                       // 0 / 8 (k)
    const int b_r = (lane & 7) + ((lane >> 4) << 3);         // n within 16
    const int b_c8 = ((lane >> 3) & 1) << 3;                 // 0 / 8 (k)

    load_stage(0, 0);
    CP_COMMIT();

    const int NIT = Hn / ZKC;             // 32
    for (int it = 0; it < NIT; it++) {
        const int st = it & 1;
        if (it + 1 < NIT) {
            load_stage(st ^ 1, (it + 1) * ZKC);
            CP_COMMIT();
            CP_WAIT(1);
        } else {
            CP_WAIT(0);
        }
        __syncthreads();

        const uint32_t sAh = sbase + st * ZSTAGE + 0 * ZBUFB;
        const uint32_t sAl = sbase + st * ZSTAGE + 1 * ZBUFB;
        const uint32_t sBh = sbase + st * ZSTAGE + 2 * ZBUFB;
        const uint32_t sBl = sbase + st * ZSTAGE + 3 * ZBUFB;

#pragma unroll
        for (int ks = 0; ks < 2; ks++) {
            const int kb = ks * 16;
            uint32_t aH[4][4], aL[4][4], bH[4][2], bL[4][2];
#pragma unroll
            for (int mi = 0; mi < 4; mi++) {
                uint32_t off = (uint32_t)(wm0 + mi * 16 + a_r) * (ZPAD * 2) + (kb + a_c8) * 2;
                ldm_x4(aH[mi][0], aH[mi][1], aH[mi][2], aH[mi][3], sAh + off);
                ldm_x4(aL[mi][0], aL[mi][1], aL[mi][2], aL[mi][3], sAl + off);
            }
#pragma unroll
            for (int p = 0; p < 2; p++) {
                uint32_t off = (uint32_t)(wn0 + p * 16 + b_r) * (ZPAD * 2) + (kb + b_c8) * 2;
                ldm_x4(bH[2 * p][0], bH[2 * p][1], bH[2 * p + 1][0], bH[2 * p + 1][1], sBh + off);
                ldm_x4(bL[2 * p][0], bL[2 * p][1], bL[2 * p + 1][0], bL[2 * p + 1][1], sBl + off);
            }
#pragma unroll
            for (int mi = 0; mi < 4; mi++)
#pragma unroll
                for (int ni = 0; ni < 4; ni++) {
                    mma_bf16(acc[mi][ni], aH[mi], bH[ni]);
                    mma_bf16(acc[mi][ni], aH[mi], bL[ni]);
                    mma_bf16(acc[mi][ni], aL[mi], bH[ni]);
                }
        }
        __syncthreads();
    }

    // epilogue: write z tile
#pragma unroll
    for (int mi = 0; mi < 4; mi++) {
        int r0 = b0 + wm0 + mi * 16 + (lane >> 2);
        float* d0 = d_zbuf + ((size_t)r0 * (Mn * Rn) + mr) * Hn + h0;
        float* d1 = d_zbuf + ((size_t)(r0 + 8) * (Mn * Rn) + mr) * Hn + h0;
#pragma unroll
        for (int ni = 0; ni < 4; ni++) {
            int cc = wn0 + ni * 8 + (lane & 3) * 2;
            *(float2*)(d0 + cc) = make_float2(acc[mi][ni][0], acc[mi][ni][1]);
            *(float2*)(d1 + cc) = make_float2(acc[mi][ni][2], acc[mi][ni][3]);
        }
    }
}

// ---------------- feat builders ----------------
__global__ void k_feat_go(const float* tokens, const float* lnw, const float* lnb) {
    int row = blockIdx.x;
    int b = row / 3, j = row - 3 * b;
    int oj = (j == 0) ? 0 : (j + 1);
    const float* tok = tokens + (size_t)b * Mn * Hn;
    float mj = d_mask[b * Mn + oj] ? 1.0f : 0.0f;
    __shared__ float sf[D3n];
    float s = 0.f, q = 0.f;
    for (int k = threadIdx.x; k < Hn; k += blockDim.x) {
        float t = tok[oj * Hn + k] * mj;
        float sv = tok[Hn + k];
        float dv = fabsf(t - sv);
        sf[k] = t; sf[Hn + k] = sv; sf[2 * Hn + k] = dv;
        s += t + sv + dv; q += t * t + sv * sv + dv * dv;
    }
    float2 rr = blkSum2(s, q);
    float mean = rr.x / D3n;
    float var = rr.y / D3n - mean * mean;
    float rstd = rsqrtf(var + 1e-5f);
    float* o = d_featgo + (size_t)row * D3n;
    for (int k = threadIdx.x; k < D3n; k += blockDim.x)
        o[k] = (sf[k] - mean) * rstd * lnw[k] + lnb[k];
}

__global__ void k_feat_ga(const float* tokens, const float* lnw, const float* lnb) {
    int b = blockIdx.x;
    const float* tok = tokens + (size_t)b * Mn * Hn;
    __shared__ float sf[D3n];
    float s = 0.f, q = 0.f;
    for (int k = threadIdx.x; k < Hn; k += blockDim.x) {
        float t = tok[Hn + k];
        float sv = d_omean[(size_t)b * Hn + k];
        float dv = fabsf(t - sv);
        sf[k] = t; sf[Hn + k] = sv; sf[2 * Hn + k] = dv;
        s += t + sv + dv; q += t * t + sv * sv + dv * dv;
    }
    float2 rr = blkSum2(s, q);
    float mean = rr.x / D3n;
    float var = rr.y / D3n - mean * mean;
    float rstd = rsqrtf(var + 1e-5f);
    float* o = d_featga + (size_t)b * D3n;
    for (int k = threadIdx.x; k < D3n; k += blockDim.x)
        o[k] = (sf[k] - mean) * rstd * lnw[k] + lnb[k];
}

// ---------------- gate tails ----------------
__global__ void k_gate_go(const float* w2, const float* b2) {
    int row = blockIdx.x;
    const float* hr = d_hidgo + (size_t)row * MIDn;
    float v = 0.f;
    for (int k = threadIdx.x; k < MIDn; k += blockDim.x) v += hr[k] * w2[k];
    float2 rr = blkSum2(v, 0.f);
    if (threadIdx.x == 0) d_ggo[row] = 1.0f / (1.0f + expf(-(rr.x + b2[0])));
}
__global__ void k_gate_ga(const float* w2, const float* b2) {
    int row = blockIdx.x;
    const float* hr = d_hidga + (size_t)row * MIDn;
    float v = 0.f;
    for (int k = threadIdx.x; k < MIDn; k += blockDim.x) v += hr[k] * w2[k];
    float2 rr = blkSum2(v, 0.f);
    if (threadIdx.x == 0) d_gavec[row] = 1.0f / (1.0f + expf(-(rr.x + b2[0])));
}

// ---------------- others_new ----------------
__global__ void k_others_new(const float* tokens, const float* lnw, const float* lnb) {
    int row = blockIdx.x;
    int b = row / 3, j = row - 3 * b;
    int oj = (j == 0) ? 0 : (j + 1);
    const float* tok = tokens + (size_t)b * Mn * Hn;
    int moj = d_mask[b * Mn + oj], ma = d_mask[b * Mn + 1];
    float* o = d_onew + (size_t)row * Hn;
    if (moj && ma) {
        __shared__ float sx[Hn];
        float g = d_ggo[row];
        float s = 0.f, q = 0.f;
        for (int k = threadIdx.x; k < Hn; k += blockDim.x) {
            float x = tok[oj * Hn + k] + g * d_a2o[(size_t)b * Hn + k];
            sx[k] = x; s += x; q += x * x;
        }
        float2 rr = blkSum2(s, q);
        float mean = rr.x / Hn;
        float var = rr.y / Hn - mean * mean;
        float rstd = rsqrtf(var + 1e-5f);
        for (int k = threadIdx.x; k < Hn; k += blockDim.x)
            o[k] = (sx[k] - mean) * rstd * lnw[k] + lnb[k];
    } else {
        float mf = moj ? 1.0f : 0.0f;
        for (int k = threadIdx.x; k < Hn; k += blockDim.x)
            o[k] = tok[oj * Hn + k] * mf;
    }
}

__global__ void k_omean() {
    int idx = blockIdx.x * 256 + threadIdx.x;
    int b = idx >> 10, h = idx & 1023;
    float m0 = d_mask[b * 4 + 0] ? 1.f : 0.f;
    float m2 = d_mask[b * 4 + 2] ? 1.f : 0.f;
    float m3 = d_mask[b * 4 + 3] ? 1.f : 0.f;
    float denom = fmaxf(1.0f, m0 + m2 + m3);
    size_t base = (size_t)b * 3 * Hn;
    float sum = d_onew[base + h] + d_onew[base + Hn + h] + d_onew[base + 2 * Hn + h];
    d_omean[idx] = sum / denom;
}

// ---------------- mixed assembly ----------------
__global__ void k_mixed(const float* tokens, const float* lnw, const float* lnb) {
    int b = blockIdx.x;
    const float* tok = tokens + (size_t)b * Mn * Hn;
    int m0 = d_mask[b * 4], m1 = d_mask[b * 4 + 1], m2 = d_mask[b * 4 + 2], m3 = d_mask[b * 4 + 3];
    float* mx = d_mixed + (size_t)b * Mn * Hn;
    int aum = m1 && (m0 || m2 || m3);
    if (aum) {
        __shared__ float sx[Hn];
        float g = d_gavec[b];
        float s = 0.f, q = 0.f;
        for (int k = threadIdx.x; k < Hn; k += blockDim.x) {
            float x = tok[Hn + k] + g * d_o2a[(size_t)b * Hn + k];
            sx[k] = x; s += x; q += x * x;
        }
        float2 rr = blkSum2(s, q);
        float mean = rr.x / Hn;
        float var = rr.y / Hn - mean * mean;
        float rstd = rsqrtf(var + 1e-5f);
        for (int k = threadIdx.x; k < Hn; k += blockDim.x)
            mx[Hn + k] = (sx[k] - mean) * rstd * lnw[k] + lnb[k];
    } else {
        float f = m1 ? 1.0f : 0.0f;
        for (int k = threadIdx.x; k < Hn; k += blockDim.x)
            mx[Hn + k] = tok[Hn + k] * f;
    }
    float f0 = m0 ? 1.f : 0.f, f2 = m2 ? 1.f : 0.f, f3 = m3 ? 1.f : 0.f;
    size_t ob = (size_t)b * 3 * Hn;
    for (int k = threadIdx.x; k < Hn; k += blockDim.x) {
        mx[k]           = d_onew[ob + k] * f0;
        mx[2 * Hn + k]  = d_onew[ob + Hn + k] * f2;
        mx[3 * Hn + k]  = d_onew[ob + 2 * Hn + k] * f3;
    }
}

// ---------------- rank product + weighted sum ----------------
__global__ void k_combine(const float* rank_w, const float* lmf_bias,
                          const float* __restrict__ factors) {
    int idx = blockIdx.x * 256 + threadIdx.x;
    int b = idx >> 10, h = idx & 1023;
    const unsigned char* mk = d_mask + b * 4;
    bool m0 = mk[0], m1 = mk[1], m2 = mk[2], m3 = mk[3];
    const float* zb = d_zbuf + (size_t)b * (Mn * Rn * Hn) + h;
    float acc = 0.f;
#pragma unroll
    for (int r = 0; r < Rn; r++) {
        float p = rank_w[r];
        if (m0) p *= zb[(0 * Rn + r) * Hn] + factors[((size_t)(0 * Rn + r) * 1025) * Hn + h];
        if (m1) p *= zb[(1 * Rn + r) * Hn] + factors[((size_t)(1 * Rn + r) * 1025) * Hn + h];
        if (m2) p *= zb[(2 * Rn + r) * Hn] + factors[((size_t)(2 * Rn + r) * 1025) * Hn + h];
        if (m3) p *= zb[(3 * Rn + r) * Hn] + factors[((size_t)(3 * Rn + r) * 1025) * Hn + h];
        acc += p;
    }
    d_fused[idx] = acc + lmf_bias[h];
}

// ---------------- row LayerNorms ----------------
__device__ __forceinline__ void rowln(const float* x, float* y, const float* w, const float* bb) {
    float s = 0.f, q = 0.f;
    for (int k = threadIdx.x; k < Hn; k += blockDim.x) { float v = x[k]; s += v; q += v * v; }
    float2 rr = blkSum2(s, q);
    float mean = rr.x / Hn;
    float var = rr.y / Hn - mean * mean;
    float rstd = rsqrtf(var + 1e-5f);
    for (int k = threadIdx.x; k < Hn; k += blockDim.x)
        y[k] = (x[k] - mean) * rstd * w[k] + bb[k];
}
__global__ void k_ln_fused(const float* w, const float* bb) {
    rowln(d_fused + (size_t)blockIdx.x * Hn, d_h1 + (size_t)blockIdx.x * Hn, w, bb);
}
__global__ void k_ln_out(const float* w, const float* bb, float* out) {
    rowln(d_h2 + (size_t)blockIdx.x * Hn, out + (size_t)blockIdx.x * Hn, w, bb);
}

// ---------------- launch ----------------
extern "C" void kernel_launch(void* const* d_in, const int* in_sizes, int n_in,
                              void* d_out, int out_size) {
    const float* tokens   = (const float*)d_in[0];
    const void*  maskraw  = d_in[1];
    const float* ln_go_w  = (const float*)d_in[2];
    const float* ln_go_b  = (const float*)d_in[3];
    const float* go_w1    = (const float*)d_in[4];
    const float* go_b1    = (const float*)d_in[5];
    const float* go_w2    = (const float*)d_in[6];
    const float* go_b2    = (const float*)d_in[7];
    const float* ln_ga_w  = (const float*)d_in[8];
    const float* ln_ga_b  = (const float*)d_in[9];
    const float* ga_w1    = (const float*)d_in[10];
    const float* ga_b1    = (const float*)d_in[11];
    const float* ga_w2    = (const float*)d_in[12];
    const float* ga_b2    = (const float*)d_in[13];
    const float* a2o_w    = (const float*)d_in[14];
    const float* o2a_w    = (const float*)d_in[15];
    const float* ln_o_w   = (const float*)d_in[16];
    const float* ln_o_b   = (const float*)d_in[17];
    const float* ln_a_w   = (const float*)d_in[18];
    const float* ln_a_b   = (const float*)d_in[19];
    const float* factors  = (const float*)d_in[20];
    const float* rank_w   = (const float*)d_in[21];
    const float* lmf_bias = (const float*)d_in[22];
    const float* out_ln1w = (const float*)d_in[23];
    const float* out_ln1b = (const float*)d_in[24];
    const float* out_w    = (const float*)d_in[25];
    const float* out_b    = (const float*)d_in[26];
    const float* out_ln2w = (const float*)d_in[27];
    const float* out_ln2b = (const float*)d_in[28];
    float* out = (float*)d_out;

    static int smem_set = 0;
    if (!smem_set) {
        cudaFuncSetAttribute(k_gemm_z_mma, cudaFuncAttributeMaxDynamicSharedMemorySize, ZSM_TOTAL);
        smem_set = 1;
    }

    k_mask_norm<<<1, 256>>>(maskraw);
    k_prep_factors<<<dim3(32, 32, Mn * Rn), dim3(32, 8)>>>(factors);
    k_gemm_a2o<<<dim3(Hn / 128, Bn / 128), 256>>>(tokens, a2o_w);
    k_feat_go<<<3 * Bn, 256>>>(tokens, ln_go_w, ln_go_b);
    k_gemm_hidgo<<<dim3(MIDn / 128, 3 * Bn / 128), 256>>>(go_w1, go_b1);
    k_gate_go<<<3 * Bn, 256>>>(go_w2, go_b2);
    k_others_new<<<3 * Bn, 256>>>(tokens, ln_o_w, ln_o_b);
    k_omean<<<Bn * Hn / 256, 256>>>();
    k_feat_ga<<<Bn, 256>>>(tokens, ln_ga_w, ln_ga_b);
    k_gemm_hidga<<<dim3(MIDn / 128, Bn / 128), 256>>>(ga_w1, ga_b1);
    k_gate_ga<<<Bn, 256>>>(ga_w2, ga_b2);
    k_gemm_o2a<<<dim3(Hn / 128, Bn / 128), 256>>>(o2a_w);
    k_mixed<<<Bn, 256>>>(tokens, ln_a_w, ln_a_b);
    k_prep_mixed<<<(Bn * Mn * Hn) / 256, 256>>>();
    k_gemm_z_mma<<<dim3(Hn / 128, Bn / 128, Mn * Rn), 256, ZSM_TOTAL>>>();
    k_combine<<<Bn * Hn / 256, 256>>>(rank_w, lmf_bias, factors);
    k_ln_fused<<<Bn, 256>>>(out_ln1w, out_ln1b);
    k_gemm_out<<<dim3(Hn / 128, Bn / 128), 256>>>(out_w, out_b);
    k_ln_out<<<Bn, 256>>>(out_ln2w, out_ln2b, out);
}

// round 4
// speedup vs baseline: 3.3237x; 1.8343x over previous
#include <cuda_runtime.h>
#include <cuda_bf16.h>
#include <math.h>
#include <cstdint>

#define Bn   4096
#define Mn   4
#define Hn   1024
#define Rn   10
#define MIDn 512
#define D3n  3072

// ---------------- scratch (__device__ globals: alloc-free) ----------------
__device__ float d_featgo[3 * Bn * D3n];
__device__ float d_hidgo[3 * Bn * MIDn];
__device__ float d_ggo[3 * Bn];
__device__ float d_a2o[Bn * Hn];
__device__ float d_onew[Bn * 3 * Hn];
__device__ float d_omean[Bn * Hn];
__device__ float d_featga[Bn * D3n];
__device__ float d_hidga[Bn * MIDn];
__device__ float d_gavec[Bn];
__device__ float d_o2a[Bn * Hn];
__device__ float d_mixed[Bn * Mn * Hn];
__device__ float d_zbuf[167772160];             // B*M*R*H fp32
__device__ float d_fused[Bn * Hn];
__device__ float d_h1[Bn * Hn];
__device__ float d_h2[Bn * Hn];
__device__ unsigned char d_mask[Bn * Mn];
__device__ int d_cidx[Mn * Bn];                 // compacted valid-b lists per m
__device__ int d_ccnt[Mn];
// bf16-split operands for the LMF GEMM
__device__ __nv_bfloat16 d_ahi[Mn * Bn * Hn];      // [m][b][h]
__device__ __nv_bfloat16 d_alo[Mn * Bn * Hn];
__device__ __nv_bfloat16 d_fhi[Mn * Rn * Hn * Hn]; // [mr][h][d] (K-contiguous)
__device__ __nv_bfloat16 d_flo[Mn * Rn * Hn * Hn];

// ---------------- generic helpers ----------------
__device__ __forceinline__ float gelu_f(float x) {
    return 0.5f * x * (1.0f + erff(x * 0.70710678118654752f));
}
__device__ __forceinline__ float2 blkSum2(float a, float b) {
    __shared__ float sa[32], sb[32];
    __shared__ float ra, rb;
    int lane = threadIdx.x & 31, w = threadIdx.x >> 5;
#pragma unroll
    for (int o = 16; o > 0; o >>= 1) {
        a += __shfl_xor_sync(0xffffffffu, a, o);
        b += __shfl_xor_sync(0xffffffffu, b, o);
    }
    if (lane == 0) { sa[w] = a; sb[w] = b; }
    __syncthreads();
    if (threadIdx.x == 0) {
        float x = 0.f, y = 0.f;
        int nw = blockDim.x >> 5;
        for (int i = 0; i < nw; i++) { x += sa[i]; y += sb[i]; }
        ra = x; rb = y;
    }
    __syncthreads();
    return make_float2(ra, rb);
}

// ---------------- mma.sync helpers ----------------
__device__ __forceinline__ uint32_t smem_u32(const void* p) {
    uint32_t a;
    asm("{ .reg .u64 t; cvta.to.shared.u64 t, %1; cvt.u32.u64 %0, t; }" : "=r"(a) : "l"(p));
    return a;
}
__device__ __forceinline__ void ldm_x4(uint32_t& r0, uint32_t& r1, uint32_t& r2, uint32_t& r3,
                                       uint32_t addr) {
    asm volatile("ldmatrix.sync.aligned.m8n8.x4.shared.b16 {%0,%1,%2,%3}, [%4];"
                 : "=r"(r0), "=r"(r1), "=r"(r2), "=r"(r3) : "r"(addr));
}
__device__ __forceinline__ void mma_bf16(float* c, const uint32_t* a, const uint32_t* b) {
    asm volatile("mma.sync.aligned.m16n8k16.row.col.f32.bf16.bf16.f32 "
                 "{%0,%1,%2,%3}, {%4,%5,%6,%7}, {%8,%9}, {%0,%1,%2,%3};"
                 : "+f"(c[0]), "+f"(c[1]), "+f"(c[2]), "+f"(c[3])
                 : "r"(a[0]), "r"(a[1]), "r"(a[2]), "r"(a[3]), "r"(b[0]), "r"(b[1]));
}
__device__ __forceinline__ void cp16(uint32_t dst, const void* src) {
    asm volatile("cp.async.cg.shared.global [%0], [%1], 16;" :: "r"(dst), "l"(src));
}
#define CP_COMMIT() asm volatile("cp.async.commit_group;" ::: "memory")
#define CP_WAIT(n)  asm volatile("cp.async.wait_group %0;" :: "n"(n) : "memory")

__device__ __forceinline__ uint32_t pack_hi_lo(float x, float y, uint32_t& lo) {
    __nv_bfloat16 hx = __float2bfloat16(x);
    __nv_bfloat16 hy = __float2bfloat16(y);
    float lxf = x - __bfloat162float(hx);
    float lyf = y - __bfloat162float(hy);
    __nv_bfloat162 hv = __halves2bfloat162(hx, hy);
    __nv_bfloat162 lv = __halves2bfloat162(__float2bfloat16(lxf), __float2bfloat16(lyf));
    lo = *reinterpret_cast<uint32_t*>(&lv);
    return *reinterpret_cast<uint32_t*>(&hv);
}

// ---------------- mask dtype sniffer ----------------
__global__ void k_mask_norm(const void* p) {
    __shared__ int ok32, okf;
    if (threadIdx.x == 0) { ok32 = 1; okf = 1; }
    __syncthreads();
    const unsigned char* pb = (const unsigned char*)p;
    const int* pi = (const int*)p;
    const float* pf = (const float*)p;
    for (int i = threadIdx.x; i < 4096; i += blockDim.x) {
        int v = pi[i];
        if (v != 0 && v != 1) ok32 = 0;
        float f = pf[i];
        if (f != 0.0f && f != 1.0f) okf = 0;
    }
    __syncthreads();
    for (int i = threadIdx.x; i < Bn * Mn; i += blockDim.x) {
        unsigned char m;
        if (ok32)      m = (pi[i] != 0);
        else if (okf)  m = (pf[i] != 0.0f);
        else           m = (pb[i] != 0);
        d_mask[i] = m;
    }
}

// ---------------- order-preserving compaction of valid b rows per m ----------------
__global__ void __launch_bounds__(1024) k_compact() {
    int m = blockIdx.x;
    __shared__ int warp_off[32];
    __shared__ int chunk_base;
    if (threadIdx.x == 0) chunk_base = 0;
    __syncthreads();
    int lane = threadIdx.x & 31, w = threadIdx.x >> 5;
    for (int c = 0; c < Bn; c += 1024) {
        int i = c + threadIdx.x;
        int v = d_mask[i * Mn + m] ? 1 : 0;
        unsigned bal = __ballot_sync(0xffffffffu, v);
        int pre = __popc(bal & ((1u << lane) - 1u));
        if (lane == 31) warp_off[w] = __popc(bal);
        __syncthreads();
        if (threadIdx.x < 32) {
            int val = warp_off[threadIdx.x];
#pragma unroll
            for (int o = 1; o < 32; o <<= 1) {
                int t = __shfl_up_sync(0xffffffffu, val, o);
                if ((int)threadIdx.x >= o) val += t;
            }
            warp_off[threadIdx.x] = val;          // inclusive
        }
        __syncthreads();
        int base = chunk_base + (w ? warp_off[w - 1] : 0) + pre;
        if (v) d_cidx[m * Bn + base] = i;
        __syncthreads();
        if (threadIdx.x == 0) chunk_base += warp_off[31];
        __syncthreads();
    }
    if (threadIdx.x == 0) d_ccnt[m] = chunk_base;
}

// ---------------- generic fp32 -> bf16-split mma GEMM ----------------
// C[m][n] = act( sum_k A[m][k]*B[n][k] + bias[n] ); block 128x128, warp 64x32.
#define GPAD   40
#define GBUF   (128 * GPAD * 2)        // 10240 B
#define GSTAGE (4 * GBUF)              // Ah,Al,Bh,Bl
#define GSM_TOTAL (2 * GSTAGE)         // 81920 B

__device__ __forceinline__ void gemm_sp_body(
    const float* __restrict__ A, int lda,
    const float* __restrict__ B, int ldb,
    float* __restrict__ C, int ldc,
    const float* __restrict__ bias, int K, int act)
{
    extern __shared__ char gsm[];
    const uint32_t sbase = smem_u32(gsm);
    const int tid = threadIdx.x;
    const int wid = tid >> 5, lane = tid & 31;
    const int n0 = blockIdx.x * 128, m0 = blockIdx.y * 128;

    const int lrow = tid >> 1, lseg = tid & 1;
    const float* Aref = A + (size_t)(m0 + lrow) * lda + lseg * 16;
    const float* Bref = B + (size_t)(n0 + lrow) * ldb + lseg * 16;

    float4 ra[4], rb[4];
    auto gload = [&](int k0) {
#pragma unroll
        for (int j = 0; j < 4; j++) {
            ra[j] = *(const float4*)(Aref + k0 + j * 4);
            rb[j] = *(const float4*)(Bref + k0 + j * 4);
        }
    };
    auto sstore = [&](int st) {
        char* p = gsm + st * GSTAGE + lrow * (GPAD * 2) + lseg * 32;
#pragma unroll
        for (int j = 0; j < 4; j++) {
            uint32_t l0, l1;
            uint32_t h0 = pack_hi_lo(ra[j].x, ra[j].y, l0);
            uint32_t h1 = pack_hi_lo(ra[j].z, ra[j].w, l1);
            *(uint2*)(p + 0 * GBUF + j * 8) = make_uint2(h0, h1);
            *(uint2*)(p + 1 * GBUF + j * 8) = make_uint2(l0, l1);
            h0 = pack_hi_lo(rb[j].x, rb[j].y, l0);
            h1 = pack_hi_lo(rb[j].z, rb[j].w, l1);
            *(uint2*)(p + 2 * GBUF + j * 8) = make_uint2(h0, h1);
            *(uint2*)(p + 3 * GBUF + j * 8) = make_uint2(l0, l1);
        }
    };

    float acc[4][4][4];
#pragma unroll
    for (int i = 0; i < 4; i++)
#pragma unroll
        for (int j = 0; j < 4; j++)
#pragma unroll
            for (int c = 0; c < 4; c++) acc[i][j][c] = 0.0f;

    const int wm0 = (wid >> 2) * 64;
    const int wn0 = (wid & 3) * 32;
    const int a_r = lane & 15;
    const int a_c8 = (lane >> 4) << 3;
    const int b_r = (lane & 7) + ((lane >> 4) << 3);
    const int b_c8 = ((lane >> 3) & 1) << 3;

    gload(0);
    const int NIT = K / 32;
    for (int it = 0; it < NIT; it++) {
        const int st = it & 1;
        sstore(st);
        __syncthreads();
        if (it + 1 < NIT) gload((it + 1) * 32);

        const uint32_t sAh = sbase + st * GSTAGE + 0 * GBUF;
        const uint32_t sAl = sbase + st * GSTAGE + 1 * GBUF;
        const uint32_t sBh = sbase + st * GSTAGE + 2 * GBUF;
        const uint32_t sBl = sbase + st * GSTAGE + 3 * GBUF;
#pragma unroll
        for (int ks = 0; ks < 2; ks++) {
            const int kb = ks * 16;
            uint32_t aH[4][4], aL[4][4], bH[4][2], bL[4][2];
#pragma unroll
            for (int mi = 0; mi < 4; mi++) {
                uint32_t off = (uint32_t)(wm0 + mi * 16 + a_r) * (GPAD * 2) + (kb + a_c8) * 2;
                ldm_x4(aH[mi][0], aH[mi][1], aH[mi][2], aH[mi][3], sAh + off);
                ldm_x4(aL[mi][0], aL[mi][1], aL[mi][2], aL[mi][3], sAl + off);
            }
#pragma unroll
            for (int p2 = 0; p2 < 2; p2++) {
                uint32_t off = (uint32_t)(wn0 + p2 * 16 + b_r) * (GPAD * 2) + (kb + b_c8) * 2;
                ldm_x4(bH[2 * p2][0], bH[2 * p2][1], bH[2 * p2 + 1][0], bH[2 * p2 + 1][1], sBh + off);
                ldm_x4(bL[2 * p2][0], bL[2 * p2][1], bL[2 * p2 + 1][0], bL[2 * p2 + 1][1], sBl + off);
            }
#pragma unroll
            for (int mi = 0; mi < 4; mi++)
#pragma unroll
                for (int ni = 0; ni < 4; ni++) {
                    mma_bf16(acc[mi][ni], aH[mi], bH[ni]);
                    mma_bf16(acc[mi][ni], aH[mi], bL[ni]);
                    mma_bf16(acc[mi][ni], aL[mi], bH[ni]);
                }
        }
    }

#pragma unroll
    for (int mi = 0; mi < 4; mi++) {
        int r0 = m0 + wm0 + mi * 16 + (lane >> 2);
        float* d0 = C + (size_t)r0 * ldc;
        float* d1 = C + (size_t)(r0 + 8) * ldc;
#pragma unroll
        for (int ni = 0; ni < 4; ni++) {
            int cc = n0 + wn0 + ni * 8 + (lane & 3) * 2;
            float b0v = bias ? bias[cc] : 0.f;
            float b1v = bias ? bias[cc + 1] : 0.f;
            float v0 = acc[mi][ni][0] + b0v, v1 = acc[mi][ni][1] + b1v;
            float v2 = acc[mi][ni][2] + b0v, v3 = acc[mi][ni][3] + b1v;
            if (act) { v0 = gelu_f(v0); v1 = gelu_f(v1); v2 = gelu_f(v2); v3 = gelu_f(v3); }
            *(float2*)(d0 + cc) = make_float2(v0, v1);
            *(float2*)(d1 + cc) = make_float2(v2, v3);
        }
    }
}

__global__ void __launch_bounds__(256) k_sp_hidgo(const float* w1, const float* b1) {
    gemm_sp_body(d_featgo, D3n, w1, D3n, d_hidgo, MIDn, b1, D3n, 1);
}
__global__ void __launch_bounds__(256) k_sp_hidga(const float* w1, const float* b1) {
    gemm_sp_body(d_featga, D3n, w1, D3n, d_hidga, MIDn, b1, D3n, 1);
}
__global__ void __launch_bounds__(256) k_sp_a2o(const float* tokens, const float* w) {
    gemm_sp_body(tokens + Hn, Mn * Hn, w, Hn, d_a2o, Hn, (const float*)0, Hn, 0);
}
__global__ void __launch_bounds__(256) k_sp_o2a(const float* w) {
    gemm_sp_body(d_omean, Hn, w, Hn, d_o2a, Hn, (const float*)0, Hn, 0);
}
__global__ void __launch_bounds__(256) k_sp_out(const float* w, const float* bb) {
    gemm_sp_body(d_h1, Hn, w, Hn, d_h2, Hn, bb, Hn, 1);
}

// ---------------- bf16-split prep ----------------
__global__ void k_prep_mixed() {
    int idx = blockIdx.x * 256 + threadIdx.x;
    int h = idx & 1023;
    int bm = idx >> 10;
    int b = bm >> 2, m = bm & 3;
    float x = d_mixed[idx];
    __nv_bfloat16 hi = __float2bfloat16(x);
    float lo = x - __bfloat162float(hi);
    size_t o = ((size_t)m * Bn + b) * Hn + h;
    d_ahi[o] = hi;
    d_alo[o] = __float2bfloat16(lo);
}

__global__ void __launch_bounds__(256) k_prep_factors(const float* __restrict__ f) {
    __shared__ float t[32][33];
    int mr = blockIdx.z;
    int d0 = blockIdx.x * 32, h0 = blockIdx.y * 32;
    int tx = threadIdx.x, ty = threadIdx.y;
#pragma unroll
    for (int i = ty; i < 32; i += 8)
        t[i][tx] = f[((size_t)mr * 1025 + 1 + d0 + i) * Hn + h0 + tx];
    __syncthreads();
#pragma unroll
    for (int i = ty; i < 32; i += 8) {
        float x = t[tx][i];
        __nv_bfloat16 hi = __float2bfloat16(x);
        float lo = x - __bfloat162float(hi);
        size_t o = ((size_t)mr * Hn + h0 + i) * Hn + d0 + tx;
        d_fhi[o] = hi;
        d_flo[o] = __float2bfloat16(lo);
    }
}

// ---------------- LMF GEMM (mask-compacted rows) ----------------
#define ZKC   32
#define ZPAD  40
#define ZBUFB (128 * ZPAD * 2)
#define ZSTAGE (4 * ZBUFB)
#define ZSM_TOTAL (2 * ZSTAGE)

__global__ void __launch_bounds__(256) k_gemm_z_mma() {
    extern __shared__ char zsm[];
    const uint32_t sbase = smem_u32(zsm);
    const int tid = threadIdx.x;
    const int wid = tid >> 5, lane = tid & 31;
    const int h0 = blockIdx.x * 128;
    const int b0 = blockIdx.y * 128;
    const int mr = blockIdx.z;
    const int m = mr / Rn;
    const int cnt = d_ccnt[m];
    if (b0 >= cnt) return;

    const int lrow = tid >> 1;
    const int lseg = (tid & 1) * 2;

    int grow = b0 + lrow;
    int gidx = d_cidx[m * Bn + (grow < cnt ? grow : cnt - 1)];

    const __nv_bfloat16* rowp[4];
    rowp[0] = d_ahi + ((size_t)m * Bn + gidx) * Hn;
    rowp[1] = d_alo + ((size_t)m * Bn + gidx) * Hn;
    rowp[2] = d_fhi + ((size_t)mr * Hn + h0 + lrow) * Hn;
    rowp[3] = d_flo + ((size_t)mr * Hn + h0 + lrow) * Hn;

    auto load_stage = [&](int st, int k0) {
#pragma unroll
        for (int bsel = 0; bsel < 4; bsel++) {
            const __nv_bfloat16* src = rowp[bsel] + k0 + lseg * 8;
            uint32_t dst = sbase + st * ZSTAGE + bsel * ZBUFB + lrow * (ZPAD * 2) + lseg * 16;
            cp16(dst, src);
            cp16(dst + 16, src + 8);
        }
    };

    float acc[4][4][4];
#pragma unroll
    for (int i = 0; i < 4; i++)
#pragma unroll
        for (int j = 0; j < 4; j++)
#pragma unroll
            for (int c = 0; c < 4; c++) acc[i][j][c] = 0.0f;

    const int wm0 = (wid >> 2) * 64;
    const int wn0 = (wid & 3) * 32;
    const int a_r = lane & 15;
    const int a_c8 = (lane >> 4) << 3;
    const int b_r = (lane & 7) + ((lane >> 4) << 3);
    const int b_c8 = ((lane >> 3) & 1) << 3;

    load_stage(0, 0);
    CP_COMMIT();

    const int NIT = Hn / ZKC;
    for (int it = 0; it < NIT; it++) {
        const int st = it & 1;
        if (it + 1 < NIT) {
            load_stage(st ^ 1, (it + 1) * ZKC);
            CP_COMMIT();
            CP_WAIT(1);
        } else {
            CP_WAIT(0);
        }
        __syncthreads();

        const uint32_t sAh = sbase + st * ZSTAGE + 0 * ZBUFB;
        const uint32_t sAl = sbase + st * ZSTAGE + 1 * ZBUFB;
        const uint32_t sBh = sbase + st * ZSTAGE + 2 * ZBUFB;
        const uint32_t sBl = sbase + st * ZSTAGE + 3 * ZBUFB;

#pragma unroll
        for (int ks = 0; ks < 2; ks++) {
            const int kb = ks * 16;
            uint32_t aH[4][4], aL[4][4], bH[4][2], bL[4][2];
#pragma unroll
            for (int mi = 0; mi < 4; mi++) {
                uint32_t off = (uint32_t)(wm0 + mi * 16 + a_r) * (ZPAD * 2) + (kb + a_c8) * 2;
                ldm_x4(aH[mi][0], aH[mi][1], aH[mi][2], aH[mi][3], sAh + off);
                ldm_x4(aL[mi][0], aL[mi][1], aL[mi][2], aL[mi][3], sAl + off);
            }
#pragma unroll
            for (int p = 0; p < 2; p++) {
                uint32_t off = (uint32_t)(wn0 + p * 16 + b_r) * (ZPAD * 2) + (kb + b_c8) * 2;
                ldm_x4(bH[2 * p][0], bH[2 * p][1], bH[2 * p + 1][0], bH[2 * p + 1][1], sBh + off);
                ldm_x4(bL[2 * p][0], bL[2 * p][1], bL[2 * p + 1][0], bL[2 * p + 1][1], sBl + off);
            }
#pragma unroll
            for (int mi = 0; mi < 4; mi++)
#pragma unroll
                for (int ni = 0; ni < 4; ni++) {
                    mma_bf16(acc[mi][ni], aH[mi], bH[ni]);
                    mma_bf16(acc[mi][ni], aH[mi], bL[ni]);
                    mma_bf16(acc[mi][ni], aL[mi], bH[ni]);
                }
        }
        __syncthreads();
    }

    // epilogue: scatter z rows through the compaction index
#pragma unroll
    for (int mi = 0; mi < 4; mi++) {
        int r0 = b0 + wm0 + mi * 16 + (lane >> 2);
        int r1 = r0 + 8;
        if (r0 < cnt) {
            int br = d_cidx[m * Bn + r0];
            float* dd = d_zbuf + ((size_t)br * (Mn * Rn) + mr) * Hn + h0;
#pragma unroll
            for (int ni = 0; ni < 4; ni++) {
                int cc = wn0 + ni * 8 + (lane & 3) * 2;
                *(float2*)(dd + cc) = make_float2(acc[mi][ni][0], acc[mi][ni][1]);
            }
        }
        if (r1 < cnt) {
            int br = d_cidx[m * Bn + r1];
            float* dd = d_zbuf + ((size_t)br * (Mn * Rn) + mr) * Hn + h0;
#pragma unroll
            for (int ni = 0; ni < 4; ni++) {
                int cc = wn0 + ni * 8 + (lane & 3) * 2;
                *(float2*)(dd + cc) = make_float2(acc[mi][ni][2], acc[mi][ni][3]);
            }
        }
    }
}

// ---------------- feat builders ----------------
__global__ void k_feat_go(const float* tokens, const float* lnw, const float* lnb) {
    int row = blockIdx.x;
    int b = row / 3, j = row - 3 * b;
    int oj = (j == 0) ? 0 : (j + 1);
    const float* tok = tokens + (size_t)b * Mn * Hn;
    float mj = d_mask[b * Mn + oj] ? 1.0f : 0.0f;
    __shared__ float sf[D3n];
    float s = 0.f, q = 0.f;
    for (int k = threadIdx.x; k < Hn; k += blockDim.x) {
        float t = tok[oj * Hn + k] * mj;
        float sv = tok[Hn + k];
        float dv = fabsf(t - sv);
        sf[k] = t; sf[Hn + k] = sv; sf[2 * Hn + k] = dv;
        s += t + sv + dv; q += t * t + sv * sv + dv * dv;
    }
    float2 rr = blkSum2(s, q);
    float mean = rr.x / D3n;
    float var = rr.y / D3n - mean * mean;
    float rstd = rsqrtf(var + 1e-5f);
    float* o = d_featgo + (size_t)row * D3n;
    for (int k = threadIdx.x; k < D3n; k += blockDim.x)
        o[k] = (sf[k] - mean) * rstd * lnw[k] + lnb[k];
}

__global__ void k_feat_ga(const float* tokens, const float* lnw, const float* lnb) {
    int b = blockIdx.x;
    const float* tok = tokens + (size_t)b * Mn * Hn;
    __shared__ float sf[D3n];
    float s = 0.f, q = 0.f;
    for (int k = threadIdx.x; k < Hn; k += blockDim.x) {
        float t = tok[Hn + k];
        float sv = d_omean[(size_t)b * Hn + k];
        float dv = fabsf(t - sv);
        sf[k] = t; sf[Hn + k] = sv; sf[2 * Hn + k] = dv;
        s += t + sv + dv; q += t * t + sv * sv + dv * dv;
    }
    float2 rr = blkSum2(s, q);
    float mean = rr.x / D3n;
    float var = rr.y / D3n - mean * mean;
    float rstd = rsqrtf(var + 1e-5f);
    float* o = d_featga + (size_t)b * D3n;
    for (int k = threadIdx.x; k < D3n; k += blockDim.x)
        o[k] = (sf[k] - mean) * rstd * lnw[k] + lnb[k];
}

// ---------------- gate tails ----------------
__global__ void k_gate_go(const float* w2, const float* b2) {
    int row = blockIdx.x;
    const float* hr = d_hidgo + (size_t)row * MIDn;
    float v = 0.f;
    for (int k = threadIdx.x; k < MIDn; k += blockDim.x) v += hr[k] * w2[k];
    float2 rr = blkSum2(v, 0.f);
    if (threadIdx.x == 0) d_ggo[row] = 1.0f / (1.0f + expf(-(rr.x + b2[0])));
}
__global__ void k_gate_ga(const float* w2, const float* b2) {
    int row = blockIdx.x;
    const float* hr = d_hidga + (size_t)row * MIDn;
    float v = 0.f;
    for (int k = threadIdx.x; k < MIDn; k += blockDim.x) v += hr[k] * w2[k];
    float2 rr = blkSum2(v, 0.f);
    if (threadIdx.x == 0) d_gavec[row] = 1.0f / (1.0f + expf(-(rr.x + b2[0])));
}

// ---------------- others_new ----------------
__global__ void k_others_new(const float* tokens, const float* lnw, const float* lnb) {
    int row = blockIdx.x;
    int b = row / 3, j = row - 3 * b;
    int oj = (j == 0) ? 0 : (j + 1);
    const float* tok = tokens + (size_t)b * Mn * Hn;
    int moj = d_mask[b * Mn + oj], ma = d_mask[b * Mn + 1];
    float* o = d_onew + (size_t)row * Hn;
    if (moj && ma) {
        __shared__ float sx[Hn];
        float g = d_ggo[row];
        float s = 0.f, q = 0.f;
        for (int k = threadIdx.x; k < Hn; k += blockDim.x) {
            float x = tok[oj * Hn + k] + g * d_a2o[(size_t)b * Hn + k];
            sx[k] = x; s += x; q += x * x;
        }
        float2 rr = blkSum2(s, q);
        float mean = rr.x / Hn;
        float var = rr.y / Hn - mean * mean;
        float rstd = rsqrtf(var + 1e-5f);
        for (int k = threadIdx.x; k < Hn; k += blockDim.x)
            o[k] = (sx[k] - mean) * rstd * lnw[k] + lnb[k];
    } else {
        float mf = moj ? 1.0f : 0.0f;
        for (int k = threadIdx.x; k < Hn; k += blockDim.x)
            o[k] = tok[oj * Hn + k] * mf;
    }
}

__global__ void k_omean() {
    int idx = blockIdx.x * 256 + threadIdx.x;
    int b = idx >> 10, h = idx & 1023;
    float m0 = d_mask[b * 4 + 0] ? 1.f : 0.f;
    float m2 = d_mask[b * 4 + 2] ? 1.f : 0.f;
    float m3 = d_mask[b * 4 + 3] ? 1.f : 0.f;
    float denom = fmaxf(1.0f, m0 + m2 + m3);
    size_t base = (size_t)b * 3 * Hn;
    float sum = d_onew[base + h] + d_onew[base + Hn + h] + d_onew[base + 2 * Hn + h];
    d_omean[idx] = sum / denom;
}

// ---------------- mixed assembly ----------------
__global__ void k_mixed(const float* tokens, const float* lnw, const float* lnb) {
    int b = blockIdx.x;
    const float* tok = tokens + (size_t)b * Mn * Hn;
    int m0 = d_mask[b * 4], m1 = d_mask[b * 4 + 1], m2 = d_mask[b * 4 + 2], m3 = d_mask[b * 4 + 3];
    float* mx = d_mixed + (size_t)b * Mn * Hn;
    int aum = m1 && (m0 || m2 || m3);
    if (aum) {
        __shared__ float sx[Hn];
        float g = d_gavec[b];
        float s = 0.f, q = 0.f;
        for (int k = threadIdx.x; k < Hn; k += blockDim.x) {
            float x = tok[Hn + k] + g * d_o2a[(size_t)b * Hn + k];
            sx[k] = x; s += x; q += x * x;
        }
        float2 rr = blkSum2(s, q);
        float mean = rr.x / Hn;
        float var = rr.y / Hn - mean * mean;
        float rstd = rsqrtf(var + 1e-5f);
        for (int k = threadIdx.x; k < Hn; k += blockDim.x)
            mx[Hn + k] = (sx[k] - mean) * rstd * lnw[k] + lnb[k];
    } else {
        float f = m1 ? 1.0f : 0.0f;
        for (int k = threadIdx.x; k < Hn; k += blockDim.x)
            mx[Hn + k] = tok[Hn + k] * f;
    }
    float f0 = m0 ? 1.f : 0.f, f2 = m2 ? 1.f : 0.f, f3 = m3 ? 1.f : 0.f;
    size_t ob = (size_t)b * 3 * Hn;
    for (int k = threadIdx.x; k < Hn; k += blockDim.x) {
        mx[k]           = d_onew[ob + k] * f0;
        mx[2 * Hn + k]  = d_onew[ob + Hn + k] * f2;
        mx[3 * Hn + k]  = d_onew[ob + 2 * Hn + k] * f3;
    }
}

// ---------------- rank product + weighted sum ----------------
__global__ void k_combine(const float* rank_w, const float* lmf_bias,
                          const float* __restrict__ factors) {
    int idx = blockIdx.x * 256 + threadIdx.x;
    int b = idx >> 10, h = idx & 1023;
    const unsigned char* mk = d_mask + b * 4;
    bool m0 = mk[0], m1 = mk[1], m2 = mk[2], m3 = mk[3];
    const float* zb = d_zbuf + (size_t)b * (Mn * Rn * Hn) + h;
    float acc = 0.f;
#pragma unroll
    for (int r = 0; r < Rn; r++) {
        float p = rank_w[r];
        if (m0) p *= zb[(0 * Rn + r) * Hn] + factors[((size_t)(0 * Rn + r) * 1025) * Hn + h];
        if (m1) p *= zb[(1 * Rn + r) * Hn] + factors[((size_t)(1 * Rn + r) * 1025) * Hn + h];
        if (m2) p *= zb[(2 * Rn + r) * Hn] + factors[((size_t)(2 * Rn + r) * 1025) * Hn + h];
        if (m3) p *= zb[(3 * Rn + r) * Hn] + factors[((size_t)(3 * Rn + r) * 1025) * Hn + h];
        acc += p;
    }
    d_fused[idx] = acc + lmf_bias[h];
}

// ---------------- row LayerNorms ----------------
__device__ __forceinline__ void rowln(const float* x, float* y, const float* w, const float* bb) {
    float s = 0.f, q = 0.f;
    for (int k = threadIdx.x; k < Hn; k += blockDim.x) { float v = x[k]; s += v; q += v * v; }
    float2 rr = blkSum2(s, q);
    float mean = rr.x / Hn;
    float var = rr.y / Hn - mean * mean;
    float rstd = rsqrtf(var + 1e-5f);
    for (int k = threadIdx.x; k < Hn; k += blockDim.x)
        y[k] = (x[k] - mean) * rstd * w[k] + bb[k];
}
__global__ void k_ln_fused(const float* w, const float* bb) {
    rowln(d_fused + (size_t)blockIdx.x * Hn, d_h1 + (size_t)blockIdx.x * Hn, w, bb);
}
__global__ void k_ln_out(const float* w, const float* bb, float* out) {
    rowln(d_h2 + (size_t)blockIdx.x * Hn, out + (size_t)blockIdx.x * Hn, w, bb);
}

// ---------------- launch ----------------
extern "C" void kernel_launch(void* const* d_in, const int* in_sizes, int n_in,
                              void* d_out, int out_size) {
    const float* tokens   = (const float*)d_in[0];
    const void*  maskraw  = d_in[1];
    const float* ln_go_w  = (const float*)d_in[2];
    const float* ln_go_b  = (const float*)d_in[3];
    const float* go_w1    = (const float*)d_in[4];
    const float* go_b1    = (const float*)d_in[5];
    const float* go_w2    = (const float*)d_in[6];
    const float* go_b2    = (const float*)d_in[7];
    const float* ln_ga_w  = (const float*)d_in[8];
    const float* ln_ga_b  = (const float*)d_in[9];
    const float* ga_w1    = (const float*)d_in[10];
    const float* ga_b1    = (const float*)d_in[11];
    const float* ga_w2    = (const float*)d_in[12];
    const float* ga_b2    = (const float*)d_in[13];
    const float* a2o_w    = (const float*)d_in[14];
    const float* o2a_w    = (const float*)d_in[15];
    const float* ln_o_w   = (const float*)d_in[16];
    const float* ln_o_b   = (const float*)d_in[17];
    const float* ln_a_w   = (const float*)d_in[18];
    const float* ln_a_b   = (const float*)d_in[19];
    const float* factors  = (const float*)d_in[20];
    const float* rank_w   = (const float*)d_in[21];
    const float* lmf_bias = (const float*)d_in[22];
    const float* out_ln1w = (const float*)d_in[23];
    const float* out_ln1b = (const float*)d_in[24];
    const float* out_w    = (const float*)d_in[25];
    const float* out_b    = (const float*)d_in[26];
    const float* out_ln2w = (const float*)d_in[27];
    const float* out_ln2b = (const float*)d_in[28];
    float* out = (float*)d_out;

    static int smem_set = 0;
    if (!smem_set) {
        cudaFuncSetAttribute(k_gemm_z_mma, cudaFuncAttributeMaxDynamicSharedMemorySize, ZSM_TOTAL);
        cudaFuncSetAttribute(k_sp_hidgo, cudaFuncAttributeMaxDynamicSharedMemorySize, GSM_TOTAL);
        cudaFuncSetAttribute(k_sp_hidga, cudaFuncAttributeMaxDynamicSharedMemorySize, GSM_TOTAL);
        cudaFuncSetAttribute(k_sp_a2o,   cudaFuncAttributeMaxDynamicSharedMemorySize, GSM_TOTAL);
        cudaFuncSetAttribute(k_sp_o2a,   cudaFuncAttributeMaxDynamicSharedMemorySize, GSM_TOTAL);
        cudaFuncSetAttribute(k_sp_out,   cudaFuncAttributeMaxDynamicSharedMemorySize, GSM_TOTAL);
        smem_set = 1;
    }

    k_mask_norm<<<1, 256>>>(maskraw);
    k_compact<<<Mn, 1024>>>();
    k_prep_factors<<<dim3(32, 32, Mn * Rn), dim3(32, 8)>>>(factors);
    k_sp_a2o<<<dim3(Hn / 128, Bn / 128), 256, GSM_TOTAL>>>(tokens, a2o_w);
    k_feat_go<<<3 * Bn, 256>>>(tokens, ln_go_w, ln_go_b);
    k_sp_hidgo<<<dim3(MIDn / 128, 3 * Bn / 128), 256, GSM_TOTAL>>>(go_w1, go_b1);
    k_gate_go<<<3 * Bn, 256>>>(go_w2, go_b2);
    k_others_new<<<3 * Bn, 256>>>(tokens, ln_o_w, ln_o_b);
    k_omean<<<Bn * Hn / 256, 256>>>();
    k_feat_ga<<<Bn, 256>>>(tokens, ln_ga_w, ln_ga_b);
    k_sp_hidga<<<dim3(MIDn / 128, Bn / 128), 256, GSM_TOTAL>>>(ga_w1, ga_b1);
    k_gate_ga<<<Bn, 256>>>(ga_w2, ga_b2);
    k_sp_o2a<<<dim3(Hn / 128, Bn / 128), 256, GSM_TOTAL>>>(o2a_w);
    k_mixed<<<Bn, 256>>>(tokens, ln_a_w, ln_a_b);
    k_prep_mixed<<<(Bn * Mn * Hn) / 256, 256>>>();
    k_gemm_z_mma<<<dim3(Hn / 128, Bn / 128, Mn * Rn), 256, ZSM_TOTAL>>>();
    k_combine<<<Bn * Hn / 256, 256>>>(rank_w, lmf_bias, factors);
    k_ln_fused<<<Bn, 256>>>(out_ln1w, out_ln1b);
    k_sp_out<<<dim3(Hn / 128, Bn / 128), 256, GSM_TOTAL>>>(out_w, out_b);
    k_ln_out<<<Bn, 256>>>(out_ln2w, out_ln2b, out);
}

// round 5
// speedup vs baseline: 4.2384x; 1.2752x over previous
#include <cuda_runtime.h>
#include <cuda_bf16.h>
#include <math.h>
#include <cstdint>

#define Bn   4096
#define Mn   4
#define Hn   1024
#define Rn   10
#define MIDn 512
#define D3n  3072

// ---------------- scratch (__device__ globals: alloc-free) ----------------
__device__ float d_featgo[3 * Bn * D3n];
__device__ float d_hidgo[3 * Bn * MIDn];
__device__ float d_ggo[3 * Bn];
__device__ float d_a2o[Bn * Hn];
__device__ float d_onew[Bn * 3 * Hn];
__device__ float d_omean[Bn * Hn];
__device__ float d_featga[Bn * D3n];
__device__ float d_hidga[Bn * MIDn];
__device__ float d_gavec[Bn];
__device__ float d_o2a[Bn * Hn];
__device__ float d_mixed[Bn * Mn * Hn];
__device__ float d_zbuf[167772160];             // B*M*R*H fp32
__device__ float d_fused[Bn * Hn];
__device__ float d_h1[Bn * Hn];
__device__ float d_h2[Bn * Hn];
__device__ unsigned char d_mask[Bn * Mn];
__device__ int d_cidx[Mn * Bn];                 // per-m compacted valid-b lists (z GEMM)
__device__ int d_ccnt[Mn];
__device__ int d_pvidx[3 * Bn];                 // pair-valid (b,j) row list
__device__ int d_pvcnt;
__device__ int d_aumidx[Bn];                    // aum b list
__device__ int d_aumcnt;
// bf16-split operands for the LMF GEMM
__device__ __nv_bfloat16 d_ahi[Mn * Bn * Hn];      // [m][b][h]
__device__ __nv_bfloat16 d_alo[Mn * Bn * Hn];
__device__ __nv_bfloat16 d_fhi[Mn * Rn * Hn * Hn]; // [mr][h][d] (K-contiguous)
__device__ __nv_bfloat16 d_flo[Mn * Rn * Hn * Hn];

// ---------------- generic helpers ----------------
__device__ __forceinline__ float gelu_f(float x) {
    return 0.5f * x * (1.0f + erff(x * 0.70710678118654752f));
}
__device__ __forceinline__ float2 blkSum2(float a, float b) {
    __shared__ float sa[32], sb[32];
    __shared__ float ra, rb;
    int lane = threadIdx.x & 31, w = threadIdx.x >> 5;
#pragma unroll
    for (int o = 16; o > 0; o >>= 1) {
        a += __shfl_xor_sync(0xffffffffu, a, o);
        b += __shfl_xor_sync(0xffffffffu, b, o);
    }
    if (lane == 0) { sa[w] = a; sb[w] = b; }
    __syncthreads();
    if (threadIdx.x == 0) {
        float x = 0.f, y = 0.f;
        int nw = blockDim.x >> 5;
        for (int i = 0; i < nw; i++) { x += sa[i]; y += sb[i]; }
        ra = x; rb = y;
    }
    __syncthreads();
    return make_float2(ra, rb);
}

// ---------------- mma.sync helpers ----------------
__device__ __forceinline__ uint32_t smem_u32(const void* p) {
    uint32_t a;
    asm("{ .reg .u64 t; cvta.to.shared.u64 t, %1; cvt.u32.u64 %0, t; }" : "=r"(a) : "l"(p));
    return a;
}
__device__ __forceinline__ void ldm_x4(uint32_t& r0, uint32_t& r1, uint32_t& r2, uint32_t& r3,
                                       uint32_t addr) {
    asm volatile("ldmatrix.sync.aligned.m8n8.x4.shared.b16 {%0,%1,%2,%3}, [%4];"
                 : "=r"(r0), "=r"(r1), "=r"(r2), "=r"(r3) : "r"(addr));
}
__device__ __forceinline__ void mma_bf16(float* c, const uint32_t* a, const uint32_t* b) {
    asm volatile("mma.sync.aligned.m16n8k16.row.col.f32.bf16.bf16.f32 "
                 "{%0,%1,%2,%3}, {%4,%5,%6,%7}, {%8,%9}, {%0,%1,%2,%3};"
                 : "+f"(c[0]), "+f"(c[1]), "+f"(c[2]), "+f"(c[3])
                 : "r"(a[0]), "r"(a[1]), "r"(a[2]), "r"(a[3]), "r"(b[0]), "r"(b[1]));
}
__device__ __forceinline__ void cp16(uint32_t dst, const void* src) {
    asm volatile("cp.async.cg.shared.global [%0], [%1], 16;" :: "r"(dst), "l"(src));
}
#define CP_COMMIT() asm volatile("cp.async.commit_group;" ::: "memory")
#define CP_WAIT(n)  asm volatile("cp.async.wait_group %0;" :: "n"(n) : "memory")

__device__ __forceinline__ uint32_t pack_hi_lo(float x, float y, uint32_t& lo) {
    __nv_bfloat16 hx = __float2bfloat16(x);
    __nv_bfloat16 hy = __float2bfloat16(y);
    float lxf = x - __bfloat162float(hx);
    float lyf = y - __bfloat162float(hy);
    __nv_bfloat162 hv = __halves2bfloat162(hx, hy);
    __nv_bfloat162 lv = __halves2bfloat162(__float2bfloat16(lxf), __float2bfloat16(lyf));
    lo = *reinterpret_cast<uint32_t*>(&lv);
    return *reinterpret_cast<uint32_t*>(&hv);
}

// ---------------- mask dtype sniffer ----------------
__global__ void k_mask_norm(const void* p) {
    __shared__ int ok32, okf;
    if (threadIdx.x == 0) { ok32 = 1; okf = 1; }
    __syncthreads();
    const unsigned char* pb = (const unsigned char*)p;
    const int* pi = (const int*)p;
    const float* pf = (const float*)p;
    for (int i = threadIdx.x; i < 4096; i += blockDim.x) {
        int v = pi[i];
        if (v != 0 && v != 1) ok32 = 0;
        float f = pf[i];
        if (f != 0.0f && f != 1.0f) okf = 0;
    }
    __syncthreads();
    for (int i = threadIdx.x; i < Bn * Mn; i += blockDim.x) {
        unsigned char m;
        if (ok32)      m = (pi[i] != 0);
        else if (okf)  m = (pf[i] != 0.0f);
        else           m = (pb[i] != 0);
        d_mask[i] = m;
    }
}

// ---------------- generic single-block order-preserving compaction ----------------
template <int NITEMS, int PRED>   // PRED: 0 = per-m valid (m in param), 1 = pair-valid rows, 2 = aum b
__device__ __forceinline__ void compact_body(int m, int* out_idx, int* out_cnt) {
    __shared__ int warp_off[32];
    __shared__ int chunk_base;
    if (threadIdx.x == 0) chunk_base = 0;
    __syncthreads();
    int lane = threadIdx.x & 31, w = threadIdx.x >> 5;
    for (int c = 0; c < NITEMS; c += 1024) {
        int i = c + threadIdx.x;
        int v;
        if (PRED == 0) {
            v = d_mask[i * Mn + m] ? 1 : 0;
        } else if (PRED == 1) {
            int b = i / 3, j = i - 3 * b;
            int oj = (j == 0) ? 0 : (j + 1);
            v = (d_mask[b * 4 + oj] && d_mask[b * 4 + 1]) ? 1 : 0;
        } else {
            v = (d_mask[i * 4 + 1] && (d_mask[i * 4] | d_mask[i * 4 + 2] | d_mask[i * 4 + 3])) ? 1 : 0;
        }
        unsigned bal = __ballot_sync(0xffffffffu, v);
        int pre = __popc(bal & ((1u << lane) - 1u));
        if (lane == 31) warp_off[w] = __popc(bal);
        __syncthreads();
        if (threadIdx.x < 32) {
            int val = warp_off[threadIdx.x];
#pragma unroll
            for (int o = 1; o < 32; o <<= 1) {
                int t = __shfl_up_sync(0xffffffffu, val, o);
                if ((int)threadIdx.x >= o) val += t;
            }
            warp_off[threadIdx.x] = val;
        }
        __syncthreads();
        int base = chunk_base + (w ? warp_off[w - 1] : 0) + pre;
        if (v) out_idx[base] = i;
        __syncthreads();
        if (threadIdx.x == 0) chunk_base += warp_off[31];
        __syncthreads();
    }
    if (threadIdx.x == 0) *out_cnt = chunk_base;
}

__global__ void __launch_bounds__(1024) k_compact() {
    int m = blockIdx.x;
    compact_body<Bn, 0>(m, d_cidx + m * Bn, d_ccnt + m);
}
__global__ void __launch_bounds__(1024) k_compact_pv() {
    compact_body<3 * Bn, 1>(0, d_pvidx, &d_pvcnt);
}
__global__ void __launch_bounds__(1024) k_compact_aum() {
    compact_body<Bn, 2>(0, d_aumidx, &d_aumcnt);
}

// ---------------- generic fp32 -> bf16-split mma GEMM (512 thr, 16 warps) ----------------
// C[m][n] = act( sum_k A[m][k]*B[n][k] + bias[n] )
// SEL: 0 = full rows; 1 = row count d_pvcnt (compact A/C); 2 = d_aumcnt count only;
//      3 = d_aumcnt + gather/scatter rows through d_aumidx
#define GPAD   40
#define GBUF   (128 * GPAD * 2)        // 10240 B
#define GSTAGE (4 * GBUF)              // Ah,Al,Bh,Bl
#define GSM_TOTAL (2 * GSTAGE)         // 81920 B

template <int SEL>
__device__ __forceinline__ void gemm_sp_body(
    const float* __restrict__ A, int lda,
    const float* __restrict__ B, int ldb,
    float* __restrict__ C, int ldc,
    const float* __restrict__ bias, int K, int act)
{
    extern __shared__ char gsm[];
    int cnt = 1 << 30;
    const int* ridx = nullptr;
    if (SEL == 1) cnt = d_pvcnt;
    if (SEL == 2) cnt = d_aumcnt;
    if (SEL == 3) { cnt = d_aumcnt; ridx = d_aumidx; }
    const int n0 = blockIdx.x * 128, m0 = blockIdx.y * 128;
    if (SEL != 0 && m0 >= cnt) return;

    const uint32_t sbase = smem_u32(gsm);
    const int tid = threadIdx.x;
    const int wid = tid >> 5, lane = tid & 31;

    const int lrow = tid >> 2, lseg = tid & 3;
    int grow = m0 + lrow;
    if (SEL != 0 && grow >= cnt) grow = cnt - 1;
    const int arow = ridx ? ridx[grow] : grow;
    const float* Aref = A + (size_t)arow * lda + lseg * 8;
    const float* Bref = B + (size_t)(n0 + lrow) * ldb + lseg * 8;

    float4 ra[2], rb[2];
    auto gload = [&](int k0) {
        ra[0] = *(const float4*)(Aref + k0);
        ra[1] = *(const float4*)(Aref + k0 + 4);
        rb[0] = *(const float4*)(Bref + k0);
        rb[1] = *(const float4*)(Bref + k0 + 4);
    };
    auto sstore = [&](int st) {
        char* p = gsm + st * GSTAGE + lrow * (GPAD * 2) + lseg * 16;
        uint32_t l0, l1, l2, l3;
        uint32_t h0 = pack_hi_lo(ra[0].x, ra[0].y, l0);
        uint32_t h1 = pack_hi_lo(ra[0].z, ra[0].w, l1);
        uint32_t h2 = pack_hi_lo(ra[1].x, ra[1].y, l2);
        uint32_t h3 = pack_hi_lo(ra[1].z, ra[1].w, l3);
        *(uint4*)(p + 0 * GBUF) = make_uint4(h0, h1, h2, h3);
        *(uint4*)(p + 1 * GBUF) = make_uint4(l0, l1, l2, l3);
        h0 = pack_hi_lo(rb[0].x, rb[0].y, l0);
        h1 = pack_hi_lo(rb[0].z, rb[0].w, l1);
        h2 = pack_hi_lo(rb[1].x, rb[1].y, l2);
        h3 = pack_hi_lo(rb[1].z, rb[1].w, l3);
        *(uint4*)(p + 2 * GBUF) = make_uint4(h0, h1, h2, h3);
        *(uint4*)(p + 3 * GBUF) = make_uint4(l0, l1, l2, l3);
    };

    float acc[2][4][4];
#pragma unroll
    for (int i = 0; i < 2; i++)
#pragma unroll
        for (int j = 0; j < 4; j++)
#pragma unroll
            for (int c = 0; c < 4; c++) acc[i][j][c] = 0.0f;

    const int wm0 = (wid >> 2) * 32;
    const int wn0 = (wid & 3) * 32;
    const int a_r = lane & 15;
    const int a_c8 = (lane >> 4) << 3;
    const int b_r = (lane & 7) + ((lane >> 4) << 3);
    const int b_c8 = ((lane >> 3) & 1) << 3;

    gload(0);
    const int NIT = K / 32;
    for (int it = 0; it < NIT; it++) {
        const int st = it & 1;
        sstore(st);
        __syncthreads();
        if (it + 1 < NIT) gload((it + 1) * 32);

        const uint32_t sAh = sbase + st * GSTAGE + 0 * GBUF;
        const uint32_t sAl = sbase + st * GSTAGE + 1 * GBUF;
        const uint32_t sBh = sbase + st * GSTAGE + 2 * GBUF;
        const uint32_t sBl = sbase + st * GSTAGE + 3 * GBUF;
#pragma unroll
        for (int ks = 0; ks < 2; ks++) {
            const int kb = ks * 16;
            uint32_t aH[2][4], aL[2][4], bH[4][2], bL[4][2];
#pragma unroll
            for (int mi = 0; mi < 2; mi++) {
                uint32_t off = (uint32_t)(wm0 + mi * 16 + a_r) * (GPAD * 2) + (kb + a_c8) * 2;
                ldm_x4(aH[mi][0], aH[mi][1], aH[mi][2], aH[mi][3], sAh + off);
                ldm_x4(aL[mi][0], aL[mi][1], aL[mi][2], aL[mi][3], sAl + off);
            }
#pragma unroll
            for (int p2 = 0; p2 < 2; p2++) {
                uint32_t off = (uint32_t)(wn0 + p2 * 16 + b_r) * (GPAD * 2) + (kb + b_c8) * 2;
                ldm_x4(bH[2 * p2][0], bH[2 * p2][1], bH[2 * p2 + 1][0], bH[2 * p2 + 1][1], sBh + off);
                ldm_x4(bL[2 * p2][0], bL[2 * p2][1], bL[2 * p2 + 1][0], bL[2 * p2 + 1][1], sBl + off);
            }
#pragma unroll
            for (int mi = 0; mi < 2; mi++)
#pragma unroll
                for (int ni = 0; ni < 4; ni++) {
                    mma_bf16(acc[mi][ni], aH[mi], bH[ni]);
                    mma_bf16(acc[mi][ni], aH[mi], bL[ni]);
                    mma_bf16(acc[mi][ni], aL[mi], bH[ni]);
                }
        }
        __syncthreads();
    }

#pragma unroll
    for (int mi = 0; mi < 2; mi++) {
#pragma unroll
        for (int half = 0; half < 2; half++) {
            int r = m0 + wm0 + mi * 16 + (lane >> 2) + half * 8;
            if (SEL != 0 && r >= cnt) continue;
            int crow = ridx ? ridx[r] : r;
            float* dd = C + (size_t)crow * ldc;
#pragma unroll
            for (int ni = 0; ni < 4; ni++) {
                int cc = n0 + wn0 + ni * 8 + (lane & 3) * 2;
                float v0 = acc[mi][ni][half * 2 + 0] + (bias ? bias[cc] : 0.f);
                float v1 = acc[mi][ni][half * 2 + 1] + (bias ? bias[cc + 1] : 0.f);
                if (act) { v0 = gelu_f(v0); v1 = gelu_f(v1); }
                *(float2*)(dd + cc) = make_float2(v0, v1);
            }
        }
    }
}

__global__ void __launch_bounds__(512) k_sp_hidgo(const float* w1, const float* b1) {
    gemm_sp_body<1>(d_featgo, D3n, w1, D3n, d_hidgo, MIDn, b1, D3n, 1);
}
__global__ void __launch_bounds__(512) k_sp_hidga(const float* w1, const float* b1) {
    gemm_sp_body<2>(d_featga, D3n, w1, D3n, d_hidga, MIDn, b1, D3n, 1);
}
__global__ void __launch_bounds__(512) k_sp_a2o(const float* tokens, const float* w) {
    gemm_sp_body<3>(tokens + Hn, Mn * Hn, w, Hn, d_a2o, Hn, (const float*)0, Hn, 0);
}
__global__ void __launch_bounds__(512) k_sp_o2a(const float* w) {
    gemm_sp_body<3>(d_omean, Hn, w, Hn, d_o2a, Hn, (const float*)0, Hn, 0);
}
__global__ void __launch_bounds__(512) k_sp_out(const float* w, const float* bb) {
    gemm_sp_body<0>(d_h1, Hn, w, Hn, d_h2, Hn, bb, Hn, 1);
}

// ---------------- bf16-split prep ----------------
__global__ void k_prep_mixed() {
    int idx = blockIdx.x * 256 + threadIdx.x;
    int h = idx & 1023;
    int bm = idx >> 10;
    int b = bm >> 2, m = bm & 3;
    float x = d_mixed[idx];
    __nv_bfloat16 hi = __float2bfloat16(x);
    float lo = x - __bfloat162float(hi);
    size_t o = ((size_t)m * Bn + b) * Hn + h;
    d_ahi[o] = hi;
    d_alo[o] = __float2bfloat16(lo);
}

__global__ void __launch_bounds__(256) k_prep_factors(const float* __restrict__ f) {
    __shared__ float t[32][33];
    int mr = blockIdx.z;
    int d0 = blockIdx.x * 32, h0 = blockIdx.y * 32;
    int tx = threadIdx.x, ty = threadIdx.y;
#pragma unroll
    for (int i = ty; i < 32; i += 8)
        t[i][tx] = f[((size_t)mr * 1025 + 1 + d0 + i) * Hn + h0 + tx];
    __syncthreads();
#pragma unroll
    for (int i = ty; i < 32; i += 8) {
        float x = t[tx][i];
        __nv_bfloat16 hi = __float2bfloat16(x);
        float lo = x - __bfloat162float(hi);
        size_t o = ((size_t)mr * Hn + h0 + i) * Hn + d0 + tx;
        d_fhi[o] = hi;
        d_flo[o] = __float2bfloat16(lo);
    }
}

// ---------------- LMF GEMM (mask-compacted, 512 thr, 3-stage cp.async) ----------------
#define ZKC   32
#define ZPAD  40
#define ZBUFB (128 * ZPAD * 2)
#define ZSTAGE (4 * ZBUFB)
#define ZSM_TOTAL (3 * ZSTAGE)         // 122880 B

__global__ void __launch_bounds__(512) k_gemm_z_mma() {
    extern __shared__ char zsm[];
    const uint32_t sbase = smem_u32(zsm);
    const int tid = threadIdx.x;
    const int wid = tid >> 5, lane = tid & 31;
    const int h0 = blockIdx.x * 128;
    const int b0 = blockIdx.y * 128;
    const int mr = blockIdx.z;
    const int m = mr / Rn;
    const int cnt = d_ccnt[m];
    if (b0 >= cnt) return;

    const int lrow = tid >> 2;
    const int lseg = tid & 3;

    int grow = b0 + lrow;
    int gidx = d_cidx[m * Bn + (grow < cnt ? grow : cnt - 1)];

    const __nv_bfloat16* rowp[4];
    rowp[0] = d_ahi + ((size_t)m * Bn + gidx) * Hn + lseg * 8;
    rowp[1] = d_alo + ((size_t)m * Bn + gidx) * Hn + lseg * 8;
    rowp[2] = d_fhi + ((size_t)mr * Hn + h0 + lrow) * Hn + lseg * 8;
    rowp[3] = d_flo + ((size_t)mr * Hn + h0 + lrow) * Hn + lseg * 8;

    auto load_stage = [&](int st, int k0) {
        uint32_t dst = sbase + st * ZSTAGE + lrow * (ZPAD * 2) + lseg * 16;
#pragma unroll
        for (int bsel = 0; bsel < 4; bsel++)
            cp16(dst + bsel * ZBUFB, rowp[bsel] + k0);
    };

    float acc[2][4][4];
#pragma unroll
    for (int i = 0; i < 2; i++)
#pragma unroll
        for (int j = 0; j < 4; j++)
#pragma unroll
            for (int c = 0; c < 4; c++) acc[i][j][c] = 0.0f;

    const int wm0 = (wid >> 2) * 32;
    const int wn0 = (wid & 3) * 32;
    const int a_r = lane & 15;
    const int a_c8 = (lane >> 4) << 3;
    const int b_r = (lane & 7) + ((lane >> 4) << 3);
    const int b_c8 = ((lane >> 3) & 1) << 3;

    load_stage(0, 0);
    CP_COMMIT();
    load_stage(1, ZKC);
    CP_COMMIT();

    const int NIT = Hn / ZKC;              // 32
    for (int it = 0; it < NIT; it++) {
        CP_WAIT(1);
        __syncthreads();
        if (it + 2 < NIT) {
            load_stage((it + 2) % 3, (it + 2) * ZKC);
            CP_COMMIT();
        }
        const int st = it % 3;
        const uint32_t sAh = sbase + st * ZSTAGE + 0 * ZBUFB;
        const uint32_t sAl = sbase + st * ZSTAGE + 1 * ZBUFB;
        const uint32_t sBh = sbase + st * ZSTAGE + 2 * ZBUFB;
        const uint32_t sBl = sbase + st * ZSTAGE + 3 * ZBUFB;

#pragma unroll
        for (int ks = 0; ks < 2; ks++) {
            const int kb = ks * 16;
            uint32_t aH[2][4], aL[2][4], bH[4][2], bL[4][2];
#pragma unroll
            for (int mi = 0; mi < 2; mi++) {
                uint32_t off = (uint32_t)(wm0 + mi * 16 + a_r) * (ZPAD * 2) + (kb + a_c8) * 2;
                ldm_x4(aH[mi][0], aH[mi][1], aH[mi][2], aH[mi][3], sAh + off);
                ldm_x4(aL[mi][0], aL[mi][1], aL[mi][2], aL[mi][3], sAl + off);
            }
#pragma unroll
            for (int p = 0; p < 2; p++) {
                uint32_t off = (uint32_t)(wn0 + p * 16 + b_r) * (ZPAD * 2) + (kb + b_c8) * 2;
                ldm_x4(bH[2 * p][0], bH[2 * p][1], bH[2 * p + 1][0], bH[2 * p + 1][1], sBh + off);
                ldm_x4(bL[2 * p][0], bL[2 * p][1], bL[2 * p + 1][0], bL[2 * p + 1][1], sBl + off);
            }
#pragma unroll
            for (int mi = 0; mi < 2; mi++)
#pragma unroll
                for (int ni = 0; ni < 4; ni++) {
                    mma_bf16(acc[mi][ni], aH[mi], bH[ni]);
                    mma_bf16(acc[mi][ni], aH[mi], bL[ni]);
                    mma_bf16(acc[mi][ni], aL[mi], bH[ni]);
                }
        }
        __syncthreads();
    }

    // epilogue: scatter z rows through the compaction index
#pragma unroll
    for (int mi = 0; mi < 2; mi++) {
#pragma unroll
        for (int half = 0; half < 2; half++) {
            int r = b0 + wm0 + mi * 16 + (lane >> 2) + half * 8;
            if (r >= cnt) continue;
            int br = d_cidx[m * Bn + r];
            float* dd = d_zbuf + ((size_t)br * (Mn * Rn) + mr) * Hn + h0;
#pragma unroll
            for (int ni = 0; ni < 4; ni++) {
                int cc = wn0 + ni * 8 + (lane & 3) * 2;
                *(float2*)(dd + cc) = make_float2(acc[mi][ni][half * 2 + 0], acc[mi][ni][half * 2 + 1]);
            }
        }
    }
}

// ---------------- feat builders (compacted) ----------------
__global__ void k_feat_go(const float* tokens, const float* lnw, const float* lnb) {
    int i = blockIdx.x;
    if (i >= d_pvcnt) return;
    int row = d_pvidx[i];
    int b = row / 3, j = row - 3 * b;
    int oj = (j == 0) ? 0 : (j + 1);
    const float* tok = tokens + (size_t)b * Mn * Hn;
    __shared__ float sf[D3n];
    float s = 0.f, q = 0.f;
    for (int k = threadIdx.x; k < Hn; k += blockDim.x) {
        float t = tok[oj * Hn + k];          // pair-valid => mask = 1
        float sv = tok[Hn + k];
        float dv = fabsf(t - sv);
        sf[k] = t; sf[Hn + k] = sv; sf[2 * Hn + k] = dv;
        s += t + sv + dv; q += t * t + sv * sv + dv * dv;
    }
    float2 rr = blkSum2(s, q);
    float mean = rr.x / D3n;
    float var = rr.y / D3n - mean * mean;
    float rstd = rsqrtf(var + 1e-5f);
    float* o = d_featgo + (size_t)i * D3n;
    for (int k = threadIdx.x; k < D3n; k += blockDim.x)
        o[k] = (sf[k] - mean) * rstd * lnw[k] + lnb[k];
}

__global__ void k_feat_ga(const float* tokens, const float* lnw, const float* lnb) {
    int i = blockIdx.x;
    if (i >= d_aumcnt) return;
    int b = d_aumidx[i];
    const float* tok = tokens + (size_t)b * Mn * Hn;
    __shared__ float sf[D3n];
    float s = 0.f, q = 0.f;
    for (int k = threadIdx.x; k < Hn; k += blockDim.x) {
        float t = tok[Hn + k];
        float sv = d_omean[(size_t)b * Hn + k];
        float dv = fabsf(t - sv);
        sf[k] = t; sf[Hn + k] = sv; sf[2 * Hn + k] = dv;
        s += t + sv + dv; q += t * t + sv * sv + dv * dv;
    }
    float2 rr = blkSum2(s, q);
    float mean = rr.x / D3n;
    float var = rr.y / D3n - mean * mean;
    float rstd = rsqrtf(var + 1e-5f);
    float* o = d_featga + (size_t)i * D3n;
    for (int k = threadIdx.x; k < D3n; k += blockDim.x)
        o[k] = (sf[k] - mean) * rstd * lnw[k] + lnb[k];
}

// ---------------- gate tails (compacted) ----------------
__global__ void k_gate_go(const float* w2, const float* b2) {
    int i = blockIdx.x;
    if (i >= d_pvcnt) return;
    const float* hr = d_hidgo + (size_t)i * MIDn;
    float v = 0.f;
    for (int k = threadIdx.x; k < MIDn; k += blockDim.x) v += hr[k] * w2[k];
    float2 rr = blkSum2(v, 0.f);
    if (threadIdx.x == 0) d_ggo[d_pvidx[i]] = 1.0f / (1.0f + expf(-(rr.x + b2[0])));
}
__global__ void k_gate_ga(const float* w2, const float* b2) {
    int i = blockIdx.x;
    if (i >= d_aumcnt) return;
    const float* hr = d_hidga + (size_t)i * MIDn;
    float v = 0.f;
    for (int k = threadIdx.x; k < MIDn; k += blockDim.x) v += hr[k] * w2[k];
    float2 rr = blkSum2(v, 0.f);
    if (threadIdx.x == 0) d_gavec[d_aumidx[i]] = 1.0f / (1.0f + expf(-(rr.x + b2[0])));
}

// ---------------- others_new ----------------
__global__ void k_others_new(const float* tokens, const float* lnw, const float* lnb) {
    int row = blockIdx.x;
    int b = row / 3, j = row - 3 * b;
    int oj = (j == 0) ? 0 : (j + 1);
    const float* tok = tokens + (size_t)b * Mn * Hn;
    int moj = d_mask[b * Mn + oj], ma = d_mask[b * Mn + 1];
    float* o = d_onew + (size_t)row * Hn;
    if (moj && ma) {
        __shared__ float sx[Hn];
        float g = d_ggo[row];
        float s = 0.f, q = 0.f;
        for (int k = threadIdx.x; k < Hn; k += blockDim.x) {
            float x = tok[oj * Hn + k] + g * d_a2o[(size_t)b * Hn + k];
            sx[k] = x; s += x; q += x * x;
        }
        float2 rr = blkSum2(s, q);
        float mean = rr.x / Hn;
        float var = rr.y / Hn - mean * mean;
        float rstd = rsqrtf(var + 1e-5f);
        for (int k = threadIdx.x; k < Hn; k += blockDim.x)
            o[k] = (sx[k] - mean) * rstd * lnw[k] + lnb[k];
    } else {
        float mf = moj ? 1.0f : 0.0f;
        for (int k = threadIdx.x; k < Hn; k += blockDim.x)
            o[k] = tok[oj * Hn + k] * mf;
    }
}

__global__ void k_omean() {
    int idx = blockIdx.x * 256 + threadIdx.x;
    int b = idx >> 10, h = idx & 1023;
    float m0 = d_mask[b * 4 + 0] ? 1.f : 0.f;
    float m2 = d_mask[b * 4 + 2] ? 1.f : 0.f;
    float m3 = d_mask[b * 4 + 3] ? 1.f : 0.f;
    float denom = fmaxf(1.0f, m0 + m2 + m3);
    size_t base = (size_t)b * 3 * Hn;
    float sum = d_onew[base + h] + d_onew[base + Hn + h] + d_onew[base + 2 * Hn + h];
    d_omean[idx] = sum / denom;
}

// ---------------- mixed assembly ----------------
__global__ void k_mixed(const float* tokens, const float* lnw, const float* lnb) {
    int b = blockIdx.x;
    const float* tok = tokens + (size_t)b * Mn * Hn;
    int m0 = d_mask[b * 4], m1 = d_mask[b * 4 + 1], m2 = d_mask[b * 4 + 2], m3 = d_mask[b * 4 + 3];
    float* mx = d_mixed + (size_t)b * Mn * Hn;
    int aum = m1 && (m0 || m2 || m3);
    if (aum) {
        __shared__ float sx[Hn];
        float g = d_gavec[b];
        float s = 0.f, q = 0.f;
        for (int k = threadIdx.x; k < Hn; k += blockDim.x) {
            float x = tok[Hn + k] + g * d_o2a[(size_t)b * Hn + k];
            sx[k] = x; s += x; q += x * x;
        }
        float2 rr = blkSum2(s, q);
        float mean = rr.x / Hn;
        float var = rr.y / Hn - mean * mean;
        float rstd = rsqrtf(var + 1e-5f);
        for (int k = threadIdx.x; k < Hn; k += blockDim.x)
            mx[Hn + k] = (sx[k] - mean) * rstd * lnw[k] + lnb[k];
    } else {
        float f = m1 ? 1.0f : 0.0f;
        for (int k = threadIdx.x; k < Hn; k += blockDim.x)
            mx[Hn + k] = tok[Hn + k] * f;
    }
    float f0 = m0 ? 1.f : 0.f, f2 = m2 ? 1.f : 0.f, f3 = m3 ? 1.f : 0.f;
    size_t ob = (size_t)b * 3 * Hn;
    for (int k = threadIdx.x; k < Hn; k += blockDim.x) {
        mx[k]           = d_onew[ob + k] * f0;
        mx[2 * Hn + k]  = d_onew[ob + Hn + k] * f2;
        mx[3 * Hn + k]  = d_onew[ob + 2 * Hn + k] * f3;
    }
}

// ---------------- rank product + weighted sum ----------------
__global__ void k_combine(const float* rank_w, const float* lmf_bias,
                          const float* __restrict__ factors) {
    int idx = blockIdx.x * 256 + threadIdx.x;
    int b = idx >> 10, h = idx & 1023;
    const unsigned char* mk = d_mask + b * 4;
    bool m0 = mk[0], m1 = mk[1], m2 = mk[2], m3 = mk[3];
    const float* zb = d_zbuf + (size_t)b * (Mn * Rn * Hn) + h;
    float acc = 0.f;
#pragma unroll
    for (int r = 0; r < Rn; r++) {
        float p = rank_w[r];
        if (m0) p *= zb[(0 * Rn + r) * Hn] + factors[((size_t)(0 * Rn + r) * 1025) * Hn + h];
        if (m1) p *= zb[(1 * Rn + r) * Hn] + factors[((size_t)(1 * Rn + r) * 1025) * Hn + h];
        if (m2) p *= zb[(2 * Rn + r) * Hn] + factors[((size_t)(2 * Rn + r) * 1025) * Hn + h];
        if (m3) p *= zb[(3 * Rn + r) * Hn] + factors[((size_t)(3 * Rn + r) * 1025) * Hn + h];
        acc += p;
    }
    d_fused[idx] = acc + lmf_bias[h];
}

// ---------------- row LayerNorms ----------------
__device__ __forceinline__ void rowln(const float* x, float* y, const float* w, const float* bb) {
    float s = 0.f, q = 0.f;
    for (int k = threadIdx.x; k < Hn; k += blockDim.x) { float v = x[k]; s += v; q += v * v; }
    float2 rr = blkSum2(s, q);
    float mean = rr.x / Hn;
    float var = rr.y / Hn - mean * mean;
    float rstd = rsqrtf(var + 1e-5f);
    for (int k = threadIdx.x; k < Hn; k += blockDim.x)
        y[k] = (x[k] - mean) * rstd * w[k] + bb[k];
}
__global__ void k_ln_fused(const float* w, const float* bb) {
    rowln(d_fused + (size_t)blockIdx.x * Hn, d_h1 + (size_t)blockIdx.x * Hn, w, bb);
}
__global__ void k_ln_out(const float* w, const float* bb, float* out) {
    rowln(d_h2 + (size_t)blockIdx.x * Hn, out + (size_t)blockIdx.x * Hn, w, bb);
}

// ---------------- launch ----------------
extern "C" void kernel_launch(void* const* d_in, const int* in_sizes, int n_in,
                              void* d_out, int out_size) {
    const float* tokens   = (const float*)d_in[0];
    const void*  maskraw  = d_in[1];
    const float* ln_go_w  = (const float*)d_in[2];
    const float* ln_go_b  = (const float*)d_in[3];
    const float* go_w1    = (const float*)d_in[4];
    const float* go_b1    = (const float*)d_in[5];
    const float* go_w2    = (const float*)d_in[6];
    const float* go_b2    = (const float*)d_in[7];
    const float* ln_ga_w  = (const float*)d_in[8];
    const float* ln_ga_b  = (const float*)d_in[9];
    const float* ga_w1    = (const float*)d_in[10];
    const float* ga_b1    = (const float*)d_in[11];
    const float* ga_w2    = (const float*)d_in[12];
    const float* ga_b2    = (const float*)d_in[13];
    const float* a2o_w    = (const float*)d_in[14];
    const float* o2a_w    = (const float*)d_in[15];
    const float* ln_o_w   = (const float*)d_in[16];
    const float* ln_o_b   = (const float*)d_in[17];
    const float* ln_a_w   = (const float*)d_in[18];
    const float* ln_a_b   = (const float*)d_in[19];
    const float* factors  = (const float*)d_in[20];
    const float* rank_w   = (const float*)d_in[21];
    const float* lmf_bias = (const float*)d_in[22];
    const float* out_ln1w = (const float*)d_in[23];
    const float* out_ln1b = (const float*)d_in[24];
    const float* out_w    = (const float*)d_in[25];
    const float* out_b    = (const float*)d_in[26];
    const float* out_ln2w = (const float*)d_in[27];
    const float* out_ln2b = (const float*)d_in[28];
    float* out = (float*)d_out;

    static int smem_set = 0;
    if (!smem_set) {
        cudaFuncSetAttribute(k_gemm_z_mma, cudaFuncAttributeMaxDynamicSharedMemorySize, ZSM_TOTAL);
        cudaFuncSetAttribute(k_sp_hidgo, cudaFuncAttributeMaxDynamicSharedMemorySize, GSM_TOTAL);
        cudaFuncSetAttribute(k_sp_hidga, cudaFuncAttributeMaxDynamicSharedMemorySize, GSM_TOTAL);
        cudaFuncSetAttribute(k_sp_a2o,   cudaFuncAttributeMaxDynamicSharedMemorySize, GSM_TOTAL);
        cudaFuncSetAttribute(k_sp_o2a,   cudaFuncAttributeMaxDynamicSharedMemorySize, GSM_TOTAL);
        cudaFuncSetAttribute(k_sp_out,   cudaFuncAttributeMaxDynamicSharedMemorySize, GSM_TOTAL);
        smem_set = 1;
    }

    k_mask_norm<<<1, 256>>>(maskraw);
    k_compact<<<Mn, 1024>>>();
    k_compact_pv<<<1, 1024>>>();
    k_compact_aum<<<1, 1024>>>();
    k_prep_factors<<<dim3(32, 32, Mn * Rn), dim3(32, 8)>>>(factors);
    k_sp_a2o<<<dim3(Hn / 128, Bn / 128), 512, GSM_TOTAL>>>(tokens, a2o_w);
    k_feat_go<<<3 * Bn, 256>>>(tokens, ln_go_w, ln_go_b);
    k_sp_hidgo<<<dim3(MIDn / 128, 3 * Bn / 128), 512, GSM_TOTAL>>>(go_w1, go_b1);
    k_gate_go<<<3 * Bn, 256>>>(go_w2, go_b2);
    k_others_new<<<3 * Bn, 256>>>(tokens, ln_o_w, ln_o_b);
    k_omean<<<Bn * Hn / 256, 256>>>();
    k_feat_ga<<<Bn, 256>>>(tokens, ln_ga_w, ln_ga_b);
    k_sp_hidga<<<dim3(MIDn / 128, Bn / 128), 512, GSM_TOTAL>>>(ga_w1, ga_b1);
    k_gate_ga<<<Bn, 256>>>(ga_w2, ga_b2);
    k_sp_o2a<<<dim3(Hn / 128, Bn / 128), 512, GSM_TOTAL>>>(o2a_w);
    k_mixed<<<Bn, 256>>>(tokens, ln_a_w, ln_a_b);
    k_prep_mixed<<<(Bn * Mn * Hn) / 256, 256>>>();
    k_gemm_z_mma<<<dim3(Hn / 128, Bn / 128, Mn * Rn), 512, ZSM_TOTAL>>>();
    k_combine<<<Bn * Hn / 256, 256>>>(rank_w, lmf_bias, factors);
    k_ln_fused<<<Bn, 256>>>(out_ln1w, out_ln1b);
    k_sp_out<<<dim3(Hn / 128, Bn / 128), 512, GSM_TOTAL>>>(out_w, out_b);
    k_ln_out<<<Bn, 256>>>(out_ln2w, out_ln2b, out);
}

// round 7
// speedup vs baseline: 4.2770x; 1.0091x over previous
#include <cuda_runtime.h>
#include <cuda_bf16.h>
#include <math.h>
#include <cstdint>

#define Bn   4096
#define Mn   4
#define Hn   1024
#define Rn   10
#define MIDn 512
#define D3n  3072

// ---------------- scratch (__device__ globals: alloc-free) ----------------
__device__ float d_featgo[3 * Bn * D3n];
__device__ float d_hidgo[3 * Bn * MIDn];
__device__ float d_ggo[3 * Bn];
__device__ float d_a2o[Bn * Hn];
__device__ float d_onew[Bn * 3 * Hn];
__device__ float d_omean[Bn * Hn];
__device__ float d_featga[Bn * D3n];
__device__ float d_hidga[Bn * MIDn];
__device__ float d_gavec[Bn];
__device__ float d_o2a[Bn * Hn];
__device__ float d_zbuf[167772160];             // B*M*R*H fp32
__device__ float d_h1[Bn * Hn];
__device__ float d_h2[Bn * Hn];
__device__ unsigned char d_mask[Bn * Mn];
__device__ int d_cidx[Mn * Bn];                 // per-m compacted valid-b lists (z GEMM)
__device__ int d_ccnt[Mn];
__device__ int d_pvidx[3 * Bn];                 // pair-valid (b,j) row list
__device__ int d_pvcnt;
__device__ int d_aumidx[Bn];                    // aum b list
__device__ int d_aumcnt;
// bf16-split operands for the LMF GEMM
__device__ __nv_bfloat16 d_ahi[Mn * Bn * Hn];      // [m][b][h]
__device__ __nv_bfloat16 d_alo[Mn * Bn * Hn];
__device__ __nv_bfloat16 d_fhi[Mn * Rn * Hn * Hn]; // [mr][h][d] (K-contiguous)
__device__ __nv_bfloat16 d_flo[Mn * Rn * Hn * Hn];

// ---------------- generic helpers ----------------
__device__ __forceinline__ float gelu_f(float x) {
    return 0.5f * x * (1.0f + erff(x * 0.70710678118654752f));
}
__device__ __forceinline__ float2 blkSum2(float a, float b) {
    __shared__ float sa[32], sb[32];
    __shared__ float ra, rb;
    int lane = threadIdx.x & 31, w = threadIdx.x >> 5;
#pragma unroll
    for (int o = 16; o > 0; o >>= 1) {
        a += __shfl_xor_sync(0xffffffffu, a, o);
        b += __shfl_xor_sync(0xffffffffu, b, o);
    }
    if (lane == 0) { sa[w] = a; sb[w] = b; }
    __syncthreads();
    if (threadIdx.x == 0) {
        float x = 0.f, y = 0.f;
        int nw = blockDim.x >> 5;
        for (int i = 0; i < nw; i++) { x += sa[i]; y += sb[i]; }
        ra = x; rb = y;
    }
    __syncthreads();
    return make_float2(ra, rb);
}

// ---------------- mma.sync helpers ----------------
__device__ __forceinline__ uint32_t smem_u32(const void* p) {
    uint32_t a;
    asm("{ .reg .u64 t; cvta.to.shared.u64 t, %1; cvt.u32.u64 %0, t; }" : "=r"(a) : "l"(p));
    return a;
}
__device__ __forceinline__ void ldm_x4(uint32_t& r0, uint32_t& r1, uint32_t& r2, uint32_t& r3,
                                       uint32_t addr) {
    asm volatile("ldmatrix.sync.aligned.m8n8.x4.shared.b16 {%0,%1,%2,%3}, [%4];"
                 : "=r"(r0), "=r"(r1), "=r"(r2), "=r"(r3) : "r"(addr));
}
__device__ __forceinline__ void mma_bf16(float* c, const uint32_t* a, const uint32_t* b) {
    asm volatile("mma.sync.aligned.m16n8k16.row.col.f32.bf16.bf16.f32 "
                 "{%0,%1,%2,%3}, {%4,%5,%6,%7}, {%8,%9}, {%0,%1,%2,%3};"
                 : "+f"(c[0]), "+f"(c[1]), "+f"(c[2]), "+f"(c[3])
                 : "r"(a[0]), "r"(a[1]), "r"(a[2]), "r"(a[3]), "r"(b[0]), "r"(b[1]));
}
__device__ __forceinline__ void cp16(uint32_t dst, const void* src) {
    asm volatile("cp.async.cg.shared.global [%0], [%1], 16;" :: "r"(dst), "l"(src));
}
#define CP_COMMIT() asm volatile("cp.async.commit_group;" ::: "memory")
#define CP_WAIT(n)  asm volatile("cp.async.wait_group %0;" :: "n"(n) : "memory")

__device__ __forceinline__ uint32_t pack_hi_lo(float x, float y, uint32_t& lo) {
    __nv_bfloat16 hx = __float2bfloat16(x);
    __nv_bfloat16 hy = __float2bfloat16(y);
    float lxf = x - __bfloat162float(hx);
    float lyf = y - __bfloat162float(hy);
    __nv_bfloat162 hv = __halves2bfloat162(hx, hy);
    __nv_bfloat162 lv = __halves2bfloat162(__float2bfloat16(lxf), __float2bfloat16(lyf));
    lo = *reinterpret_cast<uint32_t*>(&lv);
    return *reinterpret_cast<uint32_t*>(&hv);
}

// ---------------- mask dtype sniffer ----------------
__global__ void k_mask_norm(const void* p) {
    __shared__ int ok32, okf;
    if (threadIdx.x == 0) { ok32 = 1; okf = 1; }
    __syncthreads();
    const unsigned char* pb = (const unsigned char*)p;
    const int* pi = (const int*)p;
    const float* pf = (const float*)p;
    for (int i = threadIdx.x; i < 4096; i += blockDim.x) {
        int v = pi[i];
        if (v != 0 && v != 1) ok32 = 0;
        float f = pf[i];
        if (f != 0.0f && f != 1.0f) okf = 0;
    }
    __syncthreads();
    for (int i = threadIdx.x; i < Bn * Mn; i += blockDim.x) {
        unsigned char m;
        if (ok32)      m = (pi[i] != 0);
        else if (okf)  m = (pf[i] != 0.0f);
        else           m = (pb[i] != 0);
        d_mask[i] = m;
    }
}

// ---------------- generic single-block order-preserving compaction ----------------
template <int NITEMS, int PRED>
__device__ __forceinline__ void compact_body(int m, int* out_idx, int* out_cnt) {
    __shared__ int warp_off[32];
    __shared__ int chunk_base;
    if (threadIdx.x == 0) chunk_base = 0;
    __syncthreads();
    int lane = threadIdx.x & 31, w = threadIdx.x >> 5;
    for (int c = 0; c < NITEMS; c += 1024) {
        int i = c + threadIdx.x;
        int v;
        if (PRED == 0) {
            v = d_mask[i * Mn + m] ? 1 : 0;
        } else if (PRED == 1) {
            int b = i / 3, j = i - 3 * b;
            int oj = (j == 0) ? 0 : (j + 1);
            v = (d_mask[b * 4 + oj] && d_mask[b * 4 + 1]) ? 1 : 0;
        } else {
            v = (d_mask[i * 4 + 1] && (d_mask[i * 4] | d_mask[i * 4 + 2] | d_mask[i * 4 + 3])) ? 1 : 0;
        }
        unsigned bal = __ballot_sync(0xffffffffu, v);
        int pre = __popc(bal & ((1u << lane) - 1u));
        if (lane == 31) warp_off[w] = __popc(bal);
        __syncthreads();
        if (threadIdx.x < 32) {
            int val = warp_off[threadIdx.x];
#pragma unroll
            for (int o = 1; o < 32; o <<= 1) {
                int t = __shfl_up_sync(0xffffffffu, val, o);
                if ((int)threadIdx.x >= o) val += t;
            }
            warp_off[threadIdx.x] = val;
        }
        __syncthreads();
        int base = chunk_base + (w ? warp_off[w - 1] : 0) + pre;
        if (v) out_idx[base] = i;
        __syncthreads();
        if (threadIdx.x == 0) chunk_base += warp_off[31];
        __syncthreads();
    }
    if (threadIdx.x == 0) *out_cnt = chunk_base;
}

__global__ void __launch_bounds__(1024) k_compact() {
    int m = blockIdx.x;
    compact_body<Bn, 0>(m, d_cidx + m * Bn, d_ccnt + m);
}
__global__ void __launch_bounds__(1024) k_compact_pv() {
    compact_body<3 * Bn, 1>(0, d_pvidx, &d_pvcnt);
}
__global__ void __launch_bounds__(1024) k_compact_aum() {
    compact_body<Bn, 2>(0, d_aumidx, &d_aumcnt);
}

// ---------------- generic fp32 -> bf16-split mma GEMM (512 thr, 16 warps) ----------------
#define GPAD   40
#define GBUF   (128 * GPAD * 2)
#define GSTAGE (4 * GBUF)
#define GSM_TOTAL (2 * GSTAGE)

template <int SEL>   // 0 full; 1 pvcnt; 2 aumcnt; 3 aumcnt + gather/scatter
__device__ __forceinline__ void gemm_sp_body(
    const float* __restrict__ A, int lda,
    const float* __restrict__ B, int ldb,
    float* __restrict__ C, int ldc,
    const float* __restrict__ bias, int K, int act)
{
    extern __shared__ char gsm[];
    int cnt = 1 << 30;
    const int* ridx = nullptr;
    if (SEL == 1) cnt = d_pvcnt;
    if (SEL == 2) cnt = d_aumcnt;
    if (SEL == 3) { cnt = d_aumcnt; ridx = d_aumidx; }
    const int n0 = blockIdx.x * 128, m0 = blockIdx.y * 128;
    if (SEL != 0 && m0 >= cnt) return;

    const uint32_t sbase = smem_u32(gsm);
    const int tid = threadIdx.x;
    const int wid = tid >> 5, lane = tid & 31;

    const int lrow = tid >> 2, lseg = tid & 3;
    int grow = m0 + lrow;
    if (SEL != 0 && grow >= cnt) grow = cnt - 1;
    const int arow = ridx ? ridx[grow] : grow;
    const float* Aref = A + (size_t)arow * lda + lseg * 8;
    const float* Bref = B + (size_t)(n0 + lrow) * ldb + lseg * 8;

    float4 ra[2], rb[2];
    auto gload = [&](int k0) {
        ra[0] = *(const float4*)(Aref + k0);
        ra[1] = *(const float4*)(Aref + k0 + 4);
        rb[0] = *(const float4*)(Bref + k0);
        rb[1] = *(const float4*)(Bref + k0 + 4);
    };
    auto sstore = [&](int st) {
        char* p = gsm + st * GSTAGE + lrow * (GPAD * 2) + lseg * 16;
        uint32_t l0, l1, l2, l3;
        uint32_t h0 = pack_hi_lo(ra[0].x, ra[0].y, l0);
        uint32_t h1 = pack_hi_lo(ra[0].z, ra[0].w, l1);
        uint32_t h2 = pack_hi_lo(ra[1].x, ra[1].y, l2);
        uint32_t h3 = pack_hi_lo(ra[1].z, ra[1].w, l3);
        *(uint4*)(p + 0 * GBUF) = make_uint4(h0, h1, h2, h3);
        *(uint4*)(p + 1 * GBUF) = make_uint4(l0, l1, l2, l3);
        h0 = pack_hi_lo(rb[0].x, rb[0].y, l0);
        h1 = pack_hi_lo(rb[0].z, rb[0].w, l1);
        h2 = pack_hi_lo(rb[1].x, rb[1].y, l2);
        h3 = pack_hi_lo(rb[1].z, rb[1].w, l3);
        *(uint4*)(p + 2 * GBUF) = make_uint4(h0, h1, h2, h3);
        *(uint4*)(p + 3 * GBUF) = make_uint4(l0, l1, l2, l3);
    };

    float acc[2][4][4];
#pragma unroll
    for (int i = 0; i < 2; i++)
#pragma unroll
        for (int j = 0; j < 4; j++)
#pragma unroll
            for (int c = 0; c < 4; c++) acc[i][j][c] = 0.0f;

    const int wm0 = (wid >> 2) * 32;
    const int wn0 = (wid & 3) * 32;
    const int a_r = lane & 15;
    const int a_c8 = (lane >> 4) << 3;
    const int b_r = (lane & 7) + ((lane >> 4) << 3);
    const int b_c8 = ((lane >> 3) & 1) << 3;

    gload(0);
    const int NIT = K / 32;
    for (int it = 0; it < NIT; it++) {
        const int st = it & 1;
        sstore(st);
        __syncthreads();
        if (it + 1 < NIT) gload((it + 1) * 32);

        const uint32_t sAh = sbase + st * GSTAGE + 0 * GBUF;
        const uint32_t sAl = sbase + st * GSTAGE + 1 * GBUF;
        const uint32_t sBh = sbase + st * GSTAGE + 2 * GBUF;
        const uint32_t sBl = sbase + st * GSTAGE + 3 * GBUF;
#pragma unroll
        for (int ks = 0; ks < 2; ks++) {
            const int kb = ks * 16;
            uint32_t aH[2][4], aL[2][4], bH[4][2], bL[4][2];
#pragma unroll
            for (int mi = 0; mi < 2; mi++) {
                uint32_t off = (uint32_t)(wm0 + mi * 16 + a_r) * (GPAD * 2) + (kb + a_c8) * 2;
                ldm_x4(aH[mi][0], aH[mi][1], aH[mi][2], aH[mi][3], sAh + off);
                ldm_x4(aL[mi][0], aL[mi][1], aL[mi][2], aL[mi][3], sAl + off);
            }
#pragma unroll
            for (int p2 = 0; p2 < 2; p2++) {
                uint32_t off = (uint32_t)(wn0 + p2 * 16 + b_r) * (GPAD * 2) + (kb + b_c8) * 2;
                ldm_x4(bH[2 * p2][0], bH[2 * p2][1], bH[2 * p2 + 1][0], bH[2 * p2 + 1][1], sBh + off);
                ldm_x4(bL[2 * p2][0], bL[2 * p2][1], bL[2 * p2 + 1][0], bL[2 * p2 + 1][1], sBl + off);
            }
#pragma unroll
            for (int mi = 0; mi < 2; mi++)
#pragma unroll
                for (int ni = 0; ni < 4; ni++) {
                    mma_bf16(acc[mi][ni], aH[mi], bH[ni]);
                    mma_bf16(acc[mi][ni], aH[mi], bL[ni]);
                    mma_bf16(acc[mi][ni], aL[mi], bH[ni]);
                }
        }
        __syncthreads();
    }

#pragma unroll
    for (int mi = 0; mi < 2; mi++) {
#pragma unroll
        for (int half = 0; half < 2; half++) {
            int r = m0 + wm0 + mi * 16 + (lane >> 2) + half * 8;
            if (SEL != 0 && r >= cnt) continue;
            int crow = ridx ? ridx[r] : r;
            float* dd = C + (size_t)crow * ldc;
#pragma unroll
            for (int ni = 0; ni < 4; ni++) {
                int cc = n0 + wn0 + ni * 8 + (lane & 3) * 2;
                float v0 = acc[mi][ni][half * 2 + 0] + (bias ? bias[cc] : 0.f);
                float v1 = acc[mi][ni][half * 2 + 1] + (bias ? bias[cc + 1] : 0.f);
                if (act) { v0 = gelu_f(v0); v1 = gelu_f(v1); }
                *(float2*)(dd + cc) = make_float2(v0, v1);
            }
        }
    }
}

__global__ void __launch_bounds__(512) k_sp_hidgo(const float* w1, const float* b1) {
    gemm_sp_body<1>(d_featgo, D3n, w1, D3n, d_hidgo, MIDn, b1, D3n, 1);
}
__global__ void __launch_bounds__(512) k_sp_hidga(const float* w1, const float* b1) {
    gemm_sp_body<2>(d_featga, D3n, w1, D3n, d_hidga, MIDn, b1, D3n, 1);
}
__global__ void __launch_bounds__(512) k_sp_a2o(const float* tokens, const float* w) {
    gemm_sp_body<3>(tokens + Hn, Mn * Hn, w, Hn, d_a2o, Hn, (const float*)0, Hn, 0);
}
__global__ void __launch_bounds__(512) k_sp_o2a(const float* w) {
    gemm_sp_body<3>(d_omean, Hn, w, Hn, d_o2a, Hn, (const float*)0, Hn, 0);
}
__global__ void __launch_bounds__(512) k_sp_out(const float* w, const float* bb) {
    gemm_sp_body<0>(d_h1, Hn, w, Hn, d_h2, Hn, bb, Hn, 1);
}

// ---------------- factor split/transpose prep ----------------
__global__ void __launch_bounds__(256) k_prep_factors(const float* __restrict__ f) {
    __shared__ float t[32][33];
    int mr = blockIdx.z;
    int d0 = blockIdx.x * 32, h0 = blockIdx.y * 32;
    int tx = threadIdx.x, ty = threadIdx.y;
#pragma unroll
    for (int i = ty; i < 32; i += 8)
        t[i][tx] = f[((size_t)mr * 1025 + 1 + d0 + i) * Hn + h0 + tx];
    __syncthreads();
#pragma unroll
    for (int i = ty; i < 32; i += 8) {
        float x = t[tx][i];
        __nv_bfloat16 hi = __float2bfloat16(x);
        float lo = x - __bfloat162float(hi);
        size_t o = ((size_t)mr * Hn + h0 + i) * Hn + d0 + tx;
        d_fhi[o] = hi;
        d_flo[o] = __float2bfloat16(lo);
    }
}

// ---------------- LMF GEMM (mask-compacted, 512 thr, 3-stage cp.async) ----------------
#define ZKC   32
#define ZPAD  40
#define ZBUFB (128 * ZPAD * 2)
#define ZSTAGE (4 * ZBUFB)
#define ZSM_TOTAL (3 * ZSTAGE)

__global__ void __launch_bounds__(512) k_gemm_z_mma() {
    extern __shared__ char zsm[];
    const uint32_t sbase = smem_u32(zsm);
    const int tid = threadIdx.x;
    const int wid = tid >> 5, lane = tid & 31;
    const int h0 = blockIdx.x * 128;
    const int b0 = blockIdx.y * 128;
    const int mr = blockIdx.z;
    const int m = mr / Rn;
    const int cnt = d_ccnt[m];
    if (b0 >= cnt) return;

    const int lrow = tid >> 2;
    const int lseg = tid & 3;

    int grow = b0 + lrow;
    int gidx = d_cidx[m * Bn + (grow < cnt ? grow : cnt - 1)];

    const __nv_bfloat16* rowp[4];
    rowp[0] = d_ahi + ((size_t)m * Bn + gidx) * Hn + lseg * 8;
    rowp[1] = d_alo + ((size_t)m * Bn + gidx) * Hn + lseg * 8;
    rowp[2] = d_fhi + ((size_t)mr * Hn + h0 + lrow) * Hn + lseg * 8;
    rowp[3] = d_flo + ((size_t)mr * Hn + h0 + lrow) * Hn + lseg * 8;

    auto load_stage = [&](int st, int k0) {
        uint32_t dst = sbase + st * ZSTAGE + lrow * (ZPAD * 2) + lseg * 16;
#pragma unroll
        for (int bsel = 0; bsel < 4; bsel++)
            cp16(dst + bsel * ZBUFB, rowp[bsel] + k0);
    };

    float acc[2][4][4];
#pragma unroll
    for (int i = 0; i < 2; i++)
#pragma unroll
        for (int j = 0; j < 4; j++)
#pragma unroll
            for (int c = 0; c < 4; c++) acc[i][j][c] = 0.0f;

    const int wm0 = (wid >> 2) * 32;
    const int wn0 = (wid & 3) * 32;
    const int a_r = lane & 15;
    const int a_c8 = (lane >> 4) << 3;
    const int b_r = (lane & 7) + ((lane >> 4) << 3);
    const int b_c8 = ((lane >> 3) & 1) << 3;

    load_stage(0, 0);
    CP_COMMIT();
    load_stage(1, ZKC);
    CP_COMMIT();

    const int NIT = Hn / ZKC;
    for (int it = 0; it < NIT; it++) {
        CP_WAIT(1);
        __syncthreads();
        if (it + 2 < NIT) {
            load_stage((it + 2) % 3, (it + 2) * ZKC);
            CP_COMMIT();
        }
        const int st = it % 3;
        const uint32_t sAh = sbase + st * ZSTAGE + 0 * ZBUFB;
        const uint32_t sAl = sbase + st * ZSTAGE + 1 * ZBUFB;
        const uint32_t sBh = sbase + st * ZSTAGE + 2 * ZBUFB;
        const uint32_t sBl = sbase + st * ZSTAGE + 3 * ZBUFB;

#pragma unroll
        for (int ks = 0; ks < 2; ks++) {
            const int kb = ks * 16;
            uint32_t aH[2][4], aL[2][4], bH[4][2], bL[4][2];
#pragma unroll
            for (int mi = 0; mi < 2; mi++) {
                uint32_t off = (uint32_t)(wm0 + mi * 16 + a_r) * (ZPAD * 2) + (kb + a_c8) * 2;
                ldm_x4(aH[mi][0], aH[mi][1], aH[mi][2], aH[mi][3], sAh + off);
                ldm_x4(aL[mi][0], aL[mi][1], aL[mi][2], aL[mi][3], sAl + off);
            }
#pragma unroll
            for (int p = 0; p < 2; p++) {
                uint32_t off = (uint32_t)(wn0 + p * 16 + b_r) * (ZPAD * 2) + (kb + b_c8) * 2;
                ldm_x4(bH[2 * p][0], bH[2 * p][1], bH[2 * p + 1][0], bH[2 * p + 1][1], sBh + off);
                ldm_x4(bL[2 * p][0], bL[2 * p][1], bL[2 * p + 1][0], bL[2 * p + 1][1], sBl + off);
            }
#pragma unroll
            for (int mi = 0; mi < 2; mi++)
#pragma unroll
                for (int ni = 0; ni < 4; ni++) {
                    mma_bf16(acc[mi][ni], aH[mi], bH[ni]);
                    mma_bf16(acc[mi][ni], aH[mi], bL[ni]);
                    mma_bf16(acc[mi][ni], aL[mi], bH[ni]);
                }
        }
        __syncthreads();
    }

#pragma unroll
    for (int mi = 0; mi < 2; mi++) {
#pragma unroll
        for (int half = 0; half < 2; half++) {
            int r = b0 + wm0 + mi * 16 + (lane >> 2) + half * 8;
            if (r >= cnt) continue;
            int br = d_cidx[m * Bn + r];
            float* dd = d_zbuf + ((size_t)br * (Mn * Rn) + mr) * Hn + h0;
#pragma unroll
            for (int ni = 0; ni < 4; ni++) {
                int cc = wn0 + ni * 8 + (lane & 3) * 2;
                *(float2*)(dd + cc) = make_float2(acc[mi][ni][half * 2 + 0], acc[mi][ni][half * 2 + 1]);
            }
        }
    }
}

// ---------------- feat builders (compacted) ----------------
__global__ void k_feat_go(const float* tokens, const float* lnw, const float* lnb) {
    int i = blockIdx.x;
    if (i >= d_pvcnt) return;
    int row = d_pvidx[i];
    int b = row / 3, j = row - 3 * b;
    int oj = (j == 0) ? 0 : (j + 1);
    const float* tok = tokens + (size_t)b * Mn * Hn;
    __shared__ float sf[D3n];
    float s = 0.f, q = 0.f;
    for (int k = threadIdx.x; k < Hn; k += blockDim.x) {
        float t = tok[oj * Hn + k];
        float sv = tok[Hn + k];
        float dv = fabsf(t - sv);
        sf[k] = t; sf[Hn + k] = sv; sf[2 * Hn + k] = dv;
        s += t + sv + dv; q += t * t + sv * sv + dv * dv;
    }
    float2 rr = blkSum2(s, q);
    float mean = rr.x / D3n;
    float var = rr.y / D3n - mean * mean;
    float rstd = rsqrtf(var + 1e-5f);
    float* o = d_featgo + (size_t)i * D3n;
    for (int k = threadIdx.x; k < D3n; k += blockDim.x)
        o[k] = (sf[k] - mean) * rstd * lnw[k] + lnb[k];
}

__global__ void k_feat_ga(const float* tokens, const float* lnw, const float* lnb) {
    int i = blockIdx.x;
    if (i >= d_aumcnt) return;
    int b = d_aumidx[i];
    const float* tok = tokens + (size_t)b * Mn * Hn;
    __shared__ float sf[D3n];
    float s = 0.f, q = 0.f;
    for (int k = threadIdx.x; k < Hn; k += blockDim.x) {
        float t = tok[Hn + k];
        float sv = d_omean[(size_t)b * Hn + k];
        float dv = fabsf(t - sv);
        sf[k] = t; sf[Hn + k] = sv; sf[2 * Hn + k] = dv;
        s += t + sv + dv; q += t * t + sv * sv + dv * dv;
    }
    float2 rr = blkSum2(s, q);
    float mean = rr.x / D3n;
    float var = rr.y / D3n - mean * mean;
    float rstd = rsqrtf(var + 1e-5f);
    float* o = d_featga + (size_t)i * D3n;
    for (int k = threadIdx.x; k < D3n; k += blockDim.x)
        o[k] = (sf[k] - mean) * rstd * lnw[k] + lnb[k];
}

// ---------------- gate tails (compacted) ----------------
__global__ void k_gate_go(const float* w2, const float* b2) {
    int i = blockIdx.x;
    if (i >= d_pvcnt) return;
    const float* hr = d_hidgo + (size_t)i * MIDn;
    float v = 0.f;
    for (int k = threadIdx.x; k < MIDn; k += blockDim.x) v += hr[k] * w2[k];
    float2 rr = blkSum2(v, 0.f);
    if (threadIdx.x == 0) d_ggo[d_pvidx[i]] = 1.0f / (1.0f + expf(-(rr.x + b2[0])));
}
__global__ void k_gate_ga(const float* w2, const float* b2) {
    int i = blockIdx.x;
    if (i >= d_aumcnt) return;
    const float* hr = d_hidga + (size_t)i * MIDn;
    float v = 0.f;
    for (int k = threadIdx.x; k < MIDn; k += blockDim.x) v += hr[k] * w2[k];
    float2 rr = blkSum2(v, 0.f);
    if (threadIdx.x == 0) d_gavec[d_aumidx[i]] = 1.0f / (1.0f + expf(-(rr.x + b2[0])));
}

// ---------------- others_new ----------------
__global__ void k_others_new(const float* tokens, const float* lnw, const float* lnb) {
    int row = blockIdx.x;
    int b = row / 3, j = row - 3 * b;
    int oj = (j == 0) ? 0 : (j + 1);
    const float* tok = tokens + (size_t)b * Mn * Hn;
    int moj = d_mask[b * Mn + oj], ma = d_mask[b * Mn + 1];
    float* o = d_onew + (size_t)row * Hn;
    if (moj && ma) {
        __shared__ float sx[Hn];
        float g = d_ggo[row];
        float s = 0.f, q = 0.f;
        for (int k = threadIdx.x; k < Hn; k += blockDim.x) {
            float x = tok[oj * Hn + k] + g * d_a2o[(size_t)b * Hn + k];
            sx[k] = x; s += x; q += x * x;
        }
        float2 rr = blkSum2(s, q);
        float mean = rr.x / Hn;
        float var = rr.y / Hn - mean * mean;
        float rstd = rsqrtf(var + 1e-5f);
        for (int k = threadIdx.x; k < Hn; k += blockDim.x)
            o[k] = (sx[k] - mean) * rstd * lnw[k] + lnb[k];
    } else {
        float mf = moj ? 1.0f : 0.0f;
        for (int k = threadIdx.x; k < Hn; k += blockDim.x)
            o[k] = tok[oj * Hn + k] * mf;
    }
}

__global__ void k_omean() {
    int idx = blockIdx.x * 256 + threadIdx.x;
    int b = idx >> 10, h = idx & 1023;
    float m0 = d_mask[b * 4 + 0] ? 1.f : 0.f;
    float m2 = d_mask[b * 4 + 2] ? 1.f : 0.f;
    float m3 = d_mask[b * 4 + 3] ? 1.f : 0.f;
    float denom = fmaxf(1.0f, m0 + m2 + m3);
    size_t base = (size_t)b * 3 * Hn;
    float sum = d_onew[base + h] + d_onew[base + Hn + h] + d_onew[base + 2 * Hn + h];
    d_omean[idx] = sum / denom;
}

// ---------------- mixed assembly (writes bf16 hi/lo splits directly) ----------------
__device__ __forceinline__ void split_store(int m, int b, int k, float v) {
    __nv_bfloat16 hi = __float2bfloat16(v);
    float lo = v - __bfloat162float(hi);
    size_t o = ((size_t)m * Bn + b) * Hn + k;
    d_ahi[o] = hi;
    d_alo[o] = __float2bfloat16(lo);
}

__global__ void k_mixed(const float* tokens, const float* lnw, const float* lnb) {
    int b = blockIdx.x;
    const float* tok = tokens + (size_t)b * Mn * Hn;
    int m0 = d_mask[b * 4], m1 = d_mask[b * 4 + 1], m2 = d_mask[b * 4 + 2], m3 = d_mask[b * 4 + 3];
    int aum = m1 && (m0 || m2 || m3);
    if (aum) {
        __shared__ float sx[Hn];
        float g = d_gavec[b];
        float s = 0.f, q = 0.f;
        for (int k = threadIdx.x; k < Hn; k += blockDim.x) {
            float x = tok[Hn + k] + g * d_o2a[(size_t)b * Hn + k];
            sx[k] = x; s += x; q += x * x;
        }
        float2 rr = blkSum2(s, q);
        float mean = rr.x / Hn;
        float var = rr.y / Hn - mean * mean;
        float rstd = rsqrtf(var + 1e-5f);
        for (int k = threadIdx.x; k < Hn; k += blockDim.x)
            split_store(1, b, k, (sx[k] - mean) * rstd * lnw[k] + lnb[k]);
    } else {
        float f = m1 ? 1.0f : 0.0f;
        for (int k = threadIdx.x; k < Hn; k += blockDim.x)
            split_store(1, b, k, tok[Hn + k] * f);
    }
    float f0 = m0 ? 1.f : 0.f, f2 = m2 ? 1.f : 0.f, f3 = m3 ? 1.f : 0.f;
    size_t ob = (size_t)b * 3 * Hn;
    for (int k = threadIdx.x; k < Hn; k += blockDim.x) {
        split_store(0, b, k, d_onew[ob + k] * f0);
        split_store(2, b, k, d_onew[ob + Hn + k] * f2);
        split_store(3, b, k, d_onew[ob + 2 * Hn + k] * f3);
    }
}

// ---------------- rank product + weighted sum + LN (fused) ----------------
__global__ void k_combine_ln(const float* rank_w, const float* lmf_bias,
                             const float* __restrict__ factors,
                             const float* lnw, const float* lnb) {
    int b = blockIdx.x;
    const unsigned char* mk = d_mask + b * 4;
    bool m0 = mk[0], m1 = mk[1], m2 = mk[2], m3 = mk[3];
    __shared__ float sx[Hn];
    float s = 0.f, q = 0.f;
    for (int h = threadIdx.x; h < Hn; h += blockDim.x) {
        const float* zb = d_zbuf + (size_t)b * (Mn * Rn * Hn) + h;
        float acc = 0.f;
#pragma unroll
        for (int r = 0; r < Rn; r++) {
            float p = rank_w[r];
            if (m0) p *= zb[(0 * Rn + r) * Hn] + factors[((size_t)(0 * Rn + r) * 1025) * Hn + h];
            if (m1) p *= zb[(1 * Rn + r) * Hn] + factors[((size_t)(1 * Rn + r) * 1025) * Hn + h];
            if (m2) p *= zb[(2 * Rn + r) * Hn] + factors[((size_t)(2 * Rn + r) * 1025) * Hn + h];
            if (m3) p *= zb[(3 * Rn + r) * Hn] + factors[((size_t)(3 * Rn + r) * 1025) * Hn + h];
            acc += p;
        }
        float v = acc + lmf_bias[h];
        sx[h] = v;
        s += v; q += v * v;
    }
    float2 rr = blkSum2(s, q);
    float mean = rr.x / Hn;
    float var = rr.y / Hn - mean * mean;
    float rstd = rsqrtf(var + 1e-5f);
    float* o = d_h1 + (size_t)b * Hn;
    for (int h = threadIdx.x; h < Hn; h += blockDim.x)
        o[h] = (sx[h] - mean) * rstd * lnw[h] + lnb[h];
}

// ---------------- final LayerNorm ----------------
__global__ void k_ln_out(const float* w, const float* bb, float* out) {
    const float* x = d_h2 + (size_t)blockIdx.x * Hn;
    float* y = out + (size_t)blockIdx.x * Hn;
    float s = 0.f, q = 0.f;
    for (int k = threadIdx.x; k < Hn; k += blockDim.x) { float v = x[k]; s += v; q += v * v; }
    float2 rr = blkSum2(s, q);
    float mean = rr.x / Hn;
    float var = rr.y / Hn - mean * mean;
    float rstd = rsqrtf(var + 1e-5f);
    for (int k = threadIdx.x; k < Hn; k += blockDim.x)
        y[k] = (x[k] - mean) * rstd * w[k] + bb[k];
}

// ---------------- launch ----------------
extern "C" void kernel_launch(void* const* d_in, const int* in_sizes, int n_in,
                              void* d_out, int out_size) {
    const float* tokens   = (const float*)d_in[0];
    const void*  maskraw  = d_in[1];
    const float* ln_go_w  = (const float*)d_in[2];
    const float* ln_go_b  = (const float*)d_in[3];
    const float* go_w1    = (const float*)d_in[4];
    const float* go_b1    = (const float*)d_in[5];
    const float* go_w2    = (const float*)d_in[6];
    const float* go_b2    = (const float*)d_in[7];
    const float* ln_ga_w  = (const float*)d_in[8];
    const float* ln_ga_b  = (const float*)d_in[9];
    const float* ga_w1    = (const float*)d_in[10];
    const float* ga_b1    = (const float*)d_in[11];
    const float* ga_w2    = (const float*)d_in[12];
    const float* ga_b2    = (const float*)d_in[13];
    const float* a2o_w    = (const float*)d_in[14];
    const float* o2a_w    = (const float*)d_in[15];
    const float* ln_o_w   = (const float*)d_in[16];
    const float* ln_o_b   = (const float*)d_in[17];
    const float* ln_a_w   = (const float*)d_in[18];
    const float* ln_a_b   = (const float*)d_in[19];
    const float* factors  = (const float*)d_in[20];
    const float* rank_w   = (const float*)d_in[21];
    const float* lmf_bias = (const float*)d_in[22];
    const float* out_ln1w = (const float*)d_in[23];
    const float* out_ln1b = (const float*)d_in[24];
    const float* out_w    = (const float*)d_in[25];
    const float* out_b    = (const float*)d_in[26];
    const float* out_ln2w = (const float*)d_in[27];
    const float* out_ln2b = (const float*)d_in[28];
    float* out = (float*)d_out;

    static cudaStream_t s1 = nullptr, s2 = nullptr;
    static cudaEvent_t evStart, evPF, evCmp, evA2O, evOM, evO2A;
    if (!s1) {
        cudaFuncSetAttribute(k_gemm_z_mma, cudaFuncAttributeMaxDynamicSharedMemorySize, ZSM_TOTAL);
        cudaFuncSetAttribute(k_sp_hidgo, cudaFuncAttributeMaxDynamicSharedMemorySize, GSM_TOTAL);
        cudaFuncSetAttribute(k_sp_hidga, cudaFuncAttributeMaxDynamicSharedMemorySize, GSM_TOTAL);
        cudaFuncSetAttribute(k_sp_a2o,   cudaFuncAttributeMaxDynamicSharedMemorySize, GSM_TOTAL);
        cudaFuncSetAttribute(k_sp_o2a,   cudaFuncAttributeMaxDynamicSharedMemorySize, GSM_TOTAL);
        cudaFuncSetAttribute(k_sp_out,   cudaFuncAttributeMaxDynamicSharedMemorySize, GSM_TOTAL);
        cudaStreamCreateWithFlags(&s1, cudaStreamNonBlocking);
        cudaStreamCreateWithFlags(&s2, cudaStreamNonBlocking);
        cudaEventCreateWithFlags(&evStart, cudaEventDisableTiming);
        cudaEventCreateWithFlags(&evPF,    cudaEventDisableTiming);
        cudaEventCreateWithFlags(&evCmp,   cudaEventDisableTiming);
        cudaEventCreateWithFlags(&evA2O,   cudaEventDisableTiming);
        cudaEventCreateWithFlags(&evOM,    cudaEventDisableTiming);
        cudaEventCreateWithFlags(&evO2A,   cudaEventDisableTiming);
    }

    // fork: factor prep runs concurrently with the whole gate pipeline
    cudaEventRecord(evStart, 0);
    cudaStreamWaitEvent(s1, evStart, 0);
    k_prep_factors<<<dim3(32, 32, Mn * Rn), dim3(32, 8), 0, s1>>>(factors);
    cudaEventRecord(evPF, s1);

    k_mask_norm<<<1, 256>>>(maskraw);
    k_compact<<<Mn, 1024>>>();
    k_compact_pv<<<1, 1024>>>();
    k_compact_aum<<<1, 1024>>>();
    cudaEventRecord(evCmp, 0);

    // fork: a2o concurrent with the gate-others chain
    cudaStreamWaitEvent(s2, evCmp, 0);
    k_sp_a2o<<<dim3(Hn / 128, Bn / 128), 512, GSM_TOTAL, s2>>>(tokens, a2o_w);
    cudaEventRecord(evA2O, s2);

    k_feat_go<<<3 * Bn, 256>>>(tokens, ln_go_w, ln_go_b);
    k_sp_hidgo<<<dim3(MIDn / 128, 3 * Bn / 128), 512, GSM_TOTAL>>>(go_w1, go_b1);
    k_gate_go<<<3 * Bn, 256>>>(go_w2, go_b2);
    cudaStreamWaitEvent(0, evA2O, 0);
    k_others_new<<<3 * Bn, 256>>>(tokens, ln_o_w, ln_o_b);
    k_omean<<<Bn * Hn / 256, 256>>>();
    cudaEventRecord(evOM, 0);

    // fork: o2a concurrent with the gate-audio chain
    cudaStreamWaitEvent(s2, evOM, 0);
    k_sp_o2a<<<dim3(Hn / 128, Bn / 128), 512, GSM_TOTAL, s2>>>(o2a_w);
    cudaEventRecord(evO2A, s2);

    k_feat_ga<<<Bn, 256>>>(tokens, ln_ga_w, ln_ga_b);
    k_sp_hidga<<<dim3(MIDn / 128, Bn / 128), 512, GSM_TOTAL>>>(ga_w1, ga_b1);
    k_gate_ga<<<Bn, 256>>>(ga_w2, ga_b2);
    cudaStreamWaitEvent(0, evO2A, 0);
    k_mixed<<<Bn, 256>>>(tokens, ln_a_w, ln_a_b);

    cudaStreamWaitEvent(0, evPF, 0);
    k_gemm_z_mma<<<dim3(Hn / 128, Bn / 128, Mn * Rn), 512, ZSM_TOTAL>>>();
    k_combine_ln<<<Bn, 256>>>(rank_w, lmf_bias, factors, out_ln1w, out_ln1b);
    k_sp_out<<<dim3(Hn / 128, Bn / 128), 512, GSM_TOTAL>>>(out_w, out_b);
    k_ln_out<<<Bn, 256>>>(out_ln2w, out_ln2b, out);
}

// round 8
// speedup vs baseline: 4.4048x; 1.0299x over previous
#include <cuda_runtime.h>
#include <cuda_bf16.h>
#include <math.h>
#include <cstdint>

#define Bn   4096
#define Mn   4
#define Hn   1024
#define Rn   10
#define MIDn 512
#define D3n  3072

// ---------------- scratch (__device__ globals: alloc-free) ----------------
__device__ float d_featgo[3 * Bn * D3n];
__device__ float d_hidgo[3 * Bn * MIDn];
__device__ float d_ggo[3 * Bn];
__device__ float d_a2o[Bn * Hn];
__device__ float d_onew[Bn * 3 * Hn];
__device__ float d_omean[Bn * Hn];
__device__ float d_featga[Bn * D3n];
__device__ float d_hidga[Bn * MIDn];
__device__ float d_gavec[Bn];
__device__ float d_o2a[Bn * Hn];
__device__ float d_zbuf[167772160];             // B*M*R*H fp32
__device__ float d_h1[Bn * Hn];
__device__ float d_h2[Bn * Hn];
__device__ unsigned char d_mask[Bn * Mn];
__device__ int d_cidx[Mn * Bn];                 // per-m compacted valid-b lists (z GEMM)
__device__ int d_ccnt[Mn];
__device__ int d_pvidx[3 * Bn];                 // pair-valid (b,j) row list
__device__ int d_pvcnt;
__device__ int d_aumidx[Bn];                    // aum b list
__device__ int d_aumcnt;
// bf16-split operands for the LMF GEMM
__device__ __nv_bfloat16 d_ahi[Mn * Bn * Hn];      // [m][b][h]
__device__ __nv_bfloat16 d_alo[Mn * Bn * Hn];
__device__ __nv_bfloat16 d_fhi[Mn * Rn * Hn * Hn]; // [mr][h][d] (K-contiguous)
__device__ __nv_bfloat16 d_flo[Mn * Rn * Hn * Hn];

// ---------------- generic helpers ----------------
__device__ __forceinline__ float gelu_f(float x) {
    return 0.5f * x * (1.0f + erff(x * 0.70710678118654752f));
}
__device__ __forceinline__ float2 blkSum2(float a, float b) {
    __shared__ float sa[32], sb[32];
    __shared__ float ra, rb;
    int lane = threadIdx.x & 31, w = threadIdx.x >> 5;
#pragma unroll
    for (int o = 16; o > 0; o >>= 1) {
        a += __shfl_xor_sync(0xffffffffu, a, o);
        b += __shfl_xor_sync(0xffffffffu, b, o);
    }
    if (lane == 0) { sa[w] = a; sb[w] = b; }
    __syncthreads();
    if (threadIdx.x == 0) {
        float x = 0.f, y = 0.f;
        int nw = blockDim.x >> 5;
        for (int i = 0; i < nw; i++) { x += sa[i]; y += sb[i]; }
        ra = x; rb = y;
    }
    __syncthreads();
    return make_float2(ra, rb);
}

// ---------------- mma.sync helpers ----------------
__device__ __forceinline__ uint32_t smem_u32(const void* p) {
    uint32_t a;
    asm("{ .reg .u64 t; cvta.to.shared.u64 t, %1; cvt.u32.u64 %0, t; }" : "=r"(a) : "l"(p));
    return a;
}
__device__ __forceinline__ void ldm_x4(uint32_t& r0, uint32_t& r1, uint32_t& r2, uint32_t& r3,
                                       uint32_t addr) {
    asm volatile("ldmatrix.sync.aligned.m8n8.x4.shared.b16 {%0,%1,%2,%3}, [%4];"
                 : "=r"(r0), "=r"(r1), "=r"(r2), "=r"(r3) : "r"(addr));
}
__device__ __forceinline__ void mma_bf16(float* c, const uint32_t* a, const uint32_t* b) {
    asm volatile("mma.sync.aligned.m16n8k16.row.col.f32.bf16.bf16.f32 "
                 "{%0,%1,%2,%3}, {%4,%5,%6,%7}, {%8,%9}, {%0,%1,%2,%3};"
                 : "+f"(c[0]), "+f"(c[1]), "+f"(c[2]), "+f"(c[3])
                 : "r"(a[0]), "r"(a[1]), "r"(a[2]), "r"(a[3]), "r"(b[0]), "r"(b[1]));
}
__device__ __forceinline__ void cp16(uint32_t dst, const void* src) {
    asm volatile("cp.async.cg.shared.global [%0], [%1], 16;" :: "r"(dst), "l"(src));
}
#define CP_COMMIT() asm volatile("cp.async.commit_group;" ::: "memory")
#define CP_WAIT(n)  asm volatile("cp.async.wait_group %0;" :: "n"(n) : "memory")

__device__ __forceinline__ uint32_t pack_hi_lo(float x, float y, uint32_t& lo) {
    __nv_bfloat16 hx = __float2bfloat16(x);
    __nv_bfloat16 hy = __float2bfloat16(y);
    float lxf = x - __bfloat162float(hx);
    float lyf = y - __bfloat162float(hy);
    __nv_bfloat162 hv = __halves2bfloat162(hx, hy);
    __nv_bfloat162 lv = __halves2bfloat162(__float2bfloat16(lxf), __float2bfloat16(lyf));
    lo = *reinterpret_cast<uint32_t*>(&lv);
    return *reinterpret_cast<uint32_t*>(&hv);
}

// ---------------- fused mask sniff + all compactions (6 blocks) ----------------
// block 0..3: per-m valid-b lists; block 4: pair-valid rows; block 5: aum list.
__global__ void __launch_bounds__(1024) k_mask_compact(const void* raw) {
    __shared__ int ok32s, okfs;
    if (threadIdx.x == 0) { ok32s = 1; okfs = 1; }
    __syncthreads();
    const int* pi = (const int*)raw;
    const float* pf = (const float*)raw;
    const unsigned char* pb = (const unsigned char*)raw;
    int lok32 = 1, lokf = 1;
    for (int i = threadIdx.x; i < 4096; i += 1024) {
        int v = pi[i];
        if (v != 0 && v != 1) lok32 = 0;
        float f = pf[i];
        if (f != 0.0f && f != 1.0f) lokf = 0;
    }
    if (!lok32) ok32s = 0;     // benign 0-write race
    if (!lokf)  okfs = 0;
    __syncthreads();
    const int ok32 = ok32s, okf = okfs;
    auto maskat = [&](int i) -> int {
        if (ok32) return pi[i] != 0;
        if (okf)  return pf[i] != 0.0f;
        return pb[i] != 0;
    };

    const int blk = blockIdx.x;
    if (blk == 0) {
        for (int i = threadIdx.x; i < Bn * Mn; i += 1024)
            d_mask[i] = (unsigned char)maskat(i);
    }

    int* out_idx;
    int* out_cnt;
    int nitems;
    if (blk < 4)      { out_idx = d_cidx + blk * Bn; out_cnt = d_ccnt + blk; nitems = Bn; }
    else if (blk == 4){ out_idx = d_pvidx;           out_cnt = &d_pvcnt;     nitems = 3 * Bn; }
    else              { out_idx = d_aumidx;          out_cnt = &d_aumcnt;    nitems = Bn; }

    __shared__ int warp_off[32];
    __shared__ int chunk_base;
    if (threadIdx.x == 0) chunk_base = 0;
    __syncthreads();
    int lane = threadIdx.x & 31, w = threadIdx.x >> 5;
    for (int c = 0; c < nitems; c += 1024) {
        int i = c + threadIdx.x;
        int v;
        if (blk < 4) {
            v = maskat(i * Mn + blk);
        } else if (blk == 4) {
            int b = i / 3, j = i - 3 * b;
            int oj = (j == 0) ? 0 : (j + 1);
            v = maskat(b * 4 + oj) && maskat(b * 4 + 1);
        } else {
            v = maskat(i * 4 + 1) && (maskat(i * 4) | maskat(i * 4 + 2) | maskat(i * 4 + 3));
        }
        unsigned bal = __ballot_sync(0xffffffffu, v);
        int pre = __popc(bal & ((1u << lane) - 1u));
        if (lane == 31) warp_off[w] = __popc(bal);
        __syncthreads();
        if (threadIdx.x < 32) {
            int val = warp_off[threadIdx.x];
#pragma unroll
            for (int o = 1; o < 32; o <<= 1) {
                int t = __shfl_up_sync(0xffffffffu, val, o);
                if ((int)threadIdx.x >= o) val += t;
            }
            warp_off[threadIdx.x] = val;
        }
        __syncthreads();
        int base = chunk_base + (w ? warp_off[w - 1] : 0) + pre;
        if (v) out_idx[base] = i;
        __syncthreads();
        if (threadIdx.x == 0) chunk_base += warp_off[31];
        __syncthreads();
    }
    if (threadIdx.x == 0) *out_cnt = chunk_base;
}

// ---------------- generic fp32 -> bf16-split mma GEMM (512 thr, 16 warps) ----------------
#define GPAD   40
#define GBUF   (128 * GPAD * 2)
#define GSTAGE (4 * GBUF)
#define GSM_TOTAL (2 * GSTAGE)

template <int SEL>   // 0 full; 1 pvcnt; 2 aumcnt; 3 aumcnt + gather/scatter
__device__ __forceinline__ void gemm_sp_body(
    const float* __restrict__ A, int lda,
    const float* __restrict__ B, int ldb,
    float* __restrict__ C, int ldc,
    const float* __restrict__ bias, int K, int act)
{
    extern __shared__ char gsm[];
    int cnt = 1 << 30;
    const int* ridx = nullptr;
    if (SEL == 1) cnt = d_pvcnt;
    if (SEL == 2) cnt = d_aumcnt;
    if (SEL == 3) { cnt = d_aumcnt; ridx = d_aumidx; }
    const int n0 = blockIdx.x * 128, m0 = blockIdx.y * 128;
    if (SEL != 0 && m0 >= cnt) return;

    const uint32_t sbase = smem_u32(gsm);
    const int tid = threadIdx.x;
    const int wid = tid >> 5, lane = tid & 31;

    const int lrow = tid >> 2, lseg = tid & 3;
    int grow = m0 + lrow;
    if (SEL != 0 && grow >= cnt) grow = cnt - 1;
    const int arow = ridx ? ridx[grow] : grow;
    const float* Aref = A + (size_t)arow * lda + lseg * 8;
    const float* Bref = B + (size_t)(n0 + lrow) * ldb + lseg * 8;

    float4 ra[2], rb[2];
    auto gload = [&](int k0) {
        ra[0] = *(const float4*)(Aref + k0);
        ra[1] = *(const float4*)(Aref + k0 + 4);
        rb[0] = *(const float4*)(Bref + k0);
        rb[1] = *(const float4*)(Bref + k0 + 4);
    };
    auto sstore = [&](int st) {
        char* p = gsm + st * GSTAGE + lrow * (GPAD * 2) + lseg * 16;
        uint32_t l0, l1, l2, l3;
        uint32_t h0 = pack_hi_lo(ra[0].x, ra[0].y, l0);
        uint32_t h1 = pack_hi_lo(ra[0].z, ra[0].w, l1);
        uint32_t h2 = pack_hi_lo(ra[1].x, ra[1].y, l2);
        uint32_t h3 = pack_hi_lo(ra[1].z, ra[1].w, l3);
        *(uint4*)(p + 0 * GBUF) = make_uint4(h0, h1, h2, h3);
        *(uint4*)(p + 1 * GBUF) = make_uint4(l0, l1, l2, l3);
        h0 = pack_hi_lo(rb[0].x, rb[0].y, l0);
        h1 = pack_hi_lo(rb[0].z, rb[0].w, l1);
        h2 = pack_hi_lo(rb[1].x, rb[1].y, l2);
        h3 = pack_hi_lo(rb[1].z, rb[1].w, l3);
        *(uint4*)(p + 2 * GBUF) = make_uint4(h0, h1, h2, h3);
        *(uint4*)(p + 3 * GBUF) = make_uint4(l0, l1, l2, l3);
    };

    float acc[2][4][4];
#pragma unroll
    for (int i = 0; i < 2; i++)
#pragma unroll
        for (int j = 0; j < 4; j++)
#pragma unroll
            for (int c = 0; c < 4; c++) acc[i][j][c] = 0.0f;

    const int wm0 = (wid >> 2) * 32;
    const int wn0 = (wid & 3) * 32;
    const int a_r = lane & 15;
    const int a_c8 = (lane >> 4) << 3;
    const int b_r = (lane & 7) + ((lane >> 4) << 3);
    const int b_c8 = ((lane >> 3) & 1) << 3;

    gload(0);
    const int NIT = K / 32;
    for (int it = 0; it < NIT; it++) {
        const int st = it & 1;
        sstore(st);
        __syncthreads();
        if (it + 1 < NIT) gload((it + 1) * 32);

        const uint32_t sAh = sbase + st * GSTAGE + 0 * GBUF;
        const uint32_t sAl = sbase + st * GSTAGE + 1 * GBUF;
        const uint32_t sBh = sbase + st * GSTAGE + 2 * GBUF;
        const uint32_t sBl = sbase + st * GSTAGE + 3 * GBUF;
#pragma unroll
        for (int ks = 0; ks < 2; ks++) {
            const int kb = ks * 16;
            uint32_t aH[2][4], aL[2][4], bH[4][2], bL[4][2];
#pragma unroll
            for (int mi = 0; mi < 2; mi++) {
                uint32_t off = (uint32_t)(wm0 + mi * 16 + a_r) * (GPAD * 2) + (kb + a_c8) * 2;
                ldm_x4(aH[mi][0], aH[mi][1], aH[mi][2], aH[mi][3], sAh + off);
                ldm_x4(aL[mi][0], aL[mi][1], aL[mi][2], aL[mi][3], sAl + off);
            }
#pragma unroll
            for (int p2 = 0; p2 < 2; p2++) {
                uint32_t off = (uint32_t)(wn0 + p2 * 16 + b_r) * (GPAD * 2) + (kb + b_c8) * 2;
                ldm_x4(bH[2 * p2][0], bH[2 * p2][1], bH[2 * p2 + 1][0], bH[2 * p2 + 1][1], sBh + off);
                ldm_x4(bL[2 * p2][0], bL[2 * p2][1], bL[2 * p2 + 1][0], bL[2 * p2 + 1][1], sBl + off);
            }
            // term-major sweeps: 8 independent MMAs between accumulator reuses
#pragma unroll
            for (int mi = 0; mi < 2; mi++)
#pragma unroll
                for (int ni = 0; ni < 4; ni++)
                    mma_bf16(acc[mi][ni], aH[mi], bH[ni]);
#pragma unroll
            for (int mi = 0; mi < 2; mi++)
#pragma unroll
                for (int ni = 0; ni < 4; ni++)
                    mma_bf16(acc[mi][ni], aH[mi], bL[ni]);
#pragma unroll
            for (int mi = 0; mi < 2; mi++)
#pragma unroll
                for (int ni = 0; ni < 4; ni++)
                    mma_bf16(acc[mi][ni], aL[mi], bH[ni]);
        }
        __syncthreads();
    }

#pragma unroll
    for (int mi = 0; mi < 2; mi++) {
#pragma unroll
        for (int half = 0; half < 2; half++) {
            int r = m0 + wm0 + mi * 16 + (lane >> 2) + half * 8;
            if (SEL != 0 && r >= cnt) continue;
            int crow = ridx ? ridx[r] : r;
            float* dd = C + (size_t)crow * ldc;
#pragma unroll
            for (int ni = 0; ni < 4; ni++) {
                int cc = n0 + wn0 + ni * 8 + (lane & 3) * 2;
                float v0 = acc[mi][ni][half * 2 + 0] + (bias ? bias[cc] : 0.f);
                float v1 = acc[mi][ni][half * 2 + 1] + (bias ? bias[cc + 1] : 0.f);
                if (act) { v0 = gelu_f(v0); v1 = gelu_f(v1); }
                *(float2*)(dd + cc) = make_float2(v0, v1);
            }
        }
    }
}

__global__ void __launch_bounds__(512) k_sp_hidgo(const float* w1, const float* b1) {
    gemm_sp_body<1>(d_featgo, D3n, w1, D3n, d_hidgo, MIDn, b1, D3n, 1);
}
__global__ void __launch_bounds__(512) k_sp_hidga(const float* w1, const float* b1) {
    gemm_sp_body<2>(d_featga, D3n, w1, D3n, d_hidga, MIDn, b1, D3n, 1);
}
__global__ void __launch_bounds__(512) k_sp_a2o(const float* tokens, const float* w) {
    gemm_sp_body<3>(tokens + Hn, Mn * Hn, w, Hn, d_a2o, Hn, (const float*)0, Hn, 0);
}
__global__ void __launch_bounds__(512) k_sp_o2a(const float* w) {
    gemm_sp_body<3>(d_omean, Hn, w, Hn, d_o2a, Hn, (const float*)0, Hn, 0);
}
__global__ void __launch_bounds__(512) k_sp_out(const float* w, const float* bb) {
    gemm_sp_body<0>(d_h1, Hn, w, Hn, d_h2, Hn, bb, Hn, 1);
}

// ---------------- factor split/transpose prep ----------------
__global__ void __launch_bounds__(256) k_prep_factors(const float* __restrict__ f) {
    __shared__ float t[32][33];
    int mr = blockIdx.z;
    int d0 = blockIdx.x * 32, h0 = blockIdx.y * 32;
    int tx = threadIdx.x, ty = threadIdx.y;
#pragma unroll
    for (int i = ty; i < 32; i += 8)
        t[i][tx] = f[((size_t)mr * 1025 + 1 + d0 + i) * Hn + h0 + tx];
    __syncthreads();
#pragma unroll
    for (int i = ty; i < 32; i += 8) {
        float x = t[tx][i];
        __nv_bfloat16 hi = __float2bfloat16(x);
        float lo = x - __bfloat162float(hi);
        size_t o = ((size_t)mr * Hn + h0 + i) * Hn + d0 + tx;
        d_fhi[o] = hi;
        d_flo[o] = __float2bfloat16(lo);
    }
}

// ---------------- LMF GEMM (mask-compacted, 512 thr, 3-stage cp.async) ----------------
#define ZKC   32
#define ZPAD  40
#define ZBUFB (128 * ZPAD * 2)
#define ZSTAGE (4 * ZBUFB)
#define ZSM_TOTAL (3 * ZSTAGE)

__global__ void __launch_bounds__(512) k_gemm_z_mma() {
    extern __shared__ char zsm[];
    const uint32_t sbase = smem_u32(zsm);
    const int tid = threadIdx.x;
    const int wid = tid >> 5, lane = tid & 31;
    const int h0 = blockIdx.x * 128;
    const int b0 = blockIdx.y * 128;
    const int mr = blockIdx.z;
    const int m = mr / Rn;
    const int cnt = d_ccnt[m];
    if (b0 >= cnt) return;

    const int lrow = tid >> 2;
    const int lseg = tid & 3;

    int grow = b0 + lrow;
    int gidx = d_cidx[m * Bn + (grow < cnt ? grow : cnt - 1)];

    const __nv_bfloat16* rowp[4];
    rowp[0] = d_ahi + ((size_t)m * Bn + gidx) * Hn + lseg * 8;
    rowp[1] = d_alo + ((size_t)m * Bn + gidx) * Hn + lseg * 8;
    rowp[2] = d_fhi + ((size_t)mr * Hn + h0 + lrow) * Hn + lseg * 8;
    rowp[3] = d_flo + ((size_t)mr * Hn + h0 + lrow) * Hn + lseg * 8;

    auto load_stage = [&](int st, int k0) {
        uint32_t dst = sbase + st * ZSTAGE + lrow * (ZPAD * 2) + lseg * 16;
#pragma unroll
        for (int bsel = 0; bsel < 4; bsel++)
            cp16(dst + bsel * ZBUFB, rowp[bsel] + k0);
    };

    float acc[2][4][4];
#pragma unroll
    for (int i = 0; i < 2; i++)
#pragma unroll
        for (int j = 0; j < 4; j++)
#pragma unroll
            for (int c = 0; c < 4; c++) acc[i][j][c] = 0.0f;

    const int wm0 = (wid >> 2) * 32;
    const int wn0 = (wid & 3) * 32;
    const int a_r = lane & 15;
    const int a_c8 = (lane >> 4) << 3;
    const int b_r = (lane & 7) + ((lane >> 4) << 3);
    const int b_c8 = ((lane >> 3) & 1) << 3;

    load_stage(0, 0);
    CP_COMMIT();
    load_stage(1, ZKC);
    CP_COMMIT();

    const int NIT = Hn / ZKC;
    for (int it = 0; it < NIT; it++) {
        CP_WAIT(1);
        __syncthreads();       // single barrier per iteration: orders both data-ready and buffer reuse
        if (it + 2 < NIT) {
            load_stage((it + 2) % 3, (it + 2) * ZKC);
            CP_COMMIT();
        }
        const int st = it % 3;
        const uint32_t sAh = sbase + st * ZSTAGE + 0 * ZBUFB;
        const uint32_t sAl = sbase + st * ZSTAGE + 1 * ZBUFB;
        const uint32_t sBh = sbase + st * ZSTAGE + 2 * ZBUFB;
        const uint32_t sBl = sbase + st * ZSTAGE + 3 * ZBUFB;

#pragma unroll
        for (int ks = 0; ks < 2; ks++) {
            const int kb = ks * 16;
            uint32_t aH[2][4], aL[2][4], bH[4][2], bL[4][2];
#pragma unroll
            for (int mi = 0; mi < 2; mi++) {
                uint32_t off = (uint32_t)(wm0 + mi * 16 + a_r) * (ZPAD * 2) + (kb + a_c8) * 2;
                ldm_x4(aH[mi][0], aH[mi][1], aH[mi][2], aH[mi][3], sAh + off);
                ldm_x4(aL[mi][0], aL[mi][1], aL[mi][2], aL[mi][3], sAl + off);
            }
#pragma unroll
            for (int p = 0; p < 2; p++) {
                uint32_t off = (uint32_t)(wn0 + p * 16 + b_r) * (ZPAD * 2) + (kb + b_c8) * 2;
                ldm_x4(bH[2 * p][0], bH[2 * p][1], bH[2 * p + 1][0], bH[2 * p + 1][1], sBh + off);
                ldm_x4(bL[2 * p][0], bL[2 * p][1], bL[2 * p + 1][0], bL[2 * p + 1][1], sBl + off);
            }
            // term-major sweeps: 8 independent MMAs between accumulator reuses
#pragma unroll
            for (int mi = 0; mi < 2; mi++)
#pragma unroll
                for (int ni = 0; ni < 4; ni++)
                    mma_bf16(acc[mi][ni], aH[mi], bH[ni]);
#pragma unroll
            for (int mi = 0; mi < 2; mi++)
#pragma unroll
                for (int ni = 0; ni < 4; ni++)
                    mma_bf16(acc[mi][ni], aH[mi], bL[ni]);
#pragma unroll
            for (int mi = 0; mi < 2; mi++)
#pragma unroll
                for (int ni = 0; ni < 4; ni++)
                    mma_bf16(acc[mi][ni], aL[mi], bH[ni]);
        }
    }

#pragma unroll
    for (int mi = 0; mi < 2; mi++) {
#pragma unroll
        for (int half = 0; half < 2; half++) {
            int r = b0 + wm0 + mi * 16 + (lane >> 2) + half * 8;
            if (r >= cnt) continue;
            int br = d_cidx[m * Bn + r];
            float* dd = d_zbuf + ((size_t)br * (Mn * Rn) + mr) * Hn + h0;
#pragma unroll
            for (int ni = 0; ni < 4; ni++) {
                int cc = wn0 + ni * 8 + (lane & 3) * 2;
                *(float2*)(dd + cc) = make_float2(acc[mi][ni][half * 2 + 0], acc[mi][ni][half * 2 + 1]);
            }
        }
    }
}

// ---------------- feat builders (compacted) ----------------
__global__ void k_feat_go(const float* tokens, const float* lnw, const float* lnb) {
    int i = blockIdx.x;
    if (i >= d_pvcnt) return;
    int row = d_pvidx[i];
    int b = row / 3, j = row - 3 * b;
    int oj = (j == 0) ? 0 : (j + 1);
    const float* tok = tokens + (size_t)b * Mn * Hn;
    __shared__ float sf[D3n];
    float s = 0.f, q = 0.f;
    for (int k = threadIdx.x; k < Hn; k += blockDim.x) {
        float t = tok[oj * Hn + k];
        float sv = tok[Hn + k];
        float dv = fabsf(t - sv);
        sf[k] = t; sf[Hn + k] = sv; sf[2 * Hn + k] = dv;
        s += t + sv + dv; q += t * t + sv * sv + dv * dv;
    }
    float2 rr = blkSum2(s, q);
    float mean = rr.x / D3n;
    float var = rr.y / D3n - mean * mean;
    float rstd = rsqrtf(var + 1e-5f);
    float* o = d_featgo + (size_t)i * D3n;
    for (int k = threadIdx.x; k < D3n; k += blockDim.x)
        o[k] = (sf[k] - mean) * rstd * lnw[k] + lnb[k];
}

__global__ void k_feat_ga(const float* tokens, const float* lnw, const float* lnb) {
    int i = blockIdx.x;
    if (i >= d_aumcnt) return;
    int b = d_aumidx[i];
    const float* tok = tokens + (size_t)b * Mn * Hn;
    __shared__ float sf[D3n];
    float s = 0.f, q = 0.f;
    for (int k = threadIdx.x; k < Hn; k += blockDim.x) {
        float t = tok[Hn + k];
        float sv = d_omean[(size_t)b * Hn + k];
        float dv = fabsf(t - sv);
        sf[k] = t; sf[Hn + k] = sv; sf[2 * Hn + k] = dv;
        s += t + sv + dv; q += t * t + sv * sv + dv * dv;
    }
    float2 rr = blkSum2(s, q);
    float mean = rr.x / D3n;
    float var = rr.y / D3n - mean * mean;
    float rstd = rsqrtf(var + 1e-5f);
    float* o = d_featga + (size_t)i * D3n;
    for (int k = threadIdx.x; k < D3n; k += blockDim.x)
        o[k] = (sf[k] - mean) * rstd * lnw[k] + lnb[k];
}

// ---------------- gate tails (compacted) ----------------
__global__ void k_gate_go(const float* w2, const float* b2) {
    int i = blockIdx.x;
    if (i >= d_pvcnt) return;
    const float* hr = d_hidgo + (size_t)i * MIDn;
    float v = 0.f;
    for (int k = threadIdx.x; k < MIDn; k += blockDim.x) v += hr[k] * w2[k];
    float2 rr = blkSum2(v, 0.f);
    if (threadIdx.x == 0) d_ggo[d_pvidx[i]] = 1.0f / (1.0f + expf(-(rr.x + b2[0])));
}
__global__ void k_gate_ga(const float* w2, const float* b2) {
    int i = blockIdx.x;
    if (i >= d_aumcnt) return;
    const float* hr = d_hidga + (size_t)i * MIDn;
    float v = 0.f;
    for (int k = threadIdx.x; k < MIDn; k += blockDim.x) v += hr[k] * w2[k];
    float2 rr = blkSum2(v, 0.f);
    if (threadIdx.x == 0) d_gavec[d_aumidx[i]] = 1.0f / (1.0f + expf(-(rr.x + b2[0])));
}

// ---------------- others_new + omean (fused, block per b) ----------------
__global__ void k_others_omean(const float* tokens, const float* lnw, const float* lnb) {
    int b = blockIdx.x;
    const float* tok = tokens + (size_t)b * Mn * Hn;
    int ma = d_mask[b * 4 + 1];
    __shared__ float srow[Hn];
    __shared__ float ssum[Hn];
    for (int k = threadIdx.x; k < Hn; k += blockDim.x) ssum[k] = 0.f;
    float denom = 0.f;
    for (int j = 0; j < 3; j++) {
        int oj = (j == 0) ? 0 : (j + 1);
        int moj = d_mask[b * 4 + oj];
        float* o = d_onew + ((size_t)b * 3 + j) * Hn;
        if (moj && ma) {
            float g = d_ggo[b * 3 + j];
            float s = 0.f, q = 0.f;
            for (int k = threadIdx.x; k < Hn; k += blockDim.x) {
                float x = tok[oj * Hn + k] + g * d_a2o[(size_t)b * Hn + k];
                srow[k] = x; s += x; q += x * x;
            }
            float2 rr = blkSum2(s, q);
            float mean = rr.x / Hn;
            float var = rr.y / Hn - mean * mean;
            float rstd = rsqrtf(var + 1e-5f);
            for (int k = threadIdx.x; k < Hn; k += blockDim.x) {
                float v = (srow[k] - mean) * rstd * lnw[k] + lnb[k];
                o[k] = v; ssum[k] += v;
            }
        } else if (moj) {
            for (int k = threadIdx.x; k < Hn; k += blockDim.x) {
                float v = tok[oj * Hn + k];
                o[k] = v; ssum[k] += v;
            }
        } else {
            for (int k = threadIdx.x; k < Hn; k += blockDim.x) o[k] = 0.f;
        }
        if (moj) denom += 1.f;
    }
    denom = fmaxf(denom, 1.f);
    for (int k = threadIdx.x; k < Hn; k += blockDim.x)
        d_omean[(size_t)b * Hn + k] = ssum[k] / denom;
}

// ---------------- mixed assembly (writes bf16 hi/lo splits directly) ----------------
__device__ __forceinline__ void split_store(int m, int b, int k, float v) {
    __nv_bfloat16 hi = __float2bfloat16(v);
    float lo = v - __bfloat162float(hi);
    size_t o = ((size_t)m * Bn + b) * Hn + k;
    d_ahi[o] = hi;
    d_alo[o] = __float2bfloat16(lo);
}

__global__ void k_mixed(const float* tokens, const float* lnw, const float* lnb) {
    int b = blockIdx.x;
    const float* tok = tokens + (size_t)b * Mn * Hn;
    int m0 = d_mask[b * 4], m1 = d_mask[b * 4 + 1], m2 = d_mask[b * 4 + 2], m3 = d_mask[b * 4 + 3];
    int aum = m1 && (m0 || m2 || m3);
    if (aum) {
        __shared__ float sx[Hn];
        float g = d_gavec[b];
        float s = 0.f, q = 0.f;
        for (int k = threadIdx.x; k < Hn; k += blockDim.x) {
            float x = tok[Hn + k] + g * d_o2a[(size_t)b * Hn + k];
            sx[k] = x; s += x; q += x * x;
        }
        float2 rr = blkSum2(s, q);
        float mean = rr.x / Hn;
        float var = rr.y / Hn - mean * mean;
        float rstd = rsqrtf(var + 1e-5f);
        for (int k = threadIdx.x; k < Hn; k += blockDim.x)
            split_store(1, b, k, (sx[k] - mean) * rstd * lnw[k] + lnb[k]);
    } else {
        float f = m1 ? 1.0f : 0.0f;
        for (int k = threadIdx.x; k < Hn; k += blockDim.x)
            split_store(1, b, k, tok[Hn + k] * f);
    }
    float f0 = m0 ? 1.f : 0.f, f2 = m2 ? 1.f : 0.f, f3 = m3 ? 1.f : 0.f;
    size_t ob = (size_t)b * 3 * Hn;
    for (int k = threadIdx.x; k < Hn; k += blockDim.x) {
        split_store(0, b, k, d_onew[ob + k] * f0);
        split_store(2, b, k, d_onew[ob + Hn + k] * f2);
        split_store(3, b, k, d_onew[ob + 2 * Hn + k] * f3);
    }
}

// ---------------- rank product + weighted sum + LN (fused) ----------------
__global__ void k_combine_ln(const float* rank_w, const float* lmf_bias,
                             const float* __restrict__ factors,
                             const float* lnw, const float* lnb) {
    int b = blockIdx.x;
    const unsigned char* mk = d_mask + b * 4;
    bool m0 = mk[0], m1 = mk[1], m2 = mk[2], m3 = mk[3];
    __shared__ float sx[Hn];
    float s = 0.f, q = 0.f;
    for (int h = threadIdx.x; h < Hn; h += blockDim.x) {
        const float* zb = d_zbuf + (size_t)b * (Mn * Rn * Hn) + h;
        float acc = 0.f;
#pragma unroll
        for (int r = 0; r < Rn; r++) {
            float p = rank_w[r];
            if (m0) p *= zb[(0 * Rn + r) * Hn] + factors[((size_t)(0 * Rn + r) * 1025) * Hn + h];
            if (m1) p *= zb[(1 * Rn + r) * Hn] + factors[((size_t)(1 * Rn + r) * 1025) * Hn + h];
            if (m2) p *= zb[(2 * Rn + r) * Hn] + factors[((size_t)(2 * Rn + r) * 1025) * Hn + h];
            if (m3) p *= zb[(3 * Rn + r) * Hn] + factors[((size_t)(3 * Rn + r) * 1025) * Hn + h];
            acc += p;
        }
        float v = acc + lmf_bias[h];
        sx[h] = v;
        s += v; q += v * v;
    }
    float2 rr = blkSum2(s, q);
    float mean = rr.x / Hn;
    float var = rr.y / Hn - mean * mean;
    float rstd = rsqrtf(var + 1e-5f);
    float* o = d_h1 + (size_t)b * Hn;
    for (int h = threadIdx.x; h < Hn; h += blockDim.x)
        o[h] = (sx[h] - mean) * rstd * lnw[h] + lnb[h];
}

// ---------------- final LayerNorm ----------------
__global__ void k_ln_out(const float* w, const float* bb, float* out) {
    const float* x = d_h2 + (size_t)blockIdx.x * Hn;
    float* y = out + (size_t)blockIdx.x * Hn;
    float s = 0.f, q = 0.f;
    for (int k = threadIdx.x; k < Hn; k += blockDim.x) { float v = x[k]; s += v; q += v * v; }
    float2 rr = blkSum2(s, q);
    float mean = rr.x / Hn;
    float var = rr.y / Hn - mean * mean;
    float rstd = rsqrtf(var + 1e-5f);
    for (int k = threadIdx.x; k < Hn; k += blockDim.x)
        y[k] = (x[k] - mean) * rstd * w[k] + bb[k];
}

// ---------------- launch ----------------
extern "C" void kernel_launch(void* const* d_in, const int* in_sizes, int n_in,
                              void* d_out, int out_size) {
    const float* tokens   = (const float*)d_in[0];
    const void*  maskraw  = d_in[1];
    const float* ln_go_w  = (const float*)d_in[2];
    const float* ln_go_b  = (const float*)d_in[3];
    const float* go_w1    = (const float*)d_in[4];
    const float* go_b1    = (const float*)d_in[5];
    const float* go_w2    = (const float*)d_in[6];
    const float* go_b2    = (const float*)d_in[7];
    const float* ln_ga_w  = (const float*)d_in[8];
    const float* ln_ga_b  = (const float*)d_in[9];
    const float* ga_w1    = (const float*)d_in[10];
    const float* ga_b1    = (const float*)d_in[11];
    const float* ga_w2    = (const float*)d_in[12];
    const float* ga_b2    = (const float*)d_in[13];
    const float* a2o_w    = (const float*)d_in[14];
    const float* o2a_w    = (const float*)d_in[15];
    const float* ln_o_w   = (const float*)d_in[16];
    const float* ln_o_b   = (const float*)d_in[17];
    const float* ln_a_w   = (const float*)d_in[18];
    const float* ln_a_b   = (const float*)d_in[19];
    const float* factors  = (const float*)d_in[20];
    const float* rank_w   = (const float*)d_in[21];
    const float* lmf_bias = (const float*)d_in[22];
    const float* out_ln1w = (const float*)d_in[23];
    const float* out_ln1b = (const float*)d_in[24];
    const float* out_w    = (const float*)d_in[25];
    const float* out_b    = (const float*)d_in[26];
    const float* out_ln2w = (const float*)d_in[27];
    const float* out_ln2b = (const float*)d_in[28];
    float* out = (float*)d_out;

    static cudaStream_t s1 = nullptr, s2 = nullptr;
    static cudaEvent_t evStart, evPF, evCmp, evA2O, evOM, evO2A;
    if (!s1) {
        cudaFuncSetAttribute(k_gemm_z_mma, cudaFuncAttributeMaxDynamicSharedMemorySize, ZSM_TOTAL);
        cudaFuncSetAttribute(k_sp_hidgo, cudaFuncAttributeMaxDynamicSharedMemorySize, GSM_TOTAL);
        cudaFuncSetAttribute(k_sp_hidga, cudaFuncAttributeMaxDynamicSharedMemorySize, GSM_TOTAL);
        cudaFuncSetAttribute(k_sp_a2o,   cudaFuncAttributeMaxDynamicSharedMemorySize, GSM_TOTAL);
        cudaFuncSetAttribute(k_sp_o2a,   cudaFuncAttributeMaxDynamicSharedMemorySize, GSM_TOTAL);
        cudaFuncSetAttribute(k_sp_out,   cudaFuncAttributeMaxDynamicSharedMemorySize, GSM_TOTAL);
        cudaStreamCreateWithFlags(&s1, cudaStreamNonBlocking);
        cudaStreamCreateWithFlags(&s2, cudaStreamNonBlocking);
        cudaEventCreateWithFlags(&evStart, cudaEventDisableTiming);
        cudaEventCreateWithFlags(&evPF,    cudaEventDisableTiming);
        cudaEventCreateWithFlags(&evCmp,   cudaEventDisableTiming);
        cudaEventCreateWithFlags(&evA2O,   cudaEventDisableTiming);
        cudaEventCreateWithFlags(&evOM,    cudaEventDisableTiming);
        cudaEventCreateWithFlags(&evO2A,   cudaEventDisableTiming);
    }

    // fork: factor prep runs concurrently with the whole gate pipeline
    cudaEventRecord(evStart, 0);
    cudaStreamWaitEvent(s1, evStart, 0);
    k_prep_factors<<<dim3(32, 32, Mn * Rn), dim3(32, 8), 0, s1>>>(factors);
    cudaEventRecord(evPF, s1);

    k_mask_compact<<<6, 1024>>>(maskraw);
    cudaEventRecord(evCmp, 0);

    // fork: a2o concurrent with the gate-others chain
    cudaStreamWaitEvent(s2, evCmp, 0);
    k_sp_a2o<<<dim3(Hn / 128, Bn / 128), 512, GSM_TOTAL, s2>>>(tokens, a2o_w);
    cudaEventRecord(evA2O, s2);

    k_feat_go<<<3 * Bn, 256>>>(tokens, ln_go_w, ln_go_b);
    k_sp_hidgo<<<dim3(MIDn / 128, 3 * Bn / 128), 512, GSM_TOTAL>>>(go_w1, go_b1);
    k_gate_go<<<3 * Bn, 256>>>(go_w2, go_b2);
    cudaStreamWaitEvent(0, evA2O, 0);
    k_others_omean<<<Bn, 256>>>(tokens, ln_o_w, ln_o_b);
    cudaEventRecord(evOM, 0);

    // fork: o2a concurrent with the gate-audio chain
    cudaStreamWaitEvent(s2, evOM, 0);
    k_sp_o2a<<<dim3(Hn / 128, Bn / 128), 512, GSM_TOTAL, s2>>>(o2a_w);
    cudaEventRecord(evO2A, s2);

    k_feat_ga<<<Bn, 256>>>(tokens, ln_ga_w, ln_ga_b);
    k_sp_hidga<<<dim3(MIDn / 128, Bn / 128), 512, GSM_TOTAL>>>(ga_w1, ga_b1);
    k_gate_ga<<<Bn, 256>>>(ga_w2, ga_b2);
    cudaStreamWaitEvent(0, evO2A, 0);
    k_mixed<<<Bn, 256>>>(tokens, ln_a_w, ln_a_b);

    cudaStreamWaitEvent(0, evPF, 0);
    k_gemm_z_mma<<<dim3(Hn / 128, Bn / 128, Mn * Rn), 512, ZSM_TOTAL>>>();
    k_combine_ln<<<Bn, 256>>>(rank_w, lmf_bias, factors, out_ln1w, out_ln1b);
    k_sp_out<<<dim3(Hn / 128, Bn / 128), 512, GSM_TOTAL>>>(out_w, out_b);
    k_ln_out<<<Bn, 256>>>(out_ln2w, out_ln2b, out);
}

// round 9
// speedup vs baseline: 4.8671x; 1.1049x over previous
#include <cuda_runtime.h>
#include <cuda_bf16.h>
#include <math.h>
#include <cstdint>

#define Bn   4096
#define Mn   4
#define Hn   1024
#define Rn   10
#define MIDn 512
#define D3n  3072

// ---------------- scratch (__device__ globals: alloc-free) ----------------
__device__ float d_featgo[3 * Bn * D3n];
__device__ float d_hidgo[3 * Bn * MIDn];
__device__ float d_ggo[3 * Bn];
__device__ float d_a2o[Bn * Hn];
__device__ float d_onew[Bn * 3 * Hn];
__device__ float d_omean[Bn * Hn];
__device__ float d_featga[Bn * D3n];
__device__ float d_hidga[Bn * MIDn];
__device__ float d_gavec[Bn];
__device__ float d_o2a[Bn * Hn];
__device__ float d_zbuf[167772160];             // B*M*R*H fp32
__device__ float d_h1[Bn * Hn];
__device__ float d_h2[Bn * Hn];
__device__ unsigned char d_mask[Bn * Mn];
__device__ int d_cidx[Mn * Bn];
__device__ int d_ccnt[Mn];
__device__ int d_pvidx[3 * Bn];
__device__ int d_pvcnt;
__device__ int d_aumidx[Bn];
__device__ int d_aumcnt;
__device__ __nv_bfloat16 d_ahi[Mn * Bn * Hn];      // [m][b][h]
__device__ __nv_bfloat16 d_alo[Mn * Bn * Hn];
__device__ __nv_bfloat16 d_fhi[Mn * Rn * Hn * Hn]; // [mr][h][d]
__device__ __nv_bfloat16 d_flo[Mn * Rn * Hn * Hn];

// ---------------- generic helpers ----------------
__device__ __forceinline__ float gelu_f(float x) {
    return 0.5f * x * (1.0f + erff(x * 0.70710678118654752f));
}
__device__ __forceinline__ float2 blkSum2(float a, float b) {
    __shared__ float sa[32], sb[32];
    __shared__ float ra, rb;
    int lane = threadIdx.x & 31, w = threadIdx.x >> 5;
#pragma unroll
    for (int o = 16; o > 0; o >>= 1) {
        a += __shfl_xor_sync(0xffffffffu, a, o);
        b += __shfl_xor_sync(0xffffffffu, b, o);
    }
    if (lane == 0) { sa[w] = a; sb[w] = b; }
    __syncthreads();
    if (threadIdx.x == 0) {
        float x = 0.f, y = 0.f;
        int nw = blockDim.x >> 5;
        for (int i = 0; i < nw; i++) { x += sa[i]; y += sb[i]; }
        ra = x; rb = y;
    }
    __syncthreads();
    return make_float2(ra, rb);
}

// ---------------- mma.sync helpers ----------------
__device__ __forceinline__ uint32_t smem_u32(const void* p) {
    uint32_t a;
    asm("{ .reg .u64 t; cvta.to.shared.u64 t, %1; cvt.u32.u64 %0, t; }" : "=r"(a) : "l"(p));
    return a;
}
__device__ __forceinline__ void ldm_x4(uint32_t& r0, uint32_t& r1, uint32_t& r2, uint32_t& r3,
                                       uint32_t addr) {
    asm volatile("ldmatrix.sync.aligned.m8n8.x4.shared.b16 {%0,%1,%2,%3}, [%4];"
                 : "=r"(r0), "=r"(r1), "=r"(r2), "=r"(r3) : "r"(addr));
}
__device__ __forceinline__ void mma_bf16(float* c, const uint32_t* a, const uint32_t* b) {
    asm volatile("mma.sync.aligned.m16n8k16.row.col.f32.bf16.bf16.f32 "
                 "{%0,%1,%2,%3}, {%4,%5,%6,%7}, {%8,%9}, {%0,%1,%2,%3};"
                 : "+f"(c[0]), "+f"(c[1]), "+f"(c[2]), "+f"(c[3])
                 : "r"(a[0]), "r"(a[1]), "r"(a[2]), "r"(a[3]), "r"(b[0]), "r"(b[1]));
}
__device__ __forceinline__ void cp16(uint32_t dst, const void* src) {
    asm volatile("cp.async.cg.shared.global [%0], [%1], 16;" :: "r"(dst), "l"(src));
}
#define CP_COMMIT() asm volatile("cp.async.commit_group;" ::: "memory")
#define CP_WAIT(n)  asm volatile("cp.async.wait_group %0;" :: "n"(n) : "memory")

__device__ __forceinline__ uint32_t pack_hi_lo(float x, float y, uint32_t& lo) {
    __nv_bfloat16 hx = __float2bfloat16(x);
    __nv_bfloat16 hy = __float2bfloat16(y);
    float lxf = x - __bfloat162float(hx);
    float lyf = y - __bfloat162float(hy);
    __nv_bfloat162 hv = __halves2bfloat162(hx, hy);
    __nv_bfloat162 lv = __halves2bfloat162(__float2bfloat16(lxf), __float2bfloat16(lyf));
    lo = *reinterpret_cast<uint32_t*>(&lv);
    return *reinterpret_cast<uint32_t*>(&hv);
}

// ---------------- fused mask sniff + all compactions (6 blocks) ----------------
__global__ void __launch_bounds__(1024) k_mask_compact(const void* raw) {
    __shared__ int ok32s, okfs;
    if (threadIdx.x == 0) { ok32s = 1; okfs = 1; }
    __syncthreads();
    const int* pi = (const int*)raw;
    const float* pf = (const float*)raw;
    const unsigned char* pb = (const unsigned char*)raw;
    int lok32 = 1, lokf = 1;
    for (int i = threadIdx.x; i < 4096; i += 1024) {
        int v = pi[i];
        if (v != 0 && v != 1) lok32 = 0;
        float f = pf[i];
        if (f != 0.0f && f != 1.0f) lokf = 0;
    }
    if (!lok32) ok32s = 0;
    if (!lokf)  okfs = 0;
    __syncthreads();
    const int ok32 = ok32s, okf = okfs;
    auto maskat = [&](int i) -> int {
        if (ok32) return pi[i] != 0;
        if (okf)  return pf[i] != 0.0f;
        return pb[i] != 0;
    };

    const int blk = blockIdx.x;
    if (blk == 0) {
        for (int i = threadIdx.x; i < Bn * Mn; i += 1024)
            d_mask[i] = (unsigned char)maskat(i);
    }

    int* out_idx;
    int* out_cnt;
    int nitems;
    if (blk < 4)      { out_idx = d_cidx + blk * Bn; out_cnt = d_ccnt + blk; nitems = Bn; }
    else if (blk == 4){ out_idx = d_pvidx;           out_cnt = &d_pvcnt;     nitems = 3 * Bn; }
    else              { out_idx = d_aumidx;          out_cnt = &d_aumcnt;    nitems = Bn; }

    __shared__ int warp_off[32];
    __shared__ int chunk_base;
    if (threadIdx.x == 0) chunk_base = 0;
    __syncthreads();
    int lane = threadIdx.x & 31, w = threadIdx.x >> 5;
    for (int c = 0; c < nitems; c += 1024) {
        int i = c + threadIdx.x;
        int v;
        if (blk < 4) {
            v = maskat(i * Mn + blk);
        } else if (blk == 4) {
            int b = i / 3, j = i - 3 * b;
            int oj = (j == 0) ? 0 : (j + 1);
            v = maskat(b * 4 + oj) && maskat(b * 4 + 1);
        } else {
            v = maskat(i * 4 + 1) && (maskat(i * 4) | maskat(i * 4 + 2) | maskat(i * 4 + 3));
        }
        unsigned bal = __ballot_sync(0xffffffffu, v);
        int pre = __popc(bal & ((1u << lane) - 1u));
        if (lane == 31) warp_off[w] = __popc(bal);
        __syncthreads();
        if (threadIdx.x < 32) {
            int val = warp_off[threadIdx.x];
#pragma unroll
            for (int o = 1; o < 32; o <<= 1) {
                int t = __shfl_up_sync(0xffffffffu, val, o);
                if ((int)threadIdx.x >= o) val += t;
            }
            warp_off[threadIdx.x] = val;
        }
        __syncthreads();
        int base = chunk_base + (w ? warp_off[w - 1] : 0) + pre;
        if (v) out_idx[base] = i;
        __syncthreads();
        if (threadIdx.x == 0) chunk_base += warp_off[31];
        __syncthreads();
    }
    if (threadIdx.x == 0) *out_cnt = chunk_base;
}

// ---------------- generic fp32 -> bf16-split mma GEMM (512 thr, 16 warps) ----------------
#define GPAD   40
#define GBUF   (128 * GPAD * 2)
#define GSTAGE (4 * GBUF)
#define GSM_TOTAL (2 * GSTAGE)

template <int SEL>
__device__ __forceinline__ void gemm_sp_body(
    const float* __restrict__ A, int lda,
    const float* __restrict__ B, int ldb,
    float* __restrict__ C, int ldc,
    const float* __restrict__ bias, int K, int act)
{
    extern __shared__ char gsm[];
    int cnt = 1 << 30;
    const int* ridx = nullptr;
    if (SEL == 1) cnt = d_pvcnt;
    if (SEL == 2) cnt = d_aumcnt;
    if (SEL == 3) { cnt = d_aumcnt; ridx = d_aumidx; }
    const int n0 = blockIdx.x * 128, m0 = blockIdx.y * 128;
    if (SEL != 0 && m0 >= cnt) return;

    const uint32_t sbase = smem_u32(gsm);
    const int tid = threadIdx.x;
    const int wid = tid >> 5, lane = tid & 31;

    const int lrow = tid >> 2, lseg = tid & 3;
    int grow = m0 + lrow;
    if (SEL != 0 && grow >= cnt) grow = cnt - 1;
    const int arow = ridx ? ridx[grow] : grow;
    const float* Aref = A + (size_t)arow * lda + lseg * 8;
    const float* Bref = B + (size_t)(n0 + lrow) * ldb + lseg * 8;

    float4 ra[2], rb[2];
    auto gload = [&](int k0) {
        ra[0] = *(const float4*)(Aref + k0);
        ra[1] = *(const float4*)(Aref + k0 + 4);
        rb[0] = *(const float4*)(Bref + k0);
        rb[1] = *(const float4*)(Bref + k0 + 4);
    };
    auto sstore = [&](int st) {
        char* p = gsm + st * GSTAGE + lrow * (GPAD * 2) + lseg * 16;
        uint32_t l0, l1, l2, l3;
        uint32_t h0 = pack_hi_lo(ra[0].x, ra[0].y, l0);
        uint32_t h1 = pack_hi_lo(ra[0].z, ra[0].w, l1);
        uint32_t h2 = pack_hi_lo(ra[1].x, ra[1].y, l2);
        uint32_t h3 = pack_hi_lo(ra[1].z, ra[1].w, l3);
        *(uint4*)(p + 0 * GBUF) = make_uint4(h0, h1, h2, h3);
        *(uint4*)(p + 1 * GBUF) = make_uint4(l0, l1, l2, l3);
        h0 = pack_hi_lo(rb[0].x, rb[0].y, l0);
        h1 = pack_hi_lo(rb[0].z, rb[0].w, l1);
        h2 = pack_hi_lo(rb[1].x, rb[1].y, l2);
        h3 = pack_hi_lo(rb[1].z, rb[1].w, l3);
        *(uint4*)(p + 2 * GBUF) = make_uint4(h0, h1, h2, h3);
        *(uint4*)(p + 3 * GBUF) = make_uint4(l0, l1, l2, l3);
    };

    float acc[2][4][4];
#pragma unroll
    for (int i = 0; i < 2; i++)
#pragma unroll
        for (int j = 0; j < 4; j++)
#pragma unroll
            for (int c = 0; c < 4; c++) acc[i][j][c] = 0.0f;

    const int wm0 = (wid >> 2) * 32;
    const int wn0 = (wid & 3) * 32;
    const int a_r = lane & 15;
    const int a_c8 = (lane >> 4) << 3;
    const int b_r = (lane & 7) + ((lane >> 4) << 3);
    const int b_c8 = ((lane >> 3) & 1) << 3;

    gload(0);
    const int NIT = K / 32;
    for (int it = 0; it < NIT; it++) {
        const int st = it & 1;
        sstore(st);
        __syncthreads();
        if (it + 1 < NIT) gload((it + 1) * 32);

        const uint32_t sAh = sbase + st * GSTAGE + 0 * GBUF;
        const uint32_t sAl = sbase + st * GSTAGE + 1 * GBUF;
        const uint32_t sBh = sbase + st * GSTAGE + 2 * GBUF;
        const uint32_t sBl = sbase + st * GSTAGE + 3 * GBUF;
#pragma unroll
        for (int ks = 0; ks < 2; ks++) {
            const int kb = ks * 16;
            uint32_t aH[2][4], aL[2][4], bH[4][2], bL[4][2];
#pragma unroll
            for (int mi = 0; mi < 2; mi++) {
                uint32_t off = (uint32_t)(wm0 + mi * 16 + a_r) * (GPAD * 2) + (kb + a_c8) * 2;
                ldm_x4(aH[mi][0], aH[mi][1], aH[mi][2], aH[mi][3], sAh + off);
                ldm_x4(aL[mi][0], aL[mi][1], aL[mi][2], aL[mi][3], sAl + off);
            }
#pragma unroll
            for (int p2 = 0; p2 < 2; p2++) {
                uint32_t off = (uint32_t)(wn0 + p2 * 16 + b_r) * (GPAD * 2) + (kb + b_c8) * 2;
                ldm_x4(bH[2 * p2][0], bH[2 * p2][1], bH[2 * p2 + 1][0], bH[2 * p2 + 1][1], sBh + off);
                ldm_x4(bL[2 * p2][0], bL[2 * p2][1], bL[2 * p2 + 1][0], bL[2 * p2 + 1][1], sBl + off);
            }
#pragma unroll
            for (int mi = 0; mi < 2; mi++)
#pragma unroll
                for (int ni = 0; ni < 4; ni++)
                    mma_bf16(acc[mi][ni], aH[mi], bH[ni]);
#pragma unroll
            for (int mi = 0; mi < 2; mi++)
#pragma unroll
                for (int ni = 0; ni < 4; ni++)
                    mma_bf16(acc[mi][ni], aH[mi], bL[ni]);
#pragma unroll
            for (int mi = 0; mi < 2; mi++)
#pragma unroll
                for (int ni = 0; ni < 4; ni++)
                    mma_bf16(acc[mi][ni], aL[mi], bH[ni]);
        }
        __syncthreads();
    }

#pragma unroll
    for (int mi = 0; mi < 2; mi++) {
#pragma unroll
        for (int half = 0; half < 2; half++) {
            int r = m0 + wm0 + mi * 16 + (lane >> 2) + half * 8;
            if (SEL != 0 && r >= cnt) continue;
            int crow = ridx ? ridx[r] : r;
            float* dd = C + (size_t)crow * ldc;
#pragma unroll
            for (int ni = 0; ni < 4; ni++) {
                int cc = n0 + wn0 + ni * 8 + (lane & 3) * 2;
                float v0 = acc[mi][ni][half * 2 + 0] + (bias ? bias[cc] : 0.f);
                float v1 = acc[mi][ni][half * 2 + 1] + (bias ? bias[cc + 1] : 0.f);
                if (act) { v0 = gelu_f(v0); v1 = gelu_f(v1); }
                *(float2*)(dd + cc) = make_float2(v0, v1);
            }
        }
    }
}

__global__ void __launch_bounds__(512) k_sp_hidgo(const float* w1, const float* b1) {
    gemm_sp_body<1>(d_featgo, D3n, w1, D3n, d_hidgo, MIDn, b1, D3n, 1);
}
__global__ void __launch_bounds__(512) k_sp_hidga(const float* w1, const float* b1) {
    gemm_sp_body<2>(d_featga, D3n, w1, D3n, d_hidga, MIDn, b1, D3n, 1);
}
__global__ void __launch_bounds__(512) k_sp_a2o(const float* tokens, const float* w) {
    gemm_sp_body<3>(tokens + Hn, Mn * Hn, w, Hn, d_a2o, Hn, (const float*)0, Hn, 0);
}
__global__ void __launch_bounds__(512) k_sp_o2a(const float* w) {
    gemm_sp_body<3>(d_omean, Hn, w, Hn, d_o2a, Hn, (const float*)0, Hn, 0);
}
__global__ void __launch_bounds__(512) k_sp_out(const float* w, const float* bb) {
    gemm_sp_body<0>(d_h1, Hn, w, Hn, d_h2, Hn, bb, Hn, 1);
}

// ---------------- factor split/transpose prep ----------------
__global__ void __launch_bounds__(256) k_prep_factors(const float* __restrict__ f) {
    __shared__ float t[32][33];
    int mr = blockIdx.z;
    int d0 = blockIdx.x * 32, h0 = blockIdx.y * 32;
    int tx = threadIdx.x, ty = threadIdx.y;
#pragma unroll
    for (int i = ty; i < 32; i += 8)
        t[i][tx] = f[((size_t)mr * 1025 + 1 + d0 + i) * Hn + h0 + tx];
    __syncthreads();
#pragma unroll
    for (int i = ty; i < 32; i += 8) {
        float x = t[tx][i];
        __nv_bfloat16 hi = __float2bfloat16(x);
        float lo = x - __bfloat162float(hi);
        size_t o = ((size_t)mr * Hn + h0 + i) * Hn + d0 + tx;
        d_fhi[o] = hi;
        d_flo[o] = __float2bfloat16(lo);
    }
}

// ---------------- LMF GEMM: block 128x256, 16 warps, warp 32x64, 3-stage ----------------
#define ZKC     32
#define ZPAD    40
#define ZA_ROWS 128
#define ZB_ROWS 256
#define ZABUF   (ZA_ROWS * ZPAD * 2)          // 10240
#define ZBBUF   (ZB_ROWS * ZPAD * 2)          // 20480
#define ZSTAGE  (2 * ZABUF + 2 * ZBBUF)       // 61440
#define ZSM_TOTAL (3 * ZSTAGE)                // 184320

__global__ void __launch_bounds__(512) k_gemm_z_mma() {
    extern __shared__ char zsm[];
    const uint32_t sbase = smem_u32(zsm);
    const int tid = threadIdx.x;
    const int wid = tid >> 5, lane = tid & 31;
    const int h0 = blockIdx.x * 256;
    const int b0 = blockIdx.y * 128;
    const int mr = blockIdx.z;
    const int m = mr / Rn;
    const int cnt = d_ccnt[m];
    if (b0 >= cnt) return;

    const int lrow = tid >> 2;        // 0..127
    const int lseg = tid & 3;

    int grow = b0 + lrow;
    int gidx = d_cidx[m * Bn + (grow < cnt ? grow : cnt - 1)];

    const __nv_bfloat16* pAhi = d_ahi + ((size_t)m * Bn + gidx) * Hn + lseg * 8;
    const __nv_bfloat16* pAlo = d_alo + ((size_t)m * Bn + gidx) * Hn + lseg * 8;
    const __nv_bfloat16* pB0hi = d_fhi + ((size_t)mr * Hn + h0 + lrow) * Hn + lseg * 8;
    const __nv_bfloat16* pB0lo = d_flo + ((size_t)mr * Hn + h0 + lrow) * Hn + lseg * 8;
    const __nv_bfloat16* pB1hi = pB0hi + (size_t)128 * Hn;
    const __nv_bfloat16* pB1lo = pB0lo + (size_t)128 * Hn;

    auto load_stage = [&](int st, int k0) {
        uint32_t base = sbase + st * ZSTAGE;
        uint32_t offA = lrow * (ZPAD * 2) + lseg * 16;
        cp16(base + offA, pAhi + k0);
        cp16(base + ZABUF + offA, pAlo + k0);
        uint32_t offB0 = lrow * (ZPAD * 2) + lseg * 16;
        uint32_t offB1 = (lrow + 128) * (ZPAD * 2) + lseg * 16;
        cp16(base + 2 * ZABUF + offB0, pB0hi + k0);
        cp16(base + 2 * ZABUF + offB1, pB1hi + k0);
        cp16(base + 2 * ZABUF + ZBBUF + offB0, pB0lo + k0);
        cp16(base + 2 * ZABUF + ZBBUF + offB1, pB1lo + k0);
    };

    float acc[2][8][4];
#pragma unroll
    for (int i = 0; i < 2; i++)
#pragma unroll
        for (int j = 0; j < 8; j++)
#pragma unroll
            for (int c = 0; c < 4; c++) acc[i][j][c] = 0.0f;

    const int wm0 = (wid >> 2) * 32;  // 4 m-groups of 32 rows
    const int wn0 = (wid & 3) * 64;   // 4 n-groups of 64 cols
    const int a_r = lane & 15;
    const int a_c8 = (lane >> 4) << 3;
    const int b_r = (lane & 7) + ((lane >> 4) << 3);
    const int b_c8 = ((lane >> 3) & 1) << 3;

    load_stage(0, 0);
    CP_COMMIT();
    load_stage(1, ZKC);
    CP_COMMIT();

    const int NIT = Hn / ZKC;
    for (int it = 0; it < NIT; it++) {
        CP_WAIT(1);
        __syncthreads();
        if (it + 2 < NIT) {
            load_stage((it + 2) % 3, (it + 2) * ZKC);
            CP_COMMIT();
        }
        const int st = it % 3;
        const uint32_t sAh = sbase + st * ZSTAGE;
        const uint32_t sAl = sAh + ZABUF;
        const uint32_t sBh = sAh + 2 * ZABUF;
        const uint32_t sBl = sBh + ZBBUF;

#pragma unroll
        for (int ks = 0; ks < 2; ks++) {
            const int kb = ks * 16;
            uint32_t aH[2][4], aL[2][4];
#pragma unroll
            for (int mi = 0; mi < 2; mi++) {
                uint32_t off = (uint32_t)(wm0 + mi * 16 + a_r) * (ZPAD * 2) + (kb + a_c8) * 2;
                ldm_x4(aH[mi][0], aH[mi][1], aH[mi][2], aH[mi][3], sAh + off);
                ldm_x4(aL[mi][0], aL[mi][1], aL[mi][2], aL[mi][3], sAl + off);
            }
#pragma unroll
            for (int hf = 0; hf < 2; hf++) {         // two ni-halves of 32 cols
                uint32_t bH[4][2], bL[4][2];
#pragma unroll
                for (int p = 0; p < 2; p++) {
                    uint32_t off = (uint32_t)(wn0 + hf * 32 + p * 16 + b_r) * (ZPAD * 2) + (kb + b_c8) * 2;
                    ldm_x4(bH[2 * p][0], bH[2 * p][1], bH[2 * p + 1][0], bH[2 * p + 1][1], sBh + off);
                    ldm_x4(bL[2 * p][0], bL[2 * p][1], bL[2 * p + 1][0], bL[2 * p + 1][1], sBl + off);
                }
#pragma unroll
                for (int mi = 0; mi < 2; mi++)
#pragma unroll
                    for (int ni = 0; ni < 4; ni++)
                        mma_bf16(acc[mi][hf * 4 + ni], aH[mi], bH[ni]);
#pragma unroll
                for (int mi = 0; mi < 2; mi++)
#pragma unroll
                    for (int ni = 0; ni < 4; ni++)
                        mma_bf16(acc[mi][hf * 4 + ni], aH[mi], bL[ni]);
#pragma unroll
                for (int mi = 0; mi < 2; mi++)
#pragma unroll
                    for (int ni = 0; ni < 4; ni++)
                        mma_bf16(acc[mi][hf * 4 + ni], aL[mi], bH[ni]);
            }
        }
    }

#pragma unroll
    for (int mi = 0; mi < 2; mi++) {
#pragma unroll
        for (int half = 0; half < 2; half++) {
            int r = b0 + wm0 + mi * 16 + (lane >> 2) + half * 8;
            if (r >= cnt) continue;
            int br = d_cidx[m * Bn + r];
            float* dd = d_zbuf + ((size_t)br * (Mn * Rn) + mr) * Hn + h0;
#pragma unroll
            for (int ni = 0; ni < 8; ni++) {
                int cc = wn0 + ni * 8 + (lane & 3) * 2;
                *(float2*)(dd + cc) = make_float2(acc[mi][ni][half * 2 + 0], acc[mi][ni][half * 2 + 1]);
            }
        }
    }
}

// ---------------- feat builders (compacted) ----------------
__global__ void k_feat_go(const float* tokens, const float* lnw, const float* lnb) {
    int i = blockIdx.x;
    if (i >= d_pvcnt) return;
    int row = d_pvidx[i];
    int b = row / 3, j = row - 3 * b;
    int oj = (j == 0) ? 0 : (j + 1);
    const float* tok = tokens + (size_t)b * Mn * Hn;
    __shared__ float sf[D3n];
    float s = 0.f, q = 0.f;
    for (int k = threadIdx.x; k < Hn; k += blockDim.x) {
        float t = tok[oj * Hn + k];
        float sv = tok[Hn + k];
        float dv = fabsf(t - sv);
        sf[k] = t; sf[Hn + k] = sv; sf[2 * Hn + k] = dv;
        s += t + sv + dv; q += t * t + sv * sv + dv * dv;
    }
    float2 rr = blkSum2(s, q);
    float mean = rr.x / D3n;
    float var = rr.y / D3n - mean * mean;
    float rstd = rsqrtf(var + 1e-5f);
    float* o = d_featgo + (size_t)i * D3n;
    for (int k = threadIdx.x; k < D3n; k += blockDim.x)
        o[k] = (sf[k] - mean) * rstd * lnw[k] + lnb[k];
}

__global__ void k_feat_ga(const float* tokens, const float* lnw, const float* lnb) {
    int i = blockIdx.x;
    if (i >= d_aumcnt) return;
    int b = d_aumidx[i];
    const float* tok = tokens + (size_t)b * Mn * Hn;
    __shared__ float sf[D3n];
    float s = 0.f, q = 0.f;
    for (int k = threadIdx.x; k < Hn; k += blockDim.x) {
        float t = tok[Hn + k];
        float sv = d_omean[(size_t)b * Hn + k];
        float dv = fabsf(t - sv);
        sf[k] = t; sf[Hn + k] = sv; sf[2 * Hn + k] = dv;
        s += t + sv + dv; q += t * t + sv * sv + dv * dv;
    }
    float2 rr = blkSum2(s, q);
    float mean = rr.x / D3n;
    float var = rr.y / D3n - mean * mean;
    float rstd = rsqrtf(var + 1e-5f);
    float* o = d_featga + (size_t)i * D3n;
    for (int k = threadIdx.x; k < D3n; k += blockDim.x)
        o[k] = (sf[k] - mean) * rstd * lnw[k] + lnb[k];
}

// ---------------- gate tails (compacted) ----------------
__global__ void k_gate_go(const float* w2, const float* b2) {
    int i = blockIdx.x;
    if (i >= d_pvcnt) return;
    const float* hr = d_hidgo + (size_t)i * MIDn;
    float v = 0.f;
    for (int k = threadIdx.x; k < MIDn; k += blockDim.x) v += hr[k] * w2[k];
    float2 rr = blkSum2(v, 0.f);
    if (threadIdx.x == 0) d_ggo[d_pvidx[i]] = 1.0f / (1.0f + expf(-(rr.x + b2[0])));
}
__global__ void k_gate_ga(const float* w2, const float* b2) {
    int i = blockIdx.x;
    if (i >= d_aumcnt) return;
    const float* hr = d_hidga + (size_t)i * MIDn;
    float v = 0.f;
    for (int k = threadIdx.x; k < MIDn; k += blockDim.x) v += hr[k] * w2[k];
    float2 rr = blkSum2(v, 0.f);
    if (threadIdx.x == 0) d_gavec[d_aumidx[i]] = 1.0f / (1.0f + expf(-(rr.x + b2[0])));
}

// ---------------- others_new + omean (fused, block per b) ----------------
__global__ void k_others_omean(const float* tokens, const float* lnw, const float* lnb) {
    int b = blockIdx.x;
    const float* tok = tokens + (size_t)b * Mn * Hn;
    int ma = d_mask[b * 4 + 1];
    __shared__ float srow[Hn];
    __shared__ float ssum[Hn];
    for (int k = threadIdx.x; k < Hn; k += blockDim.x) ssum[k] = 0.f;
    float denom = 0.f;
    for (int j = 0; j < 3; j++) {
        int oj = (j == 0) ? 0 : (j + 1);
        int moj = d_mask[b * 4 + oj];
        float* o = d_onew + ((size_t)b * 3 + j) * Hn;
        if (moj && ma) {
            float g = d_ggo[b * 3 + j];
            float s = 0.f, q = 0.f;
            for (int k = threadIdx.x; k < Hn; k += blockDim.x) {
                float x = tok[oj * Hn + k] + g * d_a2o[(size_t)b * Hn + k];
                srow[k] = x; s += x; q += x * x;
            }
            float2 rr = blkSum2(s, q);
            float mean = rr.x / Hn;
            float var = rr.y / Hn - mean * mean;
            float rstd = rsqrtf(var + 1e-5f);
            for (int k = threadIdx.x; k < Hn; k += blockDim.x) {
                float v = (srow[k] - mean) * rstd * lnw[k] + lnb[k];
                o[k] = v; ssum[k] += v;
            }
        } else if (moj) {
            for (int k = threadIdx.x; k < Hn; k += blockDim.x) {
                float v = tok[oj * Hn + k];
                o[k] = v; ssum[k] += v;
            }
        } else {
            for (int k = threadIdx.x; k < Hn; k += blockDim.x) o[k] = 0.f;
        }
        if (moj) denom += 1.f;
    }
    denom = fmaxf(denom, 1.f);
    for (int k = threadIdx.x; k < Hn; k += blockDim.x)
        d_omean[(size_t)b * Hn + k] = ssum[k] / denom;
}

// ---------------- mixed assembly (writes bf16 hi/lo splits directly) ----------------
__device__ __forceinline__ void split_store(int m, int b, int k, float v) {
    __nv_bfloat16 hi = __float2bfloat16(v);
    float lo = v - __bfloat162float(hi);
    size_t o = ((size_t)m * Bn + b) * Hn + k;
    d_ahi[o] = hi;
    d_alo[o] = __float2bfloat16(lo);
}

__global__ void k_mixed(const float* tokens, const float* lnw, const float* lnb) {
    int b = blockIdx.x;
    const float* tok = tokens + (size_t)b * Mn * Hn;
    int m0 = d_mask[b * 4], m1 = d_mask[b * 4 + 1], m2 = d_mask[b * 4 + 2], m3 = d_mask[b * 4 + 3];
    int aum = m1 && (m0 || m2 || m3);
    if (aum) {
        __shared__ float sx[Hn];
        float g = d_gavec[b];
        float s = 0.f, q = 0.f;
        for (int k = threadIdx.x; k < Hn; k += blockDim.x) {
            float x = tok[Hn + k] + g * d_o2a[(size_t)b * Hn + k];
            sx[k] = x; s += x; q += x * x;
        }
        float2 rr = blkSum2(s, q);
        float mean = rr.x / Hn;
        float var = rr.y / Hn - mean * mean;
        float rstd = rsqrtf(var + 1e-5f);
        for (int k = threadIdx.x; k < Hn; k += blockDim.x)
            split_store(1, b, k, (sx[k] - mean) * rstd * lnw[k] + lnb[k]);
    } else {
        float f = m1 ? 1.0f : 0.0f;
        for (int k = threadIdx.x; k < Hn; k += blockDim.x)
            split_store(1, b, k, tok[Hn + k] * f);
    }
    float f0 = m0 ? 1.f : 0.f, f2 = m2 ? 1.f : 0.f, f3 = m3 ? 1.f : 0.f;
    size_t ob = (size_t)b * 3 * Hn;
    for (int k = threadIdx.x; k < Hn; k += blockDim.x) {
        split_store(0, b, k, d_onew[ob + k] * f0);
        split_store(2, b, k, d_onew[ob + Hn + k] * f2);
        split_store(3, b, k, d_onew[ob + 2 * Hn + k] * f3);
    }
}

// ---------------- rank product + weighted sum + LN (fused) ----------------
__global__ void k_combine_ln(const float* rank_w, const float* lmf_bias,
                             const float* __restrict__ factors,
                             const float* lnw, const float* lnb) {
    int b = blockIdx.x;
    const unsigned char* mk = d_mask + b * 4;
    bool m0 = mk[0], m1 = mk[1], m2 = mk[2], m3 = mk[3];
    __shared__ float sx[Hn];
    float s = 0.f, q = 0.f;
    for (int h = threadIdx.x; h < Hn; h += blockDim.x) {
        const float* zb = d_zbuf + (size_t)b * (Mn * Rn * Hn) + h;
        float acc = 0.f;
#pragma unroll
        for (int r = 0; r < Rn; r++) {
            float p = rank_w[r];
            if (m0) p *= zb[(0 * Rn + r) * Hn] + factors[((size_t)(0 * Rn + r) * 1025) * Hn + h];
            if (m1) p *= zb[(1 * Rn + r) * Hn] + factors[((size_t)(1 * Rn + r) * 1025) * Hn + h];
            if (m2) p *= zb[(2 * Rn + r) * Hn] + factors[((size_t)(2 * Rn + r) * 1025) * Hn + h];
            if (m3) p *= zb[(3 * Rn + r) * Hn] + factors[((size_t)(3 * Rn + r) * 1025) * Hn + h];
            acc += p;
        }
        float v = acc + lmf_bias[h];
        sx[h] = v;
        s += v; q += v * v;
    }
    float2 rr = blkSum2(s, q);
    float mean = rr.x / Hn;
    float var = rr.y / Hn - mean * mean;
    float rstd = rsqrtf(var + 1e-5f);
    float* o = d_h1 + (size_t)b * Hn;
    for (int h = threadIdx.x; h < Hn; h += blockDim.x)
        o[h] = (sx[h] - mean) * rstd * lnw[h] + lnb[h];
}

// ---------------- final LayerNorm ----------------
__global__ void k_ln_out(const float* w, const float* bb, float* out) {
    const float* x = d_h2 + (size_t)blockIdx.x * Hn;
    float* y = out + (size_t)blockIdx.x * Hn;
    float s = 0.f, q = 0.f;
    for (int k = threadIdx.x; k < Hn; k += blockDim.x) { float v = x[k]; s += v; q += v * v; }
    float2 rr = blkSum2(s, q);
    float mean = rr.x / Hn;
    float var = rr.y / Hn - mean * mean;
    float rstd = rsqrtf(var + 1e-5f);
    for (int k = threadIdx.x; k < Hn; k += blockDim.x)
        y[k] = (x[k] - mean) * rstd * w[k] + bb[k];
}

// ---------------- launch ----------------
extern "C" void kernel_launch(void* const* d_in, const int* in_sizes, int n_in,
                              void* d_out, int out_size) {
    const float* tokens   = (const float*)d_in[0];
    const void*  maskraw  = d_in[1];
    const float* ln_go_w  = (const float*)d_in[2];
    const float* ln_go_b  = (const float*)d_in[3];
    const float* go_w1    = (const float*)d_in[4];
    const float* go_b1    = (const float*)d_in[5];
    const float* go_w2    = (const float*)d_in[6];
    const float* go_b2    = (const float*)d_in[7];
    const float* ln_ga_w  = (const float*)d_in[8];
    const float* ln_ga_b  = (const float*)d_in[9];
    const float* ga_w1    = (const float*)d_in[10];
    const float* ga_b1    = (const float*)d_in[11];
    const float* ga_w2    = (const float*)d_in[12];
    const float* ga_b2    = (const float*)d_in[13];
    const float* a2o_w    = (const float*)d_in[14];
    const float* o2a_w    = (const float*)d_in[15];
    const float* ln_o_w   = (const float*)d_in[16];
    const float* ln_o_b   = (const float*)d_in[17];
    const float* ln_a_w   = (const float*)d_in[18];
    const float* ln_a_b   = (const float*)d_in[19];
    const float* factors  = (const float*)d_in[20];
    const float* rank_w   = (const float*)d_in[21];
    const float* lmf_bias = (const float*)d_in[22];
    const float* out_ln1w = (const float*)d_in[23];
    const float* out_ln1b = (const float*)d_in[24];
    const float* out_w    = (const float*)d_in[25];
    const float* out_b    = (const float*)d_in[26];
    const float* out_ln2w = (const float*)d_in[27];
    const float* out_ln2b = (const float*)d_in[28];
    float* out = (float*)d_out;

    static cudaStream_t s1 = nullptr, s2 = nullptr;
    static cudaEvent_t evStart, evPF, evCmp, evA2O, evOM, evO2A;
    if (!s1) {
        cudaFuncSetAttribute(k_gemm_z_mma, cudaFuncAttributeMaxDynamicSharedMemorySize, ZSM_TOTAL);
        cudaFuncSetAttribute(k_sp_hidgo, cudaFuncAttributeMaxDynamicSharedMemorySize, GSM_TOTAL);
        cudaFuncSetAttribute(k_sp_hidga, cudaFuncAttributeMaxDynamicSharedMemorySize, GSM_TOTAL);
        cudaFuncSetAttribute(k_sp_a2o,   cudaFuncAttributeMaxDynamicSharedMemorySize, GSM_TOTAL);
        cudaFuncSetAttribute(k_sp_o2a,   cudaFuncAttributeMaxDynamicSharedMemorySize, GSM_TOTAL);
        cudaFuncSetAttribute(k_sp_out,   cudaFuncAttributeMaxDynamicSharedMemorySize, GSM_TOTAL);
        cudaStreamCreateWithFlags(&s1, cudaStreamNonBlocking);
        cudaStreamCreateWithFlags(&s2, cudaStreamNonBlocking);
        cudaEventCreateWithFlags(&evStart, cudaEventDisableTiming);
        cudaEventCreateWithFlags(&evPF,    cudaEventDisableTiming);
        cudaEventCreateWithFlags(&evCmp,   cudaEventDisableTiming);
        cudaEventCreateWithFlags(&evA2O,   cudaEventDisableTiming);
        cudaEventCreateWithFlags(&evOM,    cudaEventDisableTiming);
        cudaEventCreateWithFlags(&evO2A,   cudaEventDisableTiming);
    }

    cudaEventRecord(evStart, 0);
    cudaStreamWaitEvent(s1, evStart, 0);
    k_prep_factors<<<dim3(32, 32, Mn * Rn), dim3(32, 8), 0, s1>>>(factors);
    cudaEventRecord(evPF, s1);

    k_mask_compact<<<6, 1024>>>(maskraw);
    cudaEventRecord(evCmp, 0);

    cudaStreamWaitEvent(s2, evCmp, 0);
    k_sp_a2o<<<dim3(Hn / 128, Bn / 128), 512, GSM_TOTAL, s2>>>(tokens, a2o_w);
    cudaEventRecord(evA2O, s2);

    k_feat_go<<<3 * Bn, 256>>>(tokens, ln_go_w, ln_go_b);
    k_sp_hidgo<<<dim3(MIDn / 128, 3 * Bn / 128), 512, GSM_TOTAL>>>(go_w1, go_b1);
    k_gate_go<<<3 * Bn, 256>>>(go_w2, go_b2);
    cudaStreamWaitEvent(0, evA2O, 0);
    k_others_omean<<<Bn, 256>>>(tokens, ln_o_w, ln_o_b);
    cudaEventRecord(evOM, 0);

    cudaStreamWaitEvent(s2, evOM, 0);
    k_sp_o2a<<<dim3(Hn / 128, Bn / 128), 512, GSM_TOTAL, s2>>>(o2a_w);
    cudaEventRecord(evO2A, s2);

    k_feat_ga<<<Bn, 256>>>(tokens, ln_ga_w, ln_ga_b);
    k_sp_hidga<<<dim3(MIDn / 128, Bn / 128), 512, GSM_TOTAL>>>(ga_w1, ga_b1);
    k_gate_ga<<<Bn, 256>>>(ga_w2, ga_b2);
    cudaStreamWaitEvent(0, evO2A, 0);
    k_mixed<<<Bn, 256>>>(tokens, ln_a_w, ln_a_b);

    cudaStreamWaitEvent(0, evPF, 0);
    k_gemm_z_mma<<<dim3(Hn / 256, Bn / 128, Mn * Rn), 512, ZSM_TOTAL>>>();
    k_combine_ln<<<Bn, 256>>>(rank_w, lmf_bias, factors, out_ln1w, out_ln1b);
    k_sp_out<<<dim3(Hn / 128, Bn / 128), 512, GSM_TOTAL>>>(out_w, out_b);
    k_ln_out<<<Bn, 256>>>(out_ln2w, out_ln2b, out);
}